// round 7
// baseline (speedup 1.0000x reference)
#include <cuda_runtime.h>
#include <cuda_bf16.h>
#include <math.h>

#define BB 2
#define SS 2048
#define EE 768
#define HH 12
#define DHH 64
#define WW 256
#define GG 16
#define FFD 3072
#define NEGV (-1e9f)

#define NQKV (BB*HH*SS*DHH)   /* 3145728 */
#define NXE  (BB*SS*EE)       /* 3145728 */
#define NFF  (BB*SS*FFD)      /* 12582912 */

typedef unsigned long long ull;

// ---------------- packed f32x2 helpers (sm_103a FFMA2) ----------------
__device__ __forceinline__ ull pk2(float lo, float hi) {
    ull r;
    asm("mov.b64 %0, {%1,%2};" : "=l"(r) : "f"(lo), "f"(hi));
    return r;
}
__device__ __forceinline__ void upk2(ull v, float &lo, float &hi) {
    asm("mov.b64 {%0,%1}, %2;" : "=f"(lo), "=f"(hi) : "l"(v));
}
__device__ __forceinline__ void fma2(ull &d, ull a, ull b) {
    asm("fma.rn.f32x2 %0, %1, %2, %0;" : "+l"(d) : "l"(a), "l"(b));
}

// ---------------- device scratch (no allocations allowed) ----------------
__device__ float g_q[NQKV];
__device__ float g_k[NQKV];
__device__ float g_v[NQKV];
__device__ float g_gq[NQKV];
__device__ float g_gk[NQKV];
__device__ float g_gv[NQKV];
__device__ float g_attn[NXE];   // attn output; later reused for FFN-down output
__device__ float g_h0[NXE];
__device__ float g_t1[NFF];
__device__ float g_t2[NFF];
__device__ float g_tbuf[BB*SS];

// ---------------- cumsum of global flags -> t ----------------
__global__ void mask_cumsum_kernel(const int* __restrict__ am,
                                   const int* __restrict__ gm,
                                   float* __restrict__ tb) {
    int b = blockIdx.x;
    __shared__ int mg[SS];
    for (int i = threadIdx.x; i < SS; i += blockDim.x)
        mg[i] = am[b*SS + i] * (gm[b*SS + i] + 1);
    __syncthreads();
    if (threadIdx.x == 0) {
        int c = 0;
        for (int i = 0; i < SS; i++) {
            c += (mg[i] == 2);
            tb[b*SS + i] = (mg[i] == 0) ? 0.f : (float)c;
        }
    }
}

// ---------------- generic SGEMM: C = (A[4096,K] @ W[K,N] + bias) * scale ----------------
// epi==0: plain row-major store. epi==1: scatter to (B,H,S,DH) head layout.
// Inner loop uses packed fma.rn.f32x2 (FFMA2) -> 2x fp32 FMA throughput.
struct GemmArgs {
    const float* A;
    const float* Wm[6];
    const float* bias[6];
    float* out[6];
    float scale[6];
    int N, K, epi;
};

__global__ __launch_bounds__(256, 2) void sgemm_kernel(GemmArgs g) {
    const int z = blockIdx.z;
    const float* __restrict__ A = g.A;
    const float* __restrict__ W = g.Wm[z];
    const float* __restrict__ bias = g.bias[z];
    float* __restrict__ out = g.out[z];
    const int N = g.N, K = g.K;
    const int bm = blockIdx.x << 7, bn = blockIdx.y << 7;

    __shared__ float As[8][128];
    __shared__ float Bs[8][128];

    const int tid = threadIdx.x;
    const int tx = tid & 15, ty = tid >> 4;
    const int arow = tid >> 1, aseg = (tid & 1) << 2;
    const int brow = tid >> 5, bcol = (tid & 31) << 2;

    const float* Ap = A + (size_t)(bm + arow) * K + aseg;
    const float* Wp = W + (size_t)brow * N + bn + bcol;

    // acc2[i][j4] holds output cols (2*j4, 2*j4+1) for row i, packed f32x2
    ull acc2[8][4];
#pragma unroll
    for (int i = 0; i < 8; i++)
#pragma unroll
        for (int j = 0; j < 4; j++) acc2[i][j] = 0ull;

    for (int k0 = 0; k0 < K; k0 += 8) {
        float4 a4 = *(const float4*)(Ap + k0);
        float4 b4 = *(const float4*)(Wp + (size_t)k0 * N);
        As[aseg+0][arow] = a4.x; As[aseg+1][arow] = a4.y;
        As[aseg+2][arow] = a4.z; As[aseg+3][arow] = a4.w;
        *(float4*)&Bs[brow][bcol] = b4;
        __syncthreads();
#pragma unroll
        for (int kk = 0; kk < 8; kk++) {
            float4 af0 = *(const float4*)&As[kk][ty<<3];
            float4 af1 = *(const float4*)&As[kk][(ty<<3)+4];
            float4 bf0 = *(const float4*)&Bs[kk][tx<<3];
            float4 bf1 = *(const float4*)&Bs[kk][(tx<<3)+4];
            ull bb[4];
            bb[0] = pk2(bf0.x, bf0.y);
            bb[1] = pk2(bf0.z, bf0.w);
            bb[2] = pk2(bf1.x, bf1.y);
            bb[3] = pk2(bf1.z, bf1.w);
            float af[8] = {af0.x, af0.y, af0.z, af0.w, af1.x, af1.y, af1.z, af1.w};
#pragma unroll
            for (int i = 0; i < 8; i++) {
                ull ai = pk2(af[i], af[i]);
#pragma unroll
                for (int j = 0; j < 4; j++)
                    fma2(acc2[i][j], ai, bb[j]);
            }
        }
        __syncthreads();
    }

    const float sc = g.scale[z];
#pragma unroll
    for (int i = 0; i < 8; i++) {
        int row = bm + (ty<<3) + i;
#pragma unroll
        for (int j4 = 0; j4 < 4; j4++) {
            float vlo, vhi;
            upk2(acc2[i][j4], vlo, vhi);
#pragma unroll
            for (int t = 0; t < 2; t++) {
                int col = bn + (tx<<3) + j4*2 + t;
                float v = t ? vhi : vlo;
                if (bias) v += bias[col];
                v *= sc;
                if (g.epi == 0) {
                    out[(size_t)row * N + col] = v;
                } else {
                    int b = row >> 11, s = row & (SS-1);
                    int h = col >> 6,  d = col & 63;
                    out[(((size_t)(b*HH + h) * SS + s) << 6) + d] = v;
                }
            }
        }
    }
}

// ---------------- RoPE on q and k (in-place) ----------------
__global__ void rope_kernel(float* __restrict__ q, float* __restrict__ k,
                            const float* __restrict__ tb) {
    int idx = blockIdx.x * blockDim.x + threadIdx.x;
    const int total = BB*HH*SS*32;
    if (idx >= total) return;
    int d   = idx & 31;
    int rem = idx >> 5;
    int s   = rem & (SS-1);
    int rem2 = rem >> 11;
    int h   = rem2 % HH;
    int b   = rem2 / HH;
    float tt = tb[b*SS + s];
    float inv_freq = expf(-(float)d * 0.28782313662425574f); // ln(10000)/32
    float sn, cs;
    sincosf(tt * inv_freq, &sn, &cs);
    size_t off = (((size_t)(b*HH + h) * SS + s) << 6) + d;
    float x1 = q[off], x2 = q[off + 32];
    q[off]      = x1*cs - x2*sn;
    q[off + 32] = x2*cs + x1*sn;
    x1 = k[off]; x2 = k[off + 32];
    k[off]      = x1*cs - x2*sn;
    k[off + 32] = x2*cs + x1*sn;
}

// ---------------- banded + global-key attention ----------------
// one block = 16 queries of one (b,h). 529 scores/query (16 global + 513 band).
__global__ __launch_bounds__(256) void band_attn_kernel(
    const float* __restrict__ q, const float* __restrict__ k, const float* __restrict__ v,
    const int* __restrict__ am, const int* __restrict__ gm,
    float* __restrict__ attn)
{
    const int b = blockIdx.z, h = blockIdx.y, base = blockIdx.x << 4;
    const int tid = threadIdx.x;
    const int p = tid >> 4, r = tid & 15;

    __shared__ float qs[16][64];          // 4 KB
    __shared__ float sc[16][536];         // 33.5 KB (529 used)
    __shared__ float ks[32][68];          // 8.5 KB (keys, reused for values)
    __shared__ unsigned char rmv[32];

    const float* qb = q + ((size_t)(b*HH + h) * SS) * DHH;
    const float* kb = k + ((size_t)(b*HH + h) * SS) * DHH;
    const float* vb = v + ((size_t)(b*HH + h) * SS) * DHH;

    // load q tile (16x64) and the 16 global keys
    {
        const float4* src = (const float4*)(qb + (size_t)base * DHH);
        float4* dst = (float4*)&qs[0][0];
        dst[tid] = src[tid];                       // exactly 256 float4
        const float4* ksrc = (const float4*)kb;    // rows 0..15
        int kk = tid >> 4, d4 = tid & 15;
        *((float4*)&ks[kk][d4*4]) = ksrc[tid];
    }
    __syncthreads();

    // global-key scores (idx 0..15), unmasked per reference
    {
        float s = 0.f;
        const float4* qp = (const float4*)qs[p];
        const float4* kp = (const float4*)&ks[r][0];
#pragma unroll
        for (int d4 = 0; d4 < 16; d4++) {
            float4 a = qp[d4], bb = kp[d4];
            s += a.x*bb.x + a.y*bb.y + a.z*bb.z + a.w*bb.w;
        }
        sc[p][r] = s;
    }
    __syncthreads();

    const int jmin = base - WW;
    // band scores: l in [0,512] <-> key j = base+p-W+l ; jrel = p+l in [0,527]
    for (int c = 0; c < 17; c++) {
        int j0 = jmin + c*32;
        for (int i = tid; i < 32*16; i += 256) {
            int kk = i >> 4, d4 = i & 15;
            int j = j0 + kk;
            float4 val = make_float4(0.f, 0.f, 0.f, 0.f);
            if (j >= 0 && j < SS) val = *(const float4*)(kb + (size_t)j*DHH + d4*4);
            *((float4*)&ks[kk][d4*4]) = val;
        }
        if (tid < 32) {
            int j = j0 + tid;
            int rm = 1;
            if (j >= 0 && j < SS) { int m = am[b*SS+j] * (gm[b*SS+j] + 1); rm = (m != 1); }
            rmv[tid] = (unsigned char)rm;
        }
        __syncthreads();
        int lbase = c*32 - p;
        int lo = lbase > 0 ? lbase : 0;
        int hi = lbase + 31; if (hi > 512) hi = 512;
        if (lo <= hi) {
            int m0 = (lo - r + 15) >> 4; if (m0 < 0) m0 = 0;
            int m1 = (hi - r) >= 0 ? ((hi - r) >> 4) : -1;
            const float4* qp = (const float4*)qs[p];
            for (int m = m0; m <= m1; m++) {
                int l = r + (m << 4);
                int kk = p + l - c*32;
                float s;
                if (rmv[kk]) s = NEGV;
                else {
                    s = 0.f;
                    const float4* kp = (const float4*)&ks[kk][0];
#pragma unroll
                    for (int d4 = 0; d4 < 16; d4++) {
                        float4 a = qp[d4], bb = kp[d4];
                        s += a.x*bb.x + a.y*bb.y + a.z*bb.z + a.w*bb.w;
                    }
                }
                sc[p][16 + l] = s;
            }
        }
        __syncthreads();
    }

    // softmax over 529 entries; 16 lanes per query
    float mx = -3.4e38f;
    for (int idx = r; idx < 529; idx += 16) mx = fmaxf(mx, sc[p][idx]);
#pragma unroll
    for (int o = 8; o; o >>= 1) mx = fmaxf(mx, __shfl_xor_sync(0xffffffffu, mx, o, 16));
    float sum = 0.f;
    for (int idx = r; idx < 529; idx += 16) {
        float e = __expf(sc[p][idx] - mx);
        sc[p][idx] = e;
        sum += e;
    }
#pragma unroll
    for (int o = 8; o; o >>= 1) sum += __shfl_xor_sync(0xffffffffu, sum, o, 16);
    float inv = 1.f / sum;
    __syncthreads();

    // AV: each lane owns d = 4r..4r+3
    float4 acc = make_float4(0.f, 0.f, 0.f, 0.f);
    {   // global values
        const float4* vsrc = (const float4*)vb;
        int kk = tid >> 4, d4 = tid & 15;
        *((float4*)&ks[kk][d4*4]) = vsrc[tid];
    }
    __syncthreads();
#pragma unroll
    for (int gidx = 0; gidx < 16; gidx++) {
        float pr = sc[p][gidx];
        float4 vv = *(const float4*)&ks[gidx][r*4];
        acc.x += pr*vv.x; acc.y += pr*vv.y; acc.z += pr*vv.z; acc.w += pr*vv.w;
    }
    __syncthreads();
    for (int c = 0; c < 17; c++) {
        int j0 = jmin + c*32;
        for (int i = tid; i < 32*16; i += 256) {
            int kk = i >> 4, d4 = i & 15;
            int j = j0 + kk;
            float4 val = make_float4(0.f, 0.f, 0.f, 0.f);
            if (j >= 0 && j < SS) val = *(const float4*)(vb + (size_t)j*DHH + d4*4);
            *((float4*)&ks[kk][d4*4]) = val;
        }
        __syncthreads();
        int lbase = c*32 - p;
        int lo = lbase > 0 ? lbase : 0;
        int hi = lbase + 31; if (hi > 512) hi = 512;
        for (int l = lo; l <= hi; l++) {
            int kk = p + l - c*32;
            float pr = sc[p][16 + l];
            float4 vv = *(const float4*)&ks[kk][r*4];
            acc.x += pr*vv.x; acc.y += pr*vv.y; acc.z += pr*vv.z; acc.w += pr*vv.w;
        }
        __syncthreads();
    }

    int iq = base + p;
    int mm = am[b*SS + iq] * (gm[b*SS + iq] + 1);
    float scl = (mm == 0) ? 0.f : inv;
    float4 o4 = make_float4(acc.x*scl, acc.y*scl, acc.z*scl, acc.w*scl);
    *(float4*)(attn + ((size_t)b*SS + iq)*EE + h*DHH + r*4) = o4;
}

// ---------------- global attention (overwrites attn rows < G) ----------------
__global__ __launch_bounds__(256) void global_attn_kernel(
    const float* __restrict__ gq, const float* __restrict__ gk, const float* __restrict__ gv,
    const int* __restrict__ am, const int* __restrict__ gm,
    float* __restrict__ attn)
{
    int g = blockIdx.x, h = blockIdx.y, b = blockIdx.z;
    int tid = threadIdx.x;
    __shared__ float sc[SS];
    __shared__ float qrow[64];
    __shared__ float red[8];
    __shared__ float redv[4][64];

    const float* gkb = gk + ((size_t)(b*HH + h) * SS) * DHH;
    const float* gvb = gv + ((size_t)(b*HH + h) * SS) * DHH;
    if (tid < 64) qrow[tid] = gq[(((size_t)(b*HH + h) * SS + g) << 6) + tid];
    __syncthreads();

    float lmax = -3.4e38f;
    for (int j = tid; j < SS; j += 256) {
        int m = am[b*SS + j] * (gm[b*SS + j] + 1);
        float s;
        if (m == 0) s = NEGV;
        else {
            s = 0.f;
            const float4* kp = (const float4*)(gkb + (size_t)j * DHH);
            const float4* qp = (const float4*)qrow;
#pragma unroll
            for (int d4 = 0; d4 < 16; d4++) {
                float4 a = qp[d4], bb = kp[d4];
                s += a.x*bb.x + a.y*bb.y + a.z*bb.z + a.w*bb.w;
            }
        }
        sc[j] = s;
        lmax = fmaxf(lmax, s);
    }
#pragma unroll
    for (int o = 16; o; o >>= 1) lmax = fmaxf(lmax, __shfl_xor_sync(0xffffffffu, lmax, o));
    if ((tid & 31) == 0) red[tid >> 5] = lmax;
    __syncthreads();
    float bmax = red[0];
#pragma unroll
    for (int w = 1; w < 8; w++) bmax = fmaxf(bmax, red[w]);

    float lsum = 0.f;
    for (int j = tid; j < SS; j += 256) {
        float e = __expf(sc[j] - bmax);
        sc[j] = e;
        lsum += e;
    }
#pragma unroll
    for (int o = 16; o; o >>= 1) lsum += __shfl_xor_sync(0xffffffffu, lsum, o);
    __syncthreads();
    if ((tid & 31) == 0) red[tid >> 5] = lsum;
    __syncthreads();
    float ssum = 0.f;
#pragma unroll
    for (int w = 0; w < 8; w++) ssum += red[w];
    float inv = 1.f / ssum;

    int grp = tid >> 6, d = tid & 63;
    float acc = 0.f;
    for (int j = grp; j < SS; j += 4) acc += sc[j] * gvb[(size_t)j * DHH + d];
    redv[grp][d] = acc;
    __syncthreads();
    if (grp == 0) {
        float o = (redv[0][d] + redv[1][d] + redv[2][d] + redv[3][d]) * inv;
        attn[((size_t)b*SS + g)*EE + h*DHH + d] = o;
    }
}

// ---------------- fused add + LayerNorm ----------------
__global__ __launch_bounds__(256) void add_ln_kernel(
    const float* __restrict__ a, const float* __restrict__ c,
    const float* __restrict__ gamma, const float* __restrict__ beta,
    float* __restrict__ out)
{
    int row = blockIdx.x;
    int tid = threadIdx.x;
    __shared__ float buf[EE];
    __shared__ float red[8];

    float local = 0.f;
#pragma unroll
    for (int i = 0; i < 3; i++) {
        int idx = tid + i*256;
        float v = a[(size_t)row*EE + idx] + c[(size_t)row*EE + idx];
        buf[idx] = v;
        local += v;
    }
#pragma unroll
    for (int o = 16; o; o >>= 1) local += __shfl_xor_sync(0xffffffffu, local, o);
    if ((tid & 31) == 0) red[tid >> 5] = local;
    __syncthreads();
    float s = 0.f;
#pragma unroll
    for (int w = 0; w < 8; w++) s += red[w];
    float mean = s * (1.f/768.f);

    float lv = 0.f;
#pragma unroll
    for (int i = 0; i < 3; i++) {
        float dd = buf[tid + i*256] - mean;
        lv += dd*dd;
    }
#pragma unroll
    for (int o = 16; o; o >>= 1) lv += __shfl_xor_sync(0xffffffffu, lv, o);
    __syncthreads();
    if ((tid & 31) == 0) red[tid >> 5] = lv;
    __syncthreads();
    float vs = 0.f;
#pragma unroll
    for (int w = 0; w < 8; w++) vs += red[w];
    float invstd = rsqrtf(vs * (1.f/768.f) + 1e-5f);

#pragma unroll
    for (int i = 0; i < 3; i++) {
        int idx = tid + i*256;
        out[(size_t)row*EE + idx] = (buf[idx] - mean) * invstd * gamma[idx] + beta[idx];
    }
}

// ---------------- SiLU(t1) * t2 -> t1 ----------------
__global__ void silu_mul_kernel(float* __restrict__ t1, const float* __restrict__ t2, int n) {
    int i = blockIdx.x * blockDim.x + threadIdx.x;
    if (i < n) {
        float a = t1[i];
        t1[i] = a / (1.f + expf(-a)) * t2[i];
    }
}

// ---------------- launch ----------------
extern "C" void kernel_launch(void* const* d_in, const int* in_sizes, int n_in,
                              void* d_out, int out_size) {
    (void)in_sizes; (void)n_in; (void)out_size;
    const float* x    = (const float*)d_in[0];
    const int*   am   = (const int*)d_in[1];
    const int*   gm   = (const int*)d_in[2];
    const float* Wq   = (const float*)d_in[3];  const float* bq  = (const float*)d_in[4];
    const float* Wk   = (const float*)d_in[5];  const float* bk  = (const float*)d_in[6];
    const float* Wv   = (const float*)d_in[7];  const float* bv  = (const float*)d_in[8];
    const float* Wqg  = (const float*)d_in[9];  const float* bqg = (const float*)d_in[10];
    const float* Wkg  = (const float*)d_in[11]; const float* bkg = (const float*)d_in[12];
    const float* Wvg  = (const float*)d_in[13]; const float* bvg = (const float*)d_in[14];
    const float* ln0g = (const float*)d_in[15]; const float* ln0b = (const float*)d_in[16];
    const float* ln1g = (const float*)d_in[17]; const float* ln1b = (const float*)d_in[18];
    const float* W1   = (const float*)d_in[19];
    const float* W3   = (const float*)d_in[20];
    const float* W2   = (const float*)d_in[21];
    float* out = (float*)d_out;

    float *qp, *kp, *vp, *gqp, *gkp, *gvp, *attnp, *h0p, *t1p, *t2p, *tbp;
    cudaGetSymbolAddress((void**)&qp,  g_q);
    cudaGetSymbolAddress((void**)&kp,  g_k);
    cudaGetSymbolAddress((void**)&vp,  g_v);
    cudaGetSymbolAddress((void**)&gqp, g_gq);
    cudaGetSymbolAddress((void**)&gkp, g_gk);
    cudaGetSymbolAddress((void**)&gvp, g_gv);
    cudaGetSymbolAddress((void**)&attnp, g_attn);
    cudaGetSymbolAddress((void**)&h0p, g_h0);
    cudaGetSymbolAddress((void**)&t1p, g_t1);
    cudaGetSymbolAddress((void**)&t2p, g_t2);
    cudaGetSymbolAddress((void**)&tbp, g_tbuf);

    mask_cumsum_kernel<<<BB, 256>>>(am, gm, tbp);

    // 6 projection GEMMs in one launch
    GemmArgs pa = {};
    pa.A = x; pa.N = EE; pa.K = EE; pa.epi = 1;
    pa.Wm[0] = Wq;  pa.bias[0] = bq;  pa.out[0] = qp;  pa.scale[0] = 0.125f;
    pa.Wm[1] = Wk;  pa.bias[1] = bk;  pa.out[1] = kp;  pa.scale[1] = 1.f;
    pa.Wm[2] = Wv;  pa.bias[2] = bv;  pa.out[2] = vp;  pa.scale[2] = 1.f;
    pa.Wm[3] = Wqg; pa.bias[3] = bqg; pa.out[3] = gqp; pa.scale[3] = 0.125f;
    pa.Wm[4] = Wkg; pa.bias[4] = bkg; pa.out[4] = gkp; pa.scale[4] = 1.f;
    pa.Wm[5] = Wvg; pa.bias[5] = bvg; pa.out[5] = gvp; pa.scale[5] = 1.f;
    sgemm_kernel<<<dim3(32, 6, 6), 256>>>(pa);

    rope_kernel<<<(BB*HH*SS*32 + 255)/256, 256>>>(qp, kp, tbp);

    band_attn_kernel<<<dim3(SS/16, HH, BB), 256>>>(qp, kp, vp, am, gm, attnp);
    global_attn_kernel<<<dim3(GG, HH, BB), 256>>>(gqp, gkp, gvp, am, gm, attnp);

    add_ln_kernel<<<BB*SS, 256>>>(x, attnp, ln0g, ln0b, h0p);

    GemmArgs f1 = {};
    f1.A = h0p; f1.N = FFD; f1.K = EE; f1.epi = 0;
    f1.Wm[0] = W1; f1.bias[0] = nullptr; f1.out[0] = t1p; f1.scale[0] = 1.f;
    f1.Wm[1] = W3; f1.bias[1] = nullptr; f1.out[1] = t2p; f1.scale[1] = 1.f;
    sgemm_kernel<<<dim3(32, 24, 2), 256>>>(f1);

    silu_mul_kernel<<<(NFF + 255)/256, 256>>>(t1p, t2p, NFF);

    GemmArgs f2 = {};
    f2.A = t1p; f2.N = EE; f2.K = FFD; f2.epi = 0;
    f2.Wm[0] = W2; f2.bias[0] = nullptr; f2.out[0] = attnp; f2.scale[0] = 1.f;
    sgemm_kernel<<<dim3(32, 6, 1), 256>>>(f2);

    add_ln_kernel<<<BB*SS, 256>>>(h0p, attnp, ln1g, ln1b, out);
}

// round 8
// speedup vs baseline: 1.0486x; 1.0486x over previous
#include <cuda_runtime.h>
#include <cuda_bf16.h>
#include <math.h>

#define BB 2
#define SS 2048
#define EE 768
#define HH 12
#define DHH 64
#define WW 256
#define GG 16
#define FFD 3072
#define NEGV (-1e9f)

#define NQKV (BB*HH*SS*DHH)   /* 3145728 */
#define NXE  (BB*SS*EE)       /* 3145728 */
#define NFF  (BB*SS*FFD)      /* 12582912 */

// ---------------- device scratch (no allocations allowed) ----------------
__device__ float g_q[NQKV];
__device__ float g_k[NQKV];
__device__ float g_v[NQKV];
__device__ float g_gq[NQKV];
__device__ float g_gk[NQKV];
__device__ float g_gv[NQKV];
__device__ float g_attn[NXE];   // attn output; later reused for FFN-down output
__device__ float g_h0[NXE];
__device__ float g_t1[NFF];
__device__ float g_t2[NFF];
__device__ float g_tbuf[BB*SS];

// ---------------- tf32 helpers ----------------
__device__ __forceinline__ unsigned f2tf32(float f) {
    unsigned r;
    asm("cvt.rna.tf32.f32 %0, %1;" : "=r"(r) : "f"(f));
    return r;
}
__device__ __forceinline__ void mma_tf32(float (&d)[4], const unsigned* a, const unsigned* b) {
    asm volatile(
        "mma.sync.aligned.m16n8k8.row.col.f32.tf32.tf32.f32 "
        "{%0,%1,%2,%3}, {%4,%5,%6,%7}, {%8,%9}, {%0,%1,%2,%3};\n"
        : "+f"(d[0]), "+f"(d[1]), "+f"(d[2]), "+f"(d[3])
        : "r"(a[0]), "r"(a[1]), "r"(a[2]), "r"(a[3]), "r"(b[0]), "r"(b[1]));
}

// ---------------- cumsum of global flags -> t ----------------
__global__ void mask_cumsum_kernel(const int* __restrict__ am,
                                   const int* __restrict__ gm,
                                   float* __restrict__ tb) {
    int b = blockIdx.x;
    __shared__ int mg[SS];
    for (int i = threadIdx.x; i < SS; i += blockDim.x)
        mg[i] = am[b*SS + i] * (gm[b*SS + i] + 1);
    __syncthreads();
    if (threadIdx.x == 0) {
        int c = 0;
        for (int i = 0; i < SS; i++) {
            c += (mg[i] == 2);
            tb[b*SS + i] = (mg[i] == 0) ? 0.f : (float)c;
        }
    }
}

// ---------------- tf32 tensor-core GEMM ----------------
// C[4096, N] = (A[4096,K] @ W[K,N] + bias) * scale
// CTA tile 128x128, BK=16, 8 warps (warp tile 64x32), double-buffered smem in
// mma fragment order. epi==0 row-major store, epi==1 scatter to (B,H,S,DH).
struct GemmArgs {
    const float* A;
    const float* Wm[6];
    const float* bias[6];
    float* out[6];
    float scale[6];
    int N, K, epi;
};

__global__ __launch_bounds__(256, 2) void tf32gemm_kernel(GemmArgs g) {
    const int z = blockIdx.z;
    const float* __restrict__ A = g.A;
    const float* __restrict__ W = g.Wm[z];
    const float* __restrict__ bias = g.bias[z];
    float* __restrict__ out = g.out[z];
    const int N = g.N, K = g.K;
    const int bm = blockIdx.x << 7, bn = blockIdx.y << 7;

    const int tid = threadIdx.x;
    const int lane = tid & 31, warp = tid >> 5;
    const int wm = (warp >> 2) << 6;   // 0 / 64
    const int wn = (warp & 3) << 5;    // 0 / 32 / 64 / 96

    // fragment-ordered smem: As[buf][kt][mt][lane][reg], Bs[buf][kt][nt][lane][reg]
    __shared__ float As[2][2][8][32][4];   // 16 KB
    __shared__ float Bs[2][2][16][32][2];  // 16 KB

    float acc[4][4][4];
#pragma unroll
    for (int i = 0; i < 4; i++)
#pragma unroll
        for (int j = 0; j < 4; j++)
#pragma unroll
            for (int r = 0; r < 4; r++) acc[i][j][r] = 0.f;

    // --- per-thread staging coordinates (2 float4 each for A and B) ---
    // A tile: 128 rows(m) x 16 cols(k) -> 512 float4 (4 chunks of k per row)
    int aid0 = tid, aid1 = tid + 256;
    int am0 = aid0 >> 2, akc0 = aid0 & 3;
    int am1 = aid1 >> 2, akc1 = aid1 & 3;
    // B tile: 16 rows(k) x 128 cols(n) -> 512 float4 (32 chunks per row)
    int bid0 = tid, bid1 = tid + 256;
    int bk0 = bid0 >> 5, bnc0 = bid0 & 31;
    int bk1 = bid1 >> 5, bnc1 = bid1 & 31;

    const float* Ap0 = A + (size_t)(bm + am0) * K + (akc0 << 2);
    const float* Ap1 = A + (size_t)(bm + am1) * K + (akc1 << 2);
    const float* Wp0 = W + (size_t)bk0 * N + bn + (bnc0 << 2);
    const float* Wp1 = W + (size_t)bk1 * N + bn + (bnc1 << 2);

    float4 pa0, pa1, pb0, pb1;

    // staging store helper (computed targets)
    // A element (m, kk): kt=kk>>3, reg=((kk>>2)&1)*2 + ((m>>3)&1), mt=m>>4, t=(m&7)*4 + (kk&3)
    // B element (kk, n): kt=kk>>3, reg=(kk>>2)&1, nt=n>>3, t=(n&7)*4 + (kk&3)
#define STAGE_A(buf, am, akc, v)  do {                                        \
        int kt_ = (akc) >> 1;                                                 \
        int rg_ = ((akc) & 1) * 2 + (((am) >> 3) & 1);                        \
        int mt_ = (am) >> 4;                                                  \
        int tb_ = ((am) & 7) * 4;                                             \
        As[buf][kt_][mt_][tb_+0][rg_] = __uint_as_float(f2tf32((v).x));       \
        As[buf][kt_][mt_][tb_+1][rg_] = __uint_as_float(f2tf32((v).y));       \
        As[buf][kt_][mt_][tb_+2][rg_] = __uint_as_float(f2tf32((v).z));       \
        As[buf][kt_][mt_][tb_+3][rg_] = __uint_as_float(f2tf32((v).w));       \
    } while (0)

#define STAGE_B(buf, bk, bnc, v)  do {                                        \
        int kt_ = (bk) >> 3;                                                  \
        int rg_ = ((bk) >> 2) & 1;                                            \
        int n4_ = (bnc) << 2;                                                 \
        int nt_ = n4_ >> 3;                                                   \
        int t0_ = (n4_ & 7) * 4 + ((bk) & 3);                                 \
        Bs[buf][kt_][nt_][t0_+0][rg_]  = __uint_as_float(f2tf32((v).x));      \
        Bs[buf][kt_][nt_][t0_+4][rg_]  = __uint_as_float(f2tf32((v).y));      \
        Bs[buf][kt_][nt_][t0_+8][rg_]  = __uint_as_float(f2tf32((v).z));      \
        Bs[buf][kt_][nt_][t0_+12][rg_] = __uint_as_float(f2tf32((v).w));      \
    } while (0)

    const int NIT = K >> 4;

    // prologue: load tile 0, stage into buf 0
    pa0 = *(const float4*)(Ap0);
    pa1 = *(const float4*)(Ap1);
    pb0 = *(const float4*)(Wp0);
    pb1 = *(const float4*)(Wp1);
    STAGE_A(0, am0, akc0, pa0);
    STAGE_A(0, am1, akc1, pa1);
    STAGE_B(0, bk0, bnc0, pb0);
    STAGE_B(0, bk1, bnc1, pb1);
    __syncthreads();

    const int mtb = wm >> 4;   // warp's first mt
    const int ntb = wn >> 3;   // warp's first nt

    for (int it = 0; it < NIT; it++) {
        const int cur = it & 1;
        const bool more = (it + 1) < NIT;
        if (more) {
            int k0 = (it + 1) << 4;
            pa0 = *(const float4*)(Ap0 + k0);
            pa1 = *(const float4*)(Ap1 + k0);
            pb0 = *(const float4*)(Wp0 + (size_t)k0 * N);
            pb1 = *(const float4*)(Wp1 + (size_t)k0 * N);
        }
#pragma unroll
        for (int kt = 0; kt < 2; kt++) {
            unsigned afr[4][4];
            unsigned bfr[4][2];
#pragma unroll
            for (int mtl = 0; mtl < 4; mtl++) {
                float4 fa = *(const float4*)&As[cur][kt][mtb + mtl][lane][0];
                afr[mtl][0] = __float_as_uint(fa.x);
                afr[mtl][1] = __float_as_uint(fa.y);
                afr[mtl][2] = __float_as_uint(fa.z);
                afr[mtl][3] = __float_as_uint(fa.w);
            }
#pragma unroll
            for (int ntl = 0; ntl < 4; ntl++) {
                float2 fb = *(const float2*)&Bs[cur][kt][ntb + ntl][lane][0];
                bfr[ntl][0] = __float_as_uint(fb.x);
                bfr[ntl][1] = __float_as_uint(fb.y);
            }
#pragma unroll
            for (int mtl = 0; mtl < 4; mtl++)
#pragma unroll
                for (int ntl = 0; ntl < 4; ntl++)
                    mma_tf32(acc[mtl][ntl], afr[mtl], bfr[ntl]);
        }
        if (more) {
            const int nxt = cur ^ 1;
            STAGE_A(nxt, am0, akc0, pa0);
            STAGE_A(nxt, am1, akc1, pa1);
            STAGE_B(nxt, bk0, bnc0, pb0);
            STAGE_B(nxt, bk1, bnc1, pb1);
            __syncthreads();
        }
    }

    // ---------------- epilogue ----------------
    const float sc = g.scale[z];
    const int gl = lane >> 2, qd = lane & 3;
#pragma unroll
    for (int mtl = 0; mtl < 4; mtl++) {
        int row0 = bm + wm + mtl * 16 + gl;
#pragma unroll
        for (int ntl = 0; ntl < 4; ntl++) {
            int col = bn + wn + ntl * 8 + qd * 2;
            float v0 = acc[mtl][ntl][0], v1 = acc[mtl][ntl][1];
            float v2 = acc[mtl][ntl][2], v3 = acc[mtl][ntl][3];
            if (bias) {
                float b0 = bias[col], b1 = bias[col + 1];
                v0 += b0; v1 += b1; v2 += b0; v3 += b1;
            }
            v0 *= sc; v1 *= sc; v2 *= sc; v3 *= sc;
            if (g.epi == 0) {
                float2* p0 = (float2*)(out + (size_t)row0 * N + col);
                float2* p1 = (float2*)(out + (size_t)(row0 + 8) * N + col);
                *p0 = make_float2(v0, v1);
                *p1 = make_float2(v2, v3);
            } else {
                int h = col >> 6, d = col & 63;
                int b0i = row0 >> 11, s0 = row0 & (SS - 1);
                int row1 = row0 + 8;
                int b1i = row1 >> 11, s1 = row1 & (SS - 1);
                float2* p0 = (float2*)(out + (((size_t)(b0i*HH + h) * SS + s0) << 6) + d);
                float2* p1 = (float2*)(out + (((size_t)(b1i*HH + h) * SS + s1) << 6) + d);
                *p0 = make_float2(v0, v1);
                *p1 = make_float2(v2, v3);
            }
        }
    }
#undef STAGE_A
#undef STAGE_B
}

// ---------------- RoPE on q and k (in-place) ----------------
__global__ void rope_kernel(float* __restrict__ q, float* __restrict__ k,
                            const float* __restrict__ tb) {
    int idx = blockIdx.x * blockDim.x + threadIdx.x;
    const int total = BB*HH*SS*32;
    if (idx >= total) return;
    int d   = idx & 31;
    int rem = idx >> 5;
    int s   = rem & (SS-1);
    int rem2 = rem >> 11;
    int h   = rem2 % HH;
    int b   = rem2 / HH;
    float tt = tb[b*SS + s];
    float inv_freq = expf(-(float)d * 0.28782313662425574f); // ln(10000)/32
    float sn, cs;
    sincosf(tt * inv_freq, &sn, &cs);
    size_t off = (((size_t)(b*HH + h) * SS + s) << 6) + d;
    float x1 = q[off], x2 = q[off + 32];
    q[off]      = x1*cs - x2*sn;
    q[off + 32] = x2*cs + x1*sn;
    x1 = k[off]; x2 = k[off + 32];
    k[off]      = x1*cs - x2*sn;
    k[off + 32] = x2*cs + x1*sn;
}

// ---------------- banded + global-key attention ----------------
__global__ __launch_bounds__(256) void band_attn_kernel(
    const float* __restrict__ q, const float* __restrict__ k, const float* __restrict__ v,
    const int* __restrict__ am, const int* __restrict__ gm,
    float* __restrict__ attn)
{
    const int b = blockIdx.z, h = blockIdx.y, base = blockIdx.x << 4;
    const int tid = threadIdx.x;
    const int p = tid >> 4, r = tid & 15;

    __shared__ float qs[16][64];
    __shared__ float sc[16][536];
    __shared__ float ks[32][68];
    __shared__ unsigned char rmv[32];

    const float* qb = q + ((size_t)(b*HH + h) * SS) * DHH;
    const float* kb = k + ((size_t)(b*HH + h) * SS) * DHH;
    const float* vb = v + ((size_t)(b*HH + h) * SS) * DHH;

    {
        const float4* src = (const float4*)(qb + (size_t)base * DHH);
        float4* dst = (float4*)&qs[0][0];
        dst[tid] = src[tid];
        const float4* ksrc = (const float4*)kb;
        int kk = tid >> 4, d4 = tid & 15;
        *((float4*)&ks[kk][d4*4]) = ksrc[tid];
    }
    __syncthreads();

    {
        float s = 0.f;
        const float4* qp = (const float4*)qs[p];
        const float4* kp = (const float4*)&ks[r][0];
#pragma unroll
        for (int d4 = 0; d4 < 16; d4++) {
            float4 a = qp[d4], bb = kp[d4];
            s += a.x*bb.x + a.y*bb.y + a.z*bb.z + a.w*bb.w;
        }
        sc[p][r] = s;
    }
    __syncthreads();

    const int jmin = base - WW;
    for (int c = 0; c < 17; c++) {
        int j0 = jmin + c*32;
        for (int i = tid; i < 32*16; i += 256) {
            int kk = i >> 4, d4 = i & 15;
            int j = j0 + kk;
            float4 val = make_float4(0.f, 0.f, 0.f, 0.f);
            if (j >= 0 && j < SS) val = *(const float4*)(kb + (size_t)j*DHH + d4*4);
            *((float4*)&ks[kk][d4*4]) = val;
        }
        if (tid < 32) {
            int j = j0 + tid;
            int rm = 1;
            if (j >= 0 && j < SS) { int m = am[b*SS+j] * (gm[b*SS+j] + 1); rm = (m != 1); }
            rmv[tid] = (unsigned char)rm;
        }
        __syncthreads();
        int lbase = c*32 - p;
        int lo = lbase > 0 ? lbase : 0;
        int hi = lbase + 31; if (hi > 512) hi = 512;
        if (lo <= hi) {
            int m0 = (lo - r + 15) >> 4; if (m0 < 0) m0 = 0;
            int m1 = (hi - r) >= 0 ? ((hi - r) >> 4) : -1;
            const float4* qp = (const float4*)qs[p];
            for (int m = m0; m <= m1; m++) {
                int l = r + (m << 4);
                int kk = p + l - c*32;
                float s;
                if (rmv[kk]) s = NEGV;
                else {
                    s = 0.f;
                    const float4* kp = (const float4*)&ks[kk][0];
#pragma unroll
                    for (int d4 = 0; d4 < 16; d4++) {
                        float4 a = qp[d4], bb = kp[d4];
                        s += a.x*bb.x + a.y*bb.y + a.z*bb.z + a.w*bb.w;
                    }
                }
                sc[p][16 + l] = s;
            }
        }
        __syncthreads();
    }

    float mx = -3.4e38f;
    for (int idx = r; idx < 529; idx += 16) mx = fmaxf(mx, sc[p][idx]);
#pragma unroll
    for (int o = 8; o; o >>= 1) mx = fmaxf(mx, __shfl_xor_sync(0xffffffffu, mx, o, 16));
    float sum = 0.f;
    for (int idx = r; idx < 529; idx += 16) {
        float e = __expf(sc[p][idx] - mx);
        sc[p][idx] = e;
        sum += e;
    }
#pragma unroll
    for (int o = 8; o; o >>= 1) sum += __shfl_xor_sync(0xffffffffu, sum, o, 16);
    float inv = 1.f / sum;
    __syncthreads();

    float4 acc = make_float4(0.f, 0.f, 0.f, 0.f);
    {
        const float4* vsrc = (const float4*)vb;
        int kk = tid >> 4, d4 = tid & 15;
        *((float4*)&ks[kk][d4*4]) = vsrc[tid];
    }
    __syncthreads();
#pragma unroll
    for (int gidx = 0; gidx < 16; gidx++) {
        float pr = sc[p][gidx];
        float4 vv = *(const float4*)&ks[gidx][r*4];
        acc.x += pr*vv.x; acc.y += pr*vv.y; acc.z += pr*vv.z; acc.w += pr*vv.w;
    }
    __syncthreads();
    for (int c = 0; c < 17; c++) {
        int j0 = jmin + c*32;
        for (int i = tid; i < 32*16; i += 256) {
            int kk = i >> 4, d4 = i & 15;
            int j = j0 + kk;
            float4 val = make_float4(0.f, 0.f, 0.f, 0.f);
            if (j >= 0 && j < SS) val = *(const float4*)(vb + (size_t)j*DHH + d4*4);
            *((float4*)&ks[kk][d4*4]) = val;
        }
        __syncthreads();
        int lbase = c*32 - p;
        int lo = lbase > 0 ? lbase : 0;
        int hi = lbase + 31; if (hi > 512) hi = 512;
        for (int l = lo; l <= hi; l++) {
            int kk = p + l - c*32;
            float pr = sc[p][16 + l];
            float4 vv = *(const float4*)&ks[kk][r*4];
            acc.x += pr*vv.x; acc.y += pr*vv.y; acc.z += pr*vv.z; acc.w += pr*vv.w;
        }
        __syncthreads();
    }

    int iq = base + p;
    int mm = am[b*SS + iq] * (gm[b*SS + iq] + 1);
    float scl = (mm == 0) ? 0.f : inv;
    float4 o4 = make_float4(acc.x*scl, acc.y*scl, acc.z*scl, acc.w*scl);
    *(float4*)(attn + ((size_t)b*SS + iq)*EE + h*DHH + r*4) = o4;
}

// ---------------- global attention (overwrites attn rows < G) ----------------
__global__ __launch_bounds__(256) void global_attn_kernel(
    const float* __restrict__ gq, const float* __restrict__ gk, const float* __restrict__ gv,
    const int* __restrict__ am, const int* __restrict__ gm,
    float* __restrict__ attn)
{
    int g = blockIdx.x, h = blockIdx.y, b = blockIdx.z;
    int tid = threadIdx.x;
    __shared__ float sc[SS];
    __shared__ float qrow[64];
    __shared__ float red[8];
    __shared__ float redv[4][64];

    const float* gkb = gk + ((size_t)(b*HH + h) * SS) * DHH;
    const float* gvb = gv + ((size_t)(b*HH + h) * SS) * DHH;
    if (tid < 64) qrow[tid] = gq[(((size_t)(b*HH + h) * SS + g) << 6) + tid];
    __syncthreads();

    float lmax = -3.4e38f;
    for (int j = tid; j < SS; j += 256) {
        int m = am[b*SS + j] * (gm[b*SS + j] + 1);
        float s;
        if (m == 0) s = NEGV;
        else {
            s = 0.f;
            const float4* kp = (const float4*)(gkb + (size_t)j * DHH);
            const float4* qp = (const float4*)qrow;
#pragma unroll
            for (int d4 = 0; d4 < 16; d4++) {
                float4 a = qp[d4], bb = kp[d4];
                s += a.x*bb.x + a.y*bb.y + a.z*bb.z + a.w*bb.w;
            }
        }
        sc[j] = s;
        lmax = fmaxf(lmax, s);
    }
#pragma unroll
    for (int o = 16; o; o >>= 1) lmax = fmaxf(lmax, __shfl_xor_sync(0xffffffffu, lmax, o));
    if ((tid & 31) == 0) red[tid >> 5] = lmax;
    __syncthreads();
    float bmax = red[0];
#pragma unroll
    for (int w = 1; w < 8; w++) bmax = fmaxf(bmax, red[w]);

    float lsum = 0.f;
    for (int j = tid; j < SS; j += 256) {
        float e = __expf(sc[j] - bmax);
        sc[j] = e;
        lsum += e;
    }
#pragma unroll
    for (int o = 16; o; o >>= 1) lsum += __shfl_xor_sync(0xffffffffu, lsum, o);
    __syncthreads();
    if ((tid & 31) == 0) red[tid >> 5] = lsum;
    __syncthreads();
    float ssum = 0.f;
#pragma unroll
    for (int w = 0; w < 8; w++) ssum += red[w];
    float inv = 1.f / ssum;

    int grp = tid >> 6, d = tid & 63;
    float acc = 0.f;
    for (int j = grp; j < SS; j += 4) acc += sc[j] * gvb[(size_t)j * DHH + d];
    redv[grp][d] = acc;
    __syncthreads();
    if (grp == 0) {
        float o = (redv[0][d] + redv[1][d] + redv[2][d] + redv[3][d]) * inv;
        attn[((size_t)b*SS + g)*EE + h*DHH + d] = o;
    }
}

// ---------------- fused add + LayerNorm ----------------
__global__ __launch_bounds__(256) void add_ln_kernel(
    const float* __restrict__ a, const float* __restrict__ c,
    const float* __restrict__ gamma, const float* __restrict__ beta,
    float* __restrict__ out)
{
    int row = blockIdx.x;
    int tid = threadIdx.x;
    __shared__ float buf[EE];
    __shared__ float red[8];

    float local = 0.f;
#pragma unroll
    for (int i = 0; i < 3; i++) {
        int idx = tid + i*256;
        float v = a[(size_t)row*EE + idx] + c[(size_t)row*EE + idx];
        buf[idx] = v;
        local += v;
    }
#pragma unroll
    for (int o = 16; o; o >>= 1) local += __shfl_xor_sync(0xffffffffu, local, o);
    if ((tid & 31) == 0) red[tid >> 5] = local;
    __syncthreads();
    float s = 0.f;
#pragma unroll
    for (int w = 0; w < 8; w++) s += red[w];
    float mean = s * (1.f/768.f);

    float lv = 0.f;
#pragma unroll
    for (int i = 0; i < 3; i++) {
        float dd = buf[tid + i*256] - mean;
        lv += dd*dd;
    }
#pragma unroll
    for (int o = 16; o; o >>= 1) lv += __shfl_xor_sync(0xffffffffu, lv, o);
    __syncthreads();
    if ((tid & 31) == 0) red[tid >> 5] = lv;
    __syncthreads();
    float vs = 0.f;
#pragma unroll
    for (int w = 0; w < 8; w++) vs += red[w];
    float invstd = rsqrtf(vs * (1.f/768.f) + 1e-5f);

#pragma unroll
    for (int i = 0; i < 3; i++) {
        int idx = tid + i*256;
        out[(size_t)row*EE + idx] = (buf[idx] - mean) * invstd * gamma[idx] + beta[idx];
    }
}

// ---------------- SiLU(t1) * t2 -> t1 ----------------
__global__ void silu_mul_kernel(float* __restrict__ t1, const float* __restrict__ t2, int n) {
    int i = blockIdx.x * blockDim.x + threadIdx.x;
    if (i < n) {
        float a = t1[i];
        t1[i] = a / (1.f + expf(-a)) * t2[i];
    }
}

// ---------------- launch ----------------
extern "C" void kernel_launch(void* const* d_in, const int* in_sizes, int n_in,
                              void* d_out, int out_size) {
    (void)in_sizes; (void)n_in; (void)out_size;
    const float* x    = (const float*)d_in[0];
    const int*   am   = (const int*)d_in[1];
    const int*   gm   = (const int*)d_in[2];
    const float* Wq   = (const float*)d_in[3];  const float* bq  = (const float*)d_in[4];
    const float* Wk   = (const float*)d_in[5];  const float* bk  = (const float*)d_in[6];
    const float* Wv   = (const float*)d_in[7];  const float* bv  = (const float*)d_in[8];
    const float* Wqg  = (const float*)d_in[9];  const float* bqg = (const float*)d_in[10];
    const float* Wkg  = (const float*)d_in[11]; const float* bkg = (const float*)d_in[12];
    const float* Wvg  = (const float*)d_in[13]; const float* bvg = (const float*)d_in[14];
    const float* ln0g = (const float*)d_in[15]; const float* ln0b = (const float*)d_in[16];
    const float* ln1g = (const float*)d_in[17]; const float* ln1b = (const float*)d_in[18];
    const float* W1   = (const float*)d_in[19];
    const float* W3   = (const float*)d_in[20];
    const float* W2   = (const float*)d_in[21];
    float* out = (float*)d_out;

    float *qp, *kp, *vp, *gqp, *gkp, *gvp, *attnp, *h0p, *t1p, *t2p, *tbp;
    cudaGetSymbolAddress((void**)&qp,  g_q);
    cudaGetSymbolAddress((void**)&kp,  g_k);
    cudaGetSymbolAddress((void**)&vp,  g_v);
    cudaGetSymbolAddress((void**)&gqp, g_gq);
    cudaGetSymbolAddress((void**)&gkp, g_gk);
    cudaGetSymbolAddress((void**)&gvp, g_gv);
    cudaGetSymbolAddress((void**)&attnp, g_attn);
    cudaGetSymbolAddress((void**)&h0p, g_h0);
    cudaGetSymbolAddress((void**)&t1p, g_t1);
    cudaGetSymbolAddress((void**)&t2p, g_t2);
    cudaGetSymbolAddress((void**)&tbp, g_tbuf);

    mask_cumsum_kernel<<<BB, 256>>>(am, gm, tbp);

    // 6 projection GEMMs in one launch
    GemmArgs pa = {};
    pa.A = x; pa.N = EE; pa.K = EE; pa.epi = 1;
    pa.Wm[0] = Wq;  pa.bias[0] = bq;  pa.out[0] = qp;  pa.scale[0] = 0.125f;
    pa.Wm[1] = Wk;  pa.bias[1] = bk;  pa.out[1] = kp;  pa.scale[1] = 1.f;
    pa.Wm[2] = Wv;  pa.bias[2] = bv;  pa.out[2] = vp;  pa.scale[2] = 1.f;
    pa.Wm[3] = Wqg; pa.bias[3] = bqg; pa.out[3] = gqp; pa.scale[3] = 0.125f;
    pa.Wm[4] = Wkg; pa.bias[4] = bkg; pa.out[4] = gkp; pa.scale[4] = 1.f;
    pa.Wm[5] = Wvg; pa.bias[5] = bvg; pa.out[5] = gvp; pa.scale[5] = 1.f;
    tf32gemm_kernel<<<dim3(32, 6, 6), 256>>>(pa);

    rope_kernel<<<(BB*HH*SS*32 + 255)/256, 256>>>(qp, kp, tbp);

    band_attn_kernel<<<dim3(SS/16, HH, BB), 256>>>(qp, kp, vp, am, gm, attnp);
    global_attn_kernel<<<dim3(GG, HH, BB), 256>>>(gqp, gkp, gvp, am, gm, attnp);

    add_ln_kernel<<<BB*SS, 256>>>(x, attnp, ln0g, ln0b, h0p);

    GemmArgs f1 = {};
    f1.A = h0p; f1.N = FFD; f1.K = EE; f1.epi = 0;
    f1.Wm[0] = W1; f1.bias[0] = nullptr; f1.out[0] = t1p; f1.scale[0] = 1.f;
    f1.Wm[1] = W3; f1.bias[1] = nullptr; f1.out[1] = t2p; f1.scale[1] = 1.f;
    tf32gemm_kernel<<<dim3(32, 24, 2), 256>>>(f1);

    silu_mul_kernel<<<(NFF + 255)/256, 256>>>(t1p, t2p, NFF);

    GemmArgs f2 = {};
    f2.A = t1p; f2.N = EE; f2.K = FFD; f2.epi = 0;
    f2.Wm[0] = W2; f2.bias[0] = nullptr; f2.out[0] = attnp; f2.scale[0] = 1.f;
    tf32gemm_kernel<<<dim3(32, 6, 1), 256>>>(f2);

    add_ln_kernel<<<BB*SS, 256>>>(h0p, attnp, ln1g, ln1b, out);
}

// round 9
// speedup vs baseline: 2.1261x; 2.0276x over previous
#include <cuda_runtime.h>
#include <cuda_bf16.h>
#include <math.h>

#define BB 2
#define SS 2048
#define EE 768
#define HH 12
#define DHH 64
#define WW 256
#define GG 16
#define FFD 3072
#define NEGV (-1e9f)

#define NQKV (BB*HH*SS*DHH)
#define NXE  (BB*SS*EE)
#define NFF  (BB*SS*FFD)

// ---------------- device scratch ----------------
__device__ float g_q[NQKV];
__device__ float g_k[NQKV];
__device__ float g_v[NQKV];
__device__ float g_gq[NQKV];
__device__ float g_gk[NQKV];
__device__ float g_gv[NQKV];
__device__ float g_attn[NXE];
__device__ float g_h0[NXE];
__device__ float g_t1[NFF];
__device__ float g_t2[NFF];
__device__ float g_tbuf[BB*SS];

// ---------------- mma / cp.async helpers ----------------
__device__ __forceinline__ void mma_tf32(float (&d)[4], const unsigned* a, const unsigned* b) {
    asm volatile(
        "mma.sync.aligned.m16n8k8.row.col.f32.tf32.tf32.f32 "
        "{%0,%1,%2,%3}, {%4,%5,%6,%7}, {%8,%9}, {%0,%1,%2,%3};\n"
        : "+f"(d[0]), "+f"(d[1]), "+f"(d[2]), "+f"(d[3])
        : "r"(a[0]), "r"(a[1]), "r"(a[2]), "r"(a[3]), "r"(b[0]), "r"(b[1]));
}
__device__ __forceinline__ void cpasync16(unsigned dst, const void* src) {
    asm volatile("cp.async.cg.shared.global [%0], [%1], 16;\n" :: "r"(dst), "l"(src));
}
__device__ __forceinline__ void cp_commit() {
    asm volatile("cp.async.commit_group;\n");
}
template <int N> __device__ __forceinline__ void cp_wait() {
    asm volatile("cp.async.wait_group %0;\n" :: "n"(N));
}

// ---------------- cumsum of global flags -> t ----------------
__global__ void mask_cumsum_kernel(const int* __restrict__ am,
                                   const int* __restrict__ gm,
                                   float* __restrict__ tb) {
    int b = blockIdx.x;
    __shared__ int mg[SS];
    for (int i = threadIdx.x; i < SS; i += blockDim.x)
        mg[i] = am[b*SS + i] * (gm[b*SS + i] + 1);
    __syncthreads();
    if (threadIdx.x == 0) {
        int c = 0;
        for (int i = 0; i < SS; i++) {
            c += (mg[i] == 2);
            tb[b*SS + i] = (mg[i] == 0) ? 0.f : (float)c;
        }
    }
}

// ---------------- tf32 tensor-core GEMM (cp.async + padded smem) ----------------
// C[4096, N] = (A[4096,K] @ W[K,N] + bias) * scale
// CTA tile 128x128, BK=16, 8 warps (warp tile 64x32), 2-stage cp.async pipeline.
// A smem [128][20] pad -> conflict-free scalar fragment LDS; B smem [16][136].
struct GemmArgs {
    const float* A;
    const float* Wm[6];
    const float* bias[6];
    float* out[6];
    float scale[6];
    int N, K, epi;
};

#define APAD 20
#define BPAD 136

__global__ __launch_bounds__(256, 2) void tf32gemm_kernel(GemmArgs g) {
    const int z = blockIdx.z;
    const float* __restrict__ A = g.A;
    const float* __restrict__ W = g.Wm[z];
    const float* __restrict__ bias = g.bias[z];
    float* __restrict__ out = g.out[z];
    const int N = g.N, K = g.K;
    const int bm = blockIdx.x << 7, bn = blockIdx.y << 7;

    const int tid = threadIdx.x;
    const int lane = tid & 31, warp = tid >> 5;
    const int wm = (warp >> 2) << 6;   // 0 / 64
    const int wn = (warp & 3) << 5;    // 0 / 32 / 64 / 96
    const int gl = lane >> 2, qd = lane & 3;

    __shared__ float As[2][128][APAD];   // 20.0 KB
    __shared__ float Bs[2][16][BPAD];    // 17.4 KB

    float acc[4][4][4];
#pragma unroll
    for (int i = 0; i < 4; i++)
#pragma unroll
        for (int j = 0; j < 4; j++)
#pragma unroll
            for (int r = 0; r < 4; r++) acc[i][j][r] = 0.f;

    // staging coordinates: 2 float4 for A (128x16 = 512 chunks), 2 for B (16x128)
    const int am0 = tid >> 2,           akc0 = tid & 3;
    const int am1 = (tid + 256) >> 2,   akc1 = tid & 3;
    const int bk0 = tid >> 5,           bnc0 = tid & 31;
    const int bk1 = (tid + 256) >> 5,   bnc1 = tid & 31;

    const float* Agp0 = A + (size_t)(bm + am0) * K + (akc0 << 2);
    const float* Agp1 = A + (size_t)(bm + am1) * K + (akc1 << 2);
    const float* Wgp0 = W + (size_t)bk0 * N + bn + (bnc0 << 2);
    const float* Wgp1 = W + (size_t)bk1 * N + bn + (bnc1 << 2);

    unsigned sA0[2], sA1[2], sB0[2], sB1[2];
#pragma unroll
    for (int bf = 0; bf < 2; bf++) {
        sA0[bf] = (unsigned)__cvta_generic_to_shared(&As[bf][am0][akc0 << 2]);
        sA1[bf] = (unsigned)__cvta_generic_to_shared(&As[bf][am1][akc1 << 2]);
        sB0[bf] = (unsigned)__cvta_generic_to_shared(&Bs[bf][bk0][bnc0 << 2]);
        sB1[bf] = (unsigned)__cvta_generic_to_shared(&Bs[bf][bk1][bnc1 << 2]);
    }

    const int NIT = K >> 4;

    // prologue: stage tile 0 into buf 0
    cpasync16(sA0[0], Agp0);
    cpasync16(sA1[0], Agp1);
    cpasync16(sB0[0], Wgp0);
    cpasync16(sB1[0], Wgp1);
    cp_commit();

    for (int it = 0; it < NIT; it++) {
        const int cur = it & 1;
        const bool more = (it + 1) < NIT;
        if (more) {
            const int nxt = cur ^ 1;
            int k0 = (it + 1) << 4;
            cpasync16(sA0[nxt], Agp0 + k0);
            cpasync16(sA1[nxt], Agp1 + k0);
            cpasync16(sB0[nxt], Wgp0 + (size_t)k0 * N);
            cpasync16(sB1[nxt], Wgp1 + (size_t)k0 * N);
            cp_commit();
            cp_wait<1>();
        } else {
            cp_wait<0>();
        }
        __syncthreads();

#pragma unroll
        for (int kt = 0; kt < 2; kt++) {
            const int k0 = kt << 3;
            unsigned afr[4][4], bfr[4][2];
#pragma unroll
            for (int mtl = 0; mtl < 4; mtl++) {
                int m = wm + (mtl << 4);
                afr[mtl][0] = __float_as_uint(As[cur][m + gl    ][k0 + qd    ]);
                afr[mtl][1] = __float_as_uint(As[cur][m + gl + 8][k0 + qd    ]);
                afr[mtl][2] = __float_as_uint(As[cur][m + gl    ][k0 + qd + 4]);
                afr[mtl][3] = __float_as_uint(As[cur][m + gl + 8][k0 + qd + 4]);
            }
#pragma unroll
            for (int ntl = 0; ntl < 4; ntl++) {
                int n = wn + (ntl << 3) + gl;
                bfr[ntl][0] = __float_as_uint(Bs[cur][k0 + qd    ][n]);
                bfr[ntl][1] = __float_as_uint(Bs[cur][k0 + qd + 4][n]);
            }
#pragma unroll
            for (int mtl = 0; mtl < 4; mtl++)
#pragma unroll
                for (int ntl = 0; ntl < 4; ntl++)
                    mma_tf32(acc[mtl][ntl], afr[mtl], bfr[ntl]);
        }
        __syncthreads();
    }

    // ---------------- epilogue ----------------
    const float sc = g.scale[z];
#pragma unroll
    for (int mtl = 0; mtl < 4; mtl++) {
        int row0 = bm + wm + (mtl << 4) + gl;
#pragma unroll
        for (int ntl = 0; ntl < 4; ntl++) {
            int col = bn + wn + (ntl << 3) + (qd << 1);
            float v0 = acc[mtl][ntl][0], v1 = acc[mtl][ntl][1];
            float v2 = acc[mtl][ntl][2], v3 = acc[mtl][ntl][3];
            if (bias) {
                float b0 = bias[col], b1 = bias[col + 1];
                v0 += b0; v1 += b1; v2 += b0; v3 += b1;
            }
            v0 *= sc; v1 *= sc; v2 *= sc; v3 *= sc;
            if (g.epi == 0) {
                *(float2*)(out + (size_t)row0 * N + col)       = make_float2(v0, v1);
                *(float2*)(out + (size_t)(row0 + 8) * N + col) = make_float2(v2, v3);
            } else {
                int h = col >> 6, d = col & 63;
                int b0i = row0 >> 11, s0 = row0 & (SS - 1);
                int row1 = row0 + 8;
                int b1i = row1 >> 11, s1 = row1 & (SS - 1);
                *(float2*)(out + (((size_t)(b0i*HH + h) * SS + s0) << 6) + d) = make_float2(v0, v1);
                *(float2*)(out + (((size_t)(b1i*HH + h) * SS + s1) << 6) + d) = make_float2(v2, v3);
            }
        }
    }
}

// ---------------- RoPE on q and k (in-place) ----------------
__global__ void rope_kernel(float* __restrict__ q, float* __restrict__ k,
                            const float* __restrict__ tb) {
    int idx = blockIdx.x * blockDim.x + threadIdx.x;
    const int total = BB*HH*SS*32;
    if (idx >= total) return;
    int d   = idx & 31;
    int rem = idx >> 5;
    int s   = rem & (SS-1);
    int rem2 = rem >> 11;
    int h   = rem2 % HH;
    int b   = rem2 / HH;
    float tt = tb[b*SS + s];
    float inv_freq = expf(-(float)d * 0.28782313662425574f);
    float sn, cs;
    sincosf(tt * inv_freq, &sn, &cs);
    size_t off = (((size_t)(b*HH + h) * SS + s) << 6) + d;
    float x1 = q[off], x2 = q[off + 32];
    q[off]      = x1*cs - x2*sn;
    q[off + 32] = x2*cs + x1*sn;
    x1 = k[off]; x2 = k[off + 32];
    k[off]      = x1*cs - x2*sn;
    k[off + 32] = x2*cs + x1*sn;
}

// ---------------- banded + global-key attention ----------------
__global__ __launch_bounds__(256) void band_attn_kernel(
    const float* __restrict__ q, const float* __restrict__ k, const float* __restrict__ v,
    const int* __restrict__ am, const int* __restrict__ gm,
    float* __restrict__ attn)
{
    const int b = blockIdx.z, h = blockIdx.y, base = blockIdx.x << 4;
    const int tid = threadIdx.x;
    const int p = tid >> 4, r = tid & 15;

    __shared__ float qs[16][64];
    __shared__ float sc[16][536];
    __shared__ float ks[32][68];
    __shared__ unsigned char rmv[32];

    const float* qb = q + ((size_t)(b*HH + h) * SS) * DHH;
    const float* kb = k + ((size_t)(b*HH + h) * SS) * DHH;
    const float* vb = v + ((size_t)(b*HH + h) * SS) * DHH;

    {
        const float4* src = (const float4*)(qb + (size_t)base * DHH);
        float4* dst = (float4*)&qs[0][0];
        dst[tid] = src[tid];
        const float4* ksrc = (const float4*)kb;
        int kk = tid >> 4, d4 = tid & 15;
        *((float4*)&ks[kk][d4*4]) = ksrc[tid];
    }
    __syncthreads();

    {
        float s = 0.f;
        const float4* qp = (const float4*)qs[p];
        const float4* kp = (const float4*)&ks[r][0];
#pragma unroll
        for (int d4 = 0; d4 < 16; d4++) {
            float4 a = qp[d4], bb = kp[d4];
            s += a.x*bb.x + a.y*bb.y + a.z*bb.z + a.w*bb.w;
        }
        sc[p][r] = s;
    }
    __syncthreads();

    const int jmin = base - WW;
    for (int c = 0; c < 17; c++) {
        int j0 = jmin + c*32;
        for (int i = tid; i < 32*16; i += 256) {
            int kk = i >> 4, d4 = i & 15;
            int j = j0 + kk;
            float4 val = make_float4(0.f, 0.f, 0.f, 0.f);
            if (j >= 0 && j < SS) val = *(const float4*)(kb + (size_t)j*DHH + d4*4);
            *((float4*)&ks[kk][d4*4]) = val;
        }
        if (tid < 32) {
            int j = j0 + tid;
            int rm = 1;
            if (j >= 0 && j < SS) { int m = am[b*SS+j] * (gm[b*SS+j] + 1); rm = (m != 1); }
            rmv[tid] = (unsigned char)rm;
        }
        __syncthreads();
        int lbase = c*32 - p;
        int lo = lbase > 0 ? lbase : 0;
        int hi = lbase + 31; if (hi > 512) hi = 512;
        if (lo <= hi) {
            int m0 = (lo - r + 15) >> 4; if (m0 < 0) m0 = 0;
            int m1 = (hi - r) >= 0 ? ((hi - r) >> 4) : -1;
            const float4* qp = (const float4*)qs[p];
            for (int m = m0; m <= m1; m++) {
                int l = r + (m << 4);
                int kk = p + l - c*32;
                float s;
                if (rmv[kk]) s = NEGV;
                else {
                    s = 0.f;
                    const float4* kp = (const float4*)&ks[kk][0];
#pragma unroll
                    for (int d4 = 0; d4 < 16; d4++) {
                        float4 a = qp[d4], bb = kp[d4];
                        s += a.x*bb.x + a.y*bb.y + a.z*bb.z + a.w*bb.w;
                    }
                }
                sc[p][16 + l] = s;
            }
        }
        __syncthreads();
    }

    float mx = -3.4e38f;
    for (int idx = r; idx < 529; idx += 16) mx = fmaxf(mx, sc[p][idx]);
#pragma unroll
    for (int o = 8; o; o >>= 1) mx = fmaxf(mx, __shfl_xor_sync(0xffffffffu, mx, o, 16));
    float sum = 0.f;
    for (int idx = r; idx < 529; idx += 16) {
        float e = __expf(sc[p][idx] - mx);
        sc[p][idx] = e;
        sum += e;
    }
#pragma unroll
    for (int o = 8; o; o >>= 1) sum += __shfl_xor_sync(0xffffffffu, sum, o, 16);
    float inv = 1.f / sum;
    __syncthreads();

    float4 acc = make_float4(0.f, 0.f, 0.f, 0.f);
    {
        const float4* vsrc = (const float4*)vb;
        int kk = tid >> 4, d4 = tid & 15;
        *((float4*)&ks[kk][d4*4]) = vsrc[tid];
    }
    __syncthreads();
#pragma unroll
    for (int gidx = 0; gidx < 16; gidx++) {
        float pr = sc[p][gidx];
        float4 vv = *(const float4*)&ks[gidx][r*4];
        acc.x += pr*vv.x; acc.y += pr*vv.y; acc.z += pr*vv.z; acc.w += pr*vv.w;
    }
    __syncthreads();
    for (int c = 0; c < 17; c++) {
        int j0 = jmin + c*32;
        for (int i = tid; i < 32*16; i += 256) {
            int kk = i >> 4, d4 = i & 15;
            int j = j0 + kk;
            float4 val = make_float4(0.f, 0.f, 0.f, 0.f);
            if (j >= 0 && j < SS) val = *(const float4*)(vb + (size_t)j*DHH + d4*4);
            *((float4*)&ks[kk][d4*4]) = val;
        }
        __syncthreads();
        int lbase = c*32 - p;
        int lo = lbase > 0 ? lbase : 0;
        int hi = lbase + 31; if (hi > 512) hi = 512;
        for (int l = lo; l <= hi; l++) {
            int kk = p + l - c*32;
            float pr = sc[p][16 + l];
            float4 vv = *(const float4*)&ks[kk][r*4];
            acc.x += pr*vv.x; acc.y += pr*vv.y; acc.z += pr*vv.z; acc.w += pr*vv.w;
        }
        __syncthreads();
    }

    int iq = base + p;
    int mm = am[b*SS + iq] * (gm[b*SS + iq] + 1);
    float scl = (mm == 0) ? 0.f : inv;
    float4 o4 = make_float4(acc.x*scl, acc.y*scl, acc.z*scl, acc.w*scl);
    *(float4*)(attn + ((size_t)b*SS + iq)*EE + h*DHH + r*4) = o4;
}

// ---------------- global attention (overwrites attn rows < G) ----------------
__global__ __launch_bounds__(256) void global_attn_kernel(
    const float* __restrict__ gq, const float* __restrict__ gk, const float* __restrict__ gv,
    const int* __restrict__ am, const int* __restrict__ gm,
    float* __restrict__ attn)
{
    int g = blockIdx.x, h = blockIdx.y, b = blockIdx.z;
    int tid = threadIdx.x;
    __shared__ float sc[SS];
    __shared__ float qrow[64];
    __shared__ float red[8];
    __shared__ float redv[4][64];

    const float* gkb = gk + ((size_t)(b*HH + h) * SS) * DHH;
    const float* gvb = gv + ((size_t)(b*HH + h) * SS) * DHH;
    if (tid < 64) qrow[tid] = gq[(((size_t)(b*HH + h) * SS + g) << 6) + tid];
    __syncthreads();

    float lmax = -3.4e38f;
    for (int j = tid; j < SS; j += 256) {
        int m = am[b*SS + j] * (gm[b*SS + j] + 1);
        float s;
        if (m == 0) s = NEGV;
        else {
            s = 0.f;
            const float4* kp = (const float4*)(gkb + (size_t)j * DHH);
            const float4* qp = (const float4*)qrow;
#pragma unroll
            for (int d4 = 0; d4 < 16; d4++) {
                float4 a = qp[d4], bb = kp[d4];
                s += a.x*bb.x + a.y*bb.y + a.z*bb.z + a.w*bb.w;
            }
        }
        sc[j] = s;
        lmax = fmaxf(lmax, s);
    }
#pragma unroll
    for (int o = 16; o; o >>= 1) lmax = fmaxf(lmax, __shfl_xor_sync(0xffffffffu, lmax, o));
    if ((tid & 31) == 0) red[tid >> 5] = lmax;
    __syncthreads();
    float bmax = red[0];
#pragma unroll
    for (int w = 1; w < 8; w++) bmax = fmaxf(bmax, red[w]);

    float lsum = 0.f;
    for (int j = tid; j < SS; j += 256) {
        float e = __expf(sc[j] - bmax);
        sc[j] = e;
        lsum += e;
    }
#pragma unroll
    for (int o = 16; o; o >>= 1) lsum += __shfl_xor_sync(0xffffffffu, lsum, o);
    __syncthreads();
    if ((tid & 31) == 0) red[tid >> 5] = lsum;
    __syncthreads();
    float ssum = 0.f;
#pragma unroll
    for (int w = 0; w < 8; w++) ssum += red[w];
    float inv = 1.f / ssum;

    int grp = tid >> 6, d = tid & 63;
    float acc = 0.f;
    for (int j = grp; j < SS; j += 4) acc += sc[j] * gvb[(size_t)j * DHH + d];
    redv[grp][d] = acc;
    __syncthreads();
    if (grp == 0) {
        float o = (redv[0][d] + redv[1][d] + redv[2][d] + redv[3][d]) * inv;
        attn[((size_t)b*SS + g)*EE + h*DHH + d] = o;
    }
}

// ---------------- fused add + LayerNorm ----------------
__global__ __launch_bounds__(256) void add_ln_kernel(
    const float* __restrict__ a, const float* __restrict__ c,
    const float* __restrict__ gamma, const float* __restrict__ beta,
    float* __restrict__ out)
{
    int row = blockIdx.x;
    int tid = threadIdx.x;
    __shared__ float buf[EE];
    __shared__ float red[8];

    float local = 0.f;
#pragma unroll
    for (int i = 0; i < 3; i++) {
        int idx = tid + i*256;
        float v = a[(size_t)row*EE + idx] + c[(size_t)row*EE + idx];
        buf[idx] = v;
        local += v;
    }
#pragma unroll
    for (int o = 16; o; o >>= 1) local += __shfl_xor_sync(0xffffffffu, local, o);
    if ((tid & 31) == 0) red[tid >> 5] = local;
    __syncthreads();
    float s = 0.f;
#pragma unroll
    for (int w = 0; w < 8; w++) s += red[w];
    float mean = s * (1.f/768.f);

    float lv = 0.f;
#pragma unroll
    for (int i = 0; i < 3; i++) {
        float dd = buf[tid + i*256] - mean;
        lv += dd*dd;
    }
#pragma unroll
    for (int o = 16; o; o >>= 1) lv += __shfl_xor_sync(0xffffffffu, lv, o);
    __syncthreads();
    if ((tid & 31) == 0) red[tid >> 5] = lv;
    __syncthreads();
    float vs = 0.f;
#pragma unroll
    for (int w = 0; w < 8; w++) vs += red[w];
    float invstd = rsqrtf(vs * (1.f/768.f) + 1e-5f);

#pragma unroll
    for (int i = 0; i < 3; i++) {
        int idx = tid + i*256;
        out[(size_t)row*EE + idx] = (buf[idx] - mean) * invstd * gamma[idx] + beta[idx];
    }
}

// ---------------- SiLU(t1) * t2 -> t1 ----------------
__global__ void silu_mul_kernel(float* __restrict__ t1, const float* __restrict__ t2, int n) {
    int i = blockIdx.x * blockDim.x + threadIdx.x;
    if (i < n) {
        float a = t1[i];
        t1[i] = a / (1.f + expf(-a)) * t2[i];
    }
}

// ---------------- launch ----------------
extern "C" void kernel_launch(void* const* d_in, const int* in_sizes, int n_in,
                              void* d_out, int out_size) {
    (void)in_sizes; (void)n_in; (void)out_size;
    const float* x    = (const float*)d_in[0];
    const int*   am   = (const int*)d_in[1];
    const int*   gm   = (const int*)d_in[2];
    const float* Wq   = (const float*)d_in[3];  const float* bq  = (const float*)d_in[4];
    const float* Wk   = (const float*)d_in[5];  const float* bk  = (const float*)d_in[6];
    const float* Wv   = (const float*)d_in[7];  const float* bv  = (const float*)d_in[8];
    const float* Wqg  = (const float*)d_in[9];  const float* bqg = (const float*)d_in[10];
    const float* Wkg  = (const float*)d_in[11]; const float* bkg = (const float*)d_in[12];
    const float* Wvg  = (const float*)d_in[13]; const float* bvg = (const float*)d_in[14];
    const float* ln0g = (const float*)d_in[15]; const float* ln0b = (const float*)d_in[16];
    const float* ln1g = (const float*)d_in[17]; const float* ln1b = (const float*)d_in[18];
    const float* W1   = (const float*)d_in[19];
    const float* W3   = (const float*)d_in[20];
    const float* W2   = (const float*)d_in[21];
    float* out = (float*)d_out;

    float *qp, *kp, *vp, *gqp, *gkp, *gvp, *attnp, *h0p, *t1p, *t2p, *tbp;
    cudaGetSymbolAddress((void**)&qp,  g_q);
    cudaGetSymbolAddress((void**)&kp,  g_k);
    cudaGetSymbolAddress((void**)&vp,  g_v);
    cudaGetSymbolAddress((void**)&gqp, g_gq);
    cudaGetSymbolAddress((void**)&gkp, g_gk);
    cudaGetSymbolAddress((void**)&gvp, g_gv);
    cudaGetSymbolAddress((void**)&attnp, g_attn);
    cudaGetSymbolAddress((void**)&h0p, g_h0);
    cudaGetSymbolAddress((void**)&t1p, g_t1);
    cudaGetSymbolAddress((void**)&t2p, g_t2);
    cudaGetSymbolAddress((void**)&tbp, g_tbuf);

    mask_cumsum_kernel<<<BB, 256>>>(am, gm, tbp);

    GemmArgs pa = {};
    pa.A = x; pa.N = EE; pa.K = EE; pa.epi = 1;
    pa.Wm[0] = Wq;  pa.bias[0] = bq;  pa.out[0] = qp;  pa.scale[0] = 0.125f;
    pa.Wm[1] = Wk;  pa.bias[1] = bk;  pa.out[1] = kp;  pa.scale[1] = 1.f;
    pa.Wm[2] = Wv;  pa.bias[2] = bv;  pa.out[2] = vp;  pa.scale[2] = 1.f;
    pa.Wm[3] = Wqg; pa.bias[3] = bqg; pa.out[3] = gqp; pa.scale[3] = 0.125f;
    pa.Wm[4] = Wkg; pa.bias[4] = bkg; pa.out[4] = gkp; pa.scale[4] = 1.f;
    pa.Wm[5] = Wvg; pa.bias[5] = bvg; pa.out[5] = gvp; pa.scale[5] = 1.f;
    tf32gemm_kernel<<<dim3(32, 6, 6), 256>>>(pa);

    rope_kernel<<<(BB*HH*SS*32 + 255)/256, 256>>>(qp, kp, tbp);

    band_attn_kernel<<<dim3(SS/16, HH, BB), 256>>>(qp, kp, vp, am, gm, attnp);
    global_attn_kernel<<<dim3(GG, HH, BB), 256>>>(gqp, gkp, gvp, am, gm, attnp);

    add_ln_kernel<<<BB*SS, 256>>>(x, attnp, ln0g, ln0b, h0p);

    GemmArgs f1 = {};
    f1.A = h0p; f1.N = FFD; f1.K = EE; f1.epi = 0;
    f1.Wm[0] = W1; f1.bias[0] = nullptr; f1.out[0] = t1p; f1.scale[0] = 1.f;
    f1.Wm[1] = W3; f1.bias[1] = nullptr; f1.out[1] = t2p; f1.scale[1] = 1.f;
    tf32gemm_kernel<<<dim3(32, 24, 2), 256>>>(f1);

    silu_mul_kernel<<<(NFF + 255)/256, 256>>>(t1p, t2p, NFF);

    GemmArgs f2 = {};
    f2.A = t1p; f2.N = EE; f2.K = FFD; f2.epi = 0;
    f2.Wm[0] = W2; f2.bias[0] = nullptr; f2.out[0] = attnp; f2.scale[0] = 1.f;
    tf32gemm_kernel<<<dim3(32, 6, 1), 256>>>(f2);

    add_ln_kernel<<<BB*SS, 256>>>(h0p, attnp, ln1g, ln1b, out);
}

// round 10
// speedup vs baseline: 2.2211x; 1.0447x over previous
#include <cuda_runtime.h>
#include <cuda_bf16.h>
#include <math.h>

#define BB 2
#define SS 2048
#define EE 768
#define HH 12
#define DHH 64
#define WW 256
#define GG 16
#define FFD 3072
#define NEGV (-1e9f)

#define NQKV (BB*HH*SS*DHH)
#define NXE  (BB*SS*EE)
#define NFF  (BB*SS*FFD)

// ---------------- device scratch ----------------
__device__ float g_q[NQKV];
__device__ float g_k[NQKV];
__device__ float g_v[NQKV];
__device__ float g_gq[NQKV];
__device__ float g_gk[NQKV];
__device__ float g_gv[NQKV];
__device__ float g_attn[NXE];
__device__ float g_h0[NXE];
__device__ float g_t1[NFF];
__device__ float g_t2[NFF];
__device__ float g_tbuf[BB*SS];

// ---------------- mma / cp.async helpers ----------------
__device__ __forceinline__ void mma_tf32(float (&d)[4], const unsigned* a, const unsigned* b) {
    asm volatile(
        "mma.sync.aligned.m16n8k8.row.col.f32.tf32.tf32.f32 "
        "{%0,%1,%2,%3}, {%4,%5,%6,%7}, {%8,%9}, {%0,%1,%2,%3};\n"
        : "+f"(d[0]), "+f"(d[1]), "+f"(d[2]), "+f"(d[3])
        : "r"(a[0]), "r"(a[1]), "r"(a[2]), "r"(a[3]), "r"(b[0]), "r"(b[1]));
}
__device__ __forceinline__ void cpasync16(unsigned dst, const void* src) {
    asm volatile("cp.async.cg.shared.global [%0], [%1], 16;\n" :: "r"(dst), "l"(src));
}
__device__ __forceinline__ void cp_commit() {
    asm volatile("cp.async.commit_group;\n");
}
template <int N> __device__ __forceinline__ void cp_wait() {
    asm volatile("cp.async.wait_group %0;\n" :: "n"(N));
}

// ---------------- cumsum of global flags -> t ----------------
__global__ void mask_cumsum_kernel(const int* __restrict__ am,
                                   const int* __restrict__ gm,
                                   float* __restrict__ tb) {
    int b = blockIdx.x;
    __shared__ int mg[SS];
    for (int i = threadIdx.x; i < SS; i += blockDim.x)
        mg[i] = am[b*SS + i] * (gm[b*SS + i] + 1);
    __syncthreads();
    if (threadIdx.x == 0) {
        int c = 0;
        for (int i = 0; i < SS; i++) {
            c += (mg[i] == 2);
            tb[b*SS + i] = (mg[i] == 0) ? 0.f : (float)c;
        }
    }
}

// ---------------- tf32 tensor-core GEMM (cp.async + padded smem) ----------------
struct GemmArgs {
    const float* A;
    const float* Wm[6];
    const float* bias[6];
    float* out[6];
    float scale[6];
    int N, K, epi;
};

#define APAD 20
#define BPAD 136

__global__ __launch_bounds__(256, 2) void tf32gemm_kernel(GemmArgs g) {
    const int z = blockIdx.z;
    const float* __restrict__ A = g.A;
    const float* __restrict__ W = g.Wm[z];
    const float* __restrict__ bias = g.bias[z];
    float* __restrict__ out = g.out[z];
    const int N = g.N, K = g.K;
    const int bm = blockIdx.x << 7, bn = blockIdx.y << 7;

    const int tid = threadIdx.x;
    const int lane = tid & 31, warp = tid >> 5;
    const int wm = (warp >> 2) << 6;
    const int wn = (warp & 3) << 5;
    const int gl = lane >> 2, qd = lane & 3;

    __shared__ float As[2][128][APAD];
    __shared__ float Bs[2][16][BPAD];

    float acc[4][4][4];
#pragma unroll
    for (int i = 0; i < 4; i++)
#pragma unroll
        for (int j = 0; j < 4; j++)
#pragma unroll
            for (int r = 0; r < 4; r++) acc[i][j][r] = 0.f;

    const int am0 = tid >> 2,           akc0 = tid & 3;
    const int am1 = (tid + 256) >> 2,   akc1 = tid & 3;
    const int bk0 = tid >> 5,           bnc0 = tid & 31;
    const int bk1 = (tid + 256) >> 5,   bnc1 = tid & 31;

    const float* Agp0 = A + (size_t)(bm + am0) * K + (akc0 << 2);
    const float* Agp1 = A + (size_t)(bm + am1) * K + (akc1 << 2);
    const float* Wgp0 = W + (size_t)bk0 * N + bn + (bnc0 << 2);
    const float* Wgp1 = W + (size_t)bk1 * N + bn + (bnc1 << 2);

    unsigned sA0[2], sA1[2], sB0[2], sB1[2];
#pragma unroll
    for (int bf = 0; bf < 2; bf++) {
        sA0[bf] = (unsigned)__cvta_generic_to_shared(&As[bf][am0][akc0 << 2]);
        sA1[bf] = (unsigned)__cvta_generic_to_shared(&As[bf][am1][akc1 << 2]);
        sB0[bf] = (unsigned)__cvta_generic_to_shared(&Bs[bf][bk0][bnc0 << 2]);
        sB1[bf] = (unsigned)__cvta_generic_to_shared(&Bs[bf][bk1][bnc1 << 2]);
    }

    const int NIT = K >> 4;

    cpasync16(sA0[0], Agp0);
    cpasync16(sA1[0], Agp1);
    cpasync16(sB0[0], Wgp0);
    cpasync16(sB1[0], Wgp1);
    cp_commit();

    for (int it = 0; it < NIT; it++) {
        const int cur = it & 1;
        const bool more = (it + 1) < NIT;
        if (more) {
            const int nxt = cur ^ 1;
            int k0 = (it + 1) << 4;
            cpasync16(sA0[nxt], Agp0 + k0);
            cpasync16(sA1[nxt], Agp1 + k0);
            cpasync16(sB0[nxt], Wgp0 + (size_t)k0 * N);
            cpasync16(sB1[nxt], Wgp1 + (size_t)k0 * N);
            cp_commit();
            cp_wait<1>();
        } else {
            cp_wait<0>();
        }
        __syncthreads();

#pragma unroll
        for (int kt = 0; kt < 2; kt++) {
            const int k0 = kt << 3;
            unsigned afr[4][4], bfr[4][2];
#pragma unroll
            for (int mtl = 0; mtl < 4; mtl++) {
                int m = wm + (mtl << 4);
                afr[mtl][0] = __float_as_uint(As[cur][m + gl    ][k0 + qd    ]);
                afr[mtl][1] = __float_as_uint(As[cur][m + gl + 8][k0 + qd    ]);
                afr[mtl][2] = __float_as_uint(As[cur][m + gl    ][k0 + qd + 4]);
                afr[mtl][3] = __float_as_uint(As[cur][m + gl + 8][k0 + qd + 4]);
            }
#pragma unroll
            for (int ntl = 0; ntl < 4; ntl++) {
                int n = wn + (ntl << 3) + gl;
                bfr[ntl][0] = __float_as_uint(Bs[cur][k0 + qd    ][n]);
                bfr[ntl][1] = __float_as_uint(Bs[cur][k0 + qd + 4][n]);
            }
#pragma unroll
            for (int mtl = 0; mtl < 4; mtl++)
#pragma unroll
                for (int ntl = 0; ntl < 4; ntl++)
                    mma_tf32(acc[mtl][ntl], afr[mtl], bfr[ntl]);
        }
        __syncthreads();
    }

    const float sc = g.scale[z];
#pragma unroll
    for (int mtl = 0; mtl < 4; mtl++) {
        int row0 = bm + wm + (mtl << 4) + gl;
#pragma unroll
        for (int ntl = 0; ntl < 4; ntl++) {
            int col = bn + wn + (ntl << 3) + (qd << 1);
            float v0 = acc[mtl][ntl][0], v1 = acc[mtl][ntl][1];
            float v2 = acc[mtl][ntl][2], v3 = acc[mtl][ntl][3];
            if (bias) {
                float b0 = bias[col], b1 = bias[col + 1];
                v0 += b0; v1 += b1; v2 += b0; v3 += b1;
            }
            v0 *= sc; v1 *= sc; v2 *= sc; v3 *= sc;
            if (g.epi == 0) {
                *(float2*)(out + (size_t)row0 * N + col)       = make_float2(v0, v1);
                *(float2*)(out + (size_t)(row0 + 8) * N + col) = make_float2(v2, v3);
            } else {
                int h = col >> 6, d = col & 63;
                int b0i = row0 >> 11, s0 = row0 & (SS - 1);
                int row1 = row0 + 8;
                int b1i = row1 >> 11, s1 = row1 & (SS - 1);
                *(float2*)(out + (((size_t)(b0i*HH + h) * SS + s0) << 6) + d) = make_float2(v0, v1);
                *(float2*)(out + (((size_t)(b1i*HH + h) * SS + s1) << 6) + d) = make_float2(v2, v3);
            }
        }
    }
}

// ---------------- RoPE on q and k (in-place) ----------------
__global__ void rope_kernel(float* __restrict__ q, float* __restrict__ k,
                            const float* __restrict__ tb) {
    int idx = blockIdx.x * blockDim.x + threadIdx.x;
    const int total = BB*HH*SS*32;
    if (idx >= total) return;
    int d   = idx & 31;
    int rem = idx >> 5;
    int s   = rem & (SS-1);
    int rem2 = rem >> 11;
    int h   = rem2 % HH;
    int b   = rem2 / HH;
    float tt = tb[b*SS + s];
    float inv_freq = expf(-(float)d * 0.28782313662425574f);
    float sn, cs;
    sincosf(tt * inv_freq, &sn, &cs);
    size_t off = (((size_t)(b*HH + h) * SS + s) << 6) + d;
    float x1 = q[off], x2 = q[off + 32];
    q[off]      = x1*cs - x2*sn;
    q[off + 32] = x2*cs + x1*sn;
    x1 = k[off]; x2 = k[off + 32];
    k[off]      = x1*cs - x2*sn;
    k[off + 32] = x2*cs + x1*sn;
}

// ---------------- banded + global-key attention (ILP-restructured) ----------------
// one block = 16 queries of one (b,h). 529 scores/query (16 global + 513 band).
// Score phase: each lane computes 2 keys (kk=r, r+16) with 8 parallel FMA chains.
// AV phase: 2 keys per iteration into 2 accumulator sets (8 chains).
__global__ __launch_bounds__(256) void band_attn_kernel(
    const float* __restrict__ q, const float* __restrict__ k, const float* __restrict__ v,
    const int* __restrict__ am, const int* __restrict__ gm,
    float* __restrict__ attn)
{
    const int b = blockIdx.z, h = blockIdx.y, base = blockIdx.x << 4;
    const int tid = threadIdx.x;
    const int p = tid >> 4, r = tid & 15;

    __shared__ float qs[16][64];
    __shared__ float sc[16][536];
    __shared__ float ks[32][68];
    __shared__ unsigned char rmv[32];

    const float* qb = q + ((size_t)(b*HH + h) * SS) * DHH;
    const float* kb = k + ((size_t)(b*HH + h) * SS) * DHH;
    const float* vb = v + ((size_t)(b*HH + h) * SS) * DHH;

    // load q tile (16x64) and the 16 global keys
    {
        const float4* src = (const float4*)(qb + (size_t)base * DHH);
        float4* dst = (float4*)&qs[0][0];
        dst[tid] = src[tid];
        const float4* ksrc = (const float4*)kb;
        int kk = tid >> 4, d4 = tid & 15;
        *((float4*)&ks[kk][d4*4]) = ksrc[tid];
    }
    __syncthreads();

    // global-key scores (idx 0..15): 4 independent chains
    {
        float a0 = 0.f, a1 = 0.f, a2 = 0.f, a3 = 0.f;
        const float4* qp = (const float4*)qs[p];
        const float4* kp = (const float4*)&ks[r][0];
#pragma unroll
        for (int d4 = 0; d4 < 16; d4++) {
            float4 a = qp[d4], bb = kp[d4];
            a0 += a.x*bb.x; a1 += a.y*bb.y; a2 += a.z*bb.z; a3 += a.w*bb.w;
        }
        sc[p][r] = (a0 + a1) + (a2 + a3);
    }
    __syncthreads();

    const int jmin = base - WW;
    // band scores: lane handles keys kk0=r, kk1=r+16 of each 32-key chunk.
    for (int c = 0; c < 17; c++) {
        int j0 = jmin + c*32;
        for (int i = tid; i < 32*16; i += 256) {
            int kk = i >> 4, d4 = i & 15;
            int j = j0 + kk;
            float4 val = make_float4(0.f, 0.f, 0.f, 0.f);
            if (j >= 0 && j < SS) val = *(const float4*)(kb + (size_t)j*DHH + d4*4);
            *((float4*)&ks[kk][d4*4]) = val;
        }
        if (tid < 32) {
            int j = j0 + tid;
            int rm = 1;
            if (j >= 0 && j < SS) { int m = am[b*SS+j] * (gm[b*SS+j] + 1); rm = (m != 1); }
            rmv[tid] = (unsigned char)rm;
        }
        __syncthreads();

        {
            const int kk0 = r, kk1 = r + 16;
            float e0=0.f,e1=0.f,e2=0.f,e3=0.f;
            float f0=0.f,f1=0.f,f2=0.f,f3=0.f;
            const float4* qp  = (const float4*)qs[p];
            const float4* kp0 = (const float4*)&ks[kk0][0];
            const float4* kp1 = (const float4*)&ks[kk1][0];
#pragma unroll
            for (int d4 = 0; d4 < 16; d4++) {
                float4 a  = qp[d4];
                float4 b0 = kp0[d4];
                float4 b1 = kp1[d4];
                e0 += a.x*b0.x; e1 += a.y*b0.y; e2 += a.z*b0.z; e3 += a.w*b0.w;
                f0 += a.x*b1.x; f1 += a.y*b1.y; f2 += a.z*b1.z; f3 += a.w*b1.w;
            }
            float s0 = (e0 + e1) + (e2 + e3);
            float s1 = (f0 + f1) + (f2 + f3);
            int l0 = c*32 + kk0 - p;
            int l1 = c*32 + kk1 - p;
            if (l0 >= 0 && l0 <= 512) sc[p][16 + l0] = rmv[kk0] ? NEGV : s0;
            if (l1 >= 0 && l1 <= 512) sc[p][16 + l1] = rmv[kk1] ? NEGV : s1;
        }
        __syncthreads();
    }

    // softmax over 529 entries; 16 lanes per query
    float mx = -3.4e38f;
    for (int idx = r; idx < 529; idx += 16) mx = fmaxf(mx, sc[p][idx]);
#pragma unroll
    for (int o = 8; o; o >>= 1) mx = fmaxf(mx, __shfl_xor_sync(0xffffffffu, mx, o, 16));
    float sum = 0.f;
    for (int idx = r; idx < 529; idx += 16) {
        float e = __expf(sc[p][idx] - mx);
        sc[p][idx] = e;
        sum += e;
    }
#pragma unroll
    for (int o = 8; o; o >>= 1) sum += __shfl_xor_sync(0xffffffffu, sum, o, 16);
    float inv = 1.f / sum;
    __syncthreads();

    // AV: lane owns d = 4r..4r+3; two accumulator sets for 2-key ILP
    float4 aca = make_float4(0.f, 0.f, 0.f, 0.f);
    float4 acb = make_float4(0.f, 0.f, 0.f, 0.f);
    {   // global values
        const float4* vsrc = (const float4*)vb;
        int kk = tid >> 4, d4 = tid & 15;
        *((float4*)&ks[kk][d4*4]) = vsrc[tid];
    }
    __syncthreads();
#pragma unroll
    for (int gidx = 0; gidx < 16; gidx += 2) {
        float pr0 = sc[p][gidx], pr1 = sc[p][gidx + 1];
        float4 v0 = *(const float4*)&ks[gidx][r*4];
        float4 v1 = *(const float4*)&ks[gidx + 1][r*4];
        aca.x += pr0*v0.x; aca.y += pr0*v0.y; aca.z += pr0*v0.z; aca.w += pr0*v0.w;
        acb.x += pr1*v1.x; acb.y += pr1*v1.y; acb.z += pr1*v1.z; acb.w += pr1*v1.w;
    }
    __syncthreads();
    for (int c = 0; c < 17; c++) {
        int j0 = jmin + c*32;
        for (int i = tid; i < 32*16; i += 256) {
            int kk = i >> 4, d4 = i & 15;
            int j = j0 + kk;
            float4 val = make_float4(0.f, 0.f, 0.f, 0.f);
            if (j >= 0 && j < SS) val = *(const float4*)(vb + (size_t)j*DHH + d4*4);
            *((float4*)&ks[kk][d4*4]) = val;
        }
        __syncthreads();
        int lbase = c*32 - p;
        int lo = lbase > 0 ? lbase : 0;
        int hi = lbase + 31; if (hi > 512) hi = 512;
        int l = lo;
        for (; l + 1 <= hi; l += 2) {
            int kk = p + l - c*32;
            float pr0 = sc[p][16 + l];
            float pr1 = sc[p][17 + l];
            float4 v0 = *(const float4*)&ks[kk][r*4];
            float4 v1 = *(const float4*)&ks[kk + 1][r*4];
            aca.x += pr0*v0.x; aca.y += pr0*v0.y; aca.z += pr0*v0.z; aca.w += pr0*v0.w;
            acb.x += pr1*v1.x; acb.y += pr1*v1.y; acb.z += pr1*v1.z; acb.w += pr1*v1.w;
        }
        if (l <= hi) {
            int kk = p + l - c*32;
            float pr0 = sc[p][16 + l];
            float4 v0 = *(const float4*)&ks[kk][r*4];
            aca.x += pr0*v0.x; aca.y += pr0*v0.y; aca.z += pr0*v0.z; aca.w += pr0*v0.w;
        }
        __syncthreads();
    }

    int iq = base + p;
    int mm = am[b*SS + iq] * (gm[b*SS + iq] + 1);
    float scl = (mm == 0) ? 0.f : inv;
    float4 o4 = make_float4((aca.x + acb.x)*scl, (aca.y + acb.y)*scl,
                            (aca.z + acb.z)*scl, (aca.w + acb.w)*scl);
    *(float4*)(attn + ((size_t)b*SS + iq)*EE + h*DHH + r*4) = o4;
}

// ---------------- global attention (overwrites attn rows < G) ----------------
__global__ __launch_bounds__(256) void global_attn_kernel(
    const float* __restrict__ gq, const float* __restrict__ gk, const float* __restrict__ gv,
    const int* __restrict__ am, const int* __restrict__ gm,
    float* __restrict__ attn)
{
    int g = blockIdx.x, h = blockIdx.y, b = blockIdx.z;
    int tid = threadIdx.x;
    __shared__ float sc[SS];
    __shared__ float qrow[64];
    __shared__ float red[8];
    __shared__ float redv[4][64];

    const float* gkb = gk + ((size_t)(b*HH + h) * SS) * DHH;
    const float* gvb = gv + ((size_t)(b*HH + h) * SS) * DHH;
    if (tid < 64) qrow[tid] = gq[(((size_t)(b*HH + h) * SS + g) << 6) + tid];
    __syncthreads();

    float lmax = -3.4e38f;
    for (int j = tid; j < SS; j += 256) {
        int m = am[b*SS + j] * (gm[b*SS + j] + 1);
        float s;
        if (m == 0) s = NEGV;
        else {
            float a0=0.f,a1=0.f,a2=0.f,a3=0.f;
            const float4* kp = (const float4*)(gkb + (size_t)j * DHH);
            const float4* qp = (const float4*)qrow;
#pragma unroll
            for (int d4 = 0; d4 < 16; d4++) {
                float4 a = qp[d4], bb = kp[d4];
                a0 += a.x*bb.x; a1 += a.y*bb.y; a2 += a.z*bb.z; a3 += a.w*bb.w;
            }
            s = (a0 + a1) + (a2 + a3);
        }
        sc[j] = s;
        lmax = fmaxf(lmax, s);
    }
#pragma unroll
    for (int o = 16; o; o >>= 1) lmax = fmaxf(lmax, __shfl_xor_sync(0xffffffffu, lmax, o));
    if ((tid & 31) == 0) red[tid >> 5] = lmax;
    __syncthreads();
    float bmax = red[0];
#pragma unroll
    for (int w = 1; w < 8; w++) bmax = fmaxf(bmax, red[w]);

    float lsum = 0.f;
    for (int j = tid; j < SS; j += 256) {
        float e = __expf(sc[j] - bmax);
        sc[j] = e;
        lsum += e;
    }
#pragma unroll
    for (int o = 16; o; o >>= 1) lsum += __shfl_xor_sync(0xffffffffu, lsum, o);
    __syncthreads();
    if ((tid & 31) == 0) red[tid >> 5] = lsum;
    __syncthreads();
    float ssum = 0.f;
#pragma unroll
    for (int w = 0; w < 8; w++) ssum += red[w];
    float inv = 1.f / ssum;

    int grp = tid >> 6, d = tid & 63;
    float acc0 = 0.f, acc1 = 0.f;
    for (int j = grp; j < SS; j += 8) {
        acc0 += sc[j] * gvb[(size_t)j * DHH + d];
        acc1 += sc[j + 4] * gvb[(size_t)(j + 4) * DHH + d];
    }
    redv[grp][d] = acc0 + acc1;
    __syncthreads();
    if (grp == 0) {
        float o = (redv[0][d] + redv[1][d] + redv[2][d] + redv[3][d]) * inv;
        attn[((size_t)b*SS + g)*EE + h*DHH + d] = o;
    }
}

// ---------------- fused add + LayerNorm ----------------
__global__ __launch_bounds__(256) void add_ln_kernel(
    const float* __restrict__ a, const float* __restrict__ c,
    const float* __restrict__ gamma, const float* __restrict__ beta,
    float* __restrict__ out)
{
    int row = blockIdx.x;
    int tid = threadIdx.x;
    __shared__ float buf[EE];
    __shared__ float red[8];

    float local = 0.f;
#pragma unroll
    for (int i = 0; i < 3; i++) {
        int idx = tid + i*256;
        float v = a[(size_t)row*EE + idx] + c[(size_t)row*EE + idx];
        buf[idx] = v;
        local += v;
    }
#pragma unroll
    for (int o = 16; o; o >>= 1) local += __shfl_xor_sync(0xffffffffu, local, o);
    if ((tid & 31) == 0) red[tid >> 5] = local;
    __syncthreads();
    float s = 0.f;
#pragma unroll
    for (int w = 0; w < 8; w++) s += red[w];
    float mean = s * (1.f/768.f);

    float lv = 0.f;
#pragma unroll
    for (int i = 0; i < 3; i++) {
        float dd = buf[tid + i*256] - mean;
        lv += dd*dd;
    }
#pragma unroll
    for (int o = 16; o; o >>= 1) lv += __shfl_xor_sync(0xffffffffu, lv, o);
    __syncthreads();
    if ((tid & 31) == 0) red[tid >> 5] = lv;
    __syncthreads();
    float vs = 0.f;
#pragma unroll
    for (int w = 0; w < 8; w++) vs += red[w];
    float invstd = rsqrtf(vs * (1.f/768.f) + 1e-5f);

#pragma unroll
    for (int i = 0; i < 3; i++) {
        int idx = tid + i*256;
        out[(size_t)row*EE + idx] = (buf[idx] - mean) * invstd * gamma[idx] + beta[idx];
    }
}

// ---------------- SiLU(t1) * t2 -> t1 ----------------
__global__ void silu_mul_kernel(float* __restrict__ t1, const float* __restrict__ t2, int n) {
    int i = blockIdx.x * blockDim.x + threadIdx.x;
    if (i < n) {
        float a = t1[i];
        t1[i] = a / (1.f + expf(-a)) * t2[i];
    }
}

// ---------------- launch ----------------
extern "C" void kernel_launch(void* const* d_in, const int* in_sizes, int n_in,
                              void* d_out, int out_size) {
    (void)in_sizes; (void)n_in; (void)out_size;
    const float* x    = (const float*)d_in[0];
    const int*   am   = (const int*)d_in[1];
    const int*   gm   = (const int*)d_in[2];
    const float* Wq   = (const float*)d_in[3];  const float* bq  = (const float*)d_in[4];
    const float* Wk   = (const float*)d_in[5];  const float* bk  = (const float*)d_in[6];
    const float* Wv   = (const float*)d_in[7];  const float* bv  = (const float*)d_in[8];
    const float* Wqg  = (const float*)d_in[9];  const float* bqg = (const float*)d_in[10];
    const float* Wkg  = (const float*)d_in[11]; const float* bkg = (const float*)d_in[12];
    const float* Wvg  = (const float*)d_in[13]; const float* bvg = (const float*)d_in[14];
    const float* ln0g = (const float*)d_in[15]; const float* ln0b = (const float*)d_in[16];
    const float* ln1g = (const float*)d_in[17]; const float* ln1b = (const float*)d_in[18];
    const float* W1   = (const float*)d_in[19];
    const float* W3   = (const float*)d_in[20];
    const float* W2   = (const float*)d_in[21];
    float* out = (float*)d_out;

    float *qp, *kp, *vp, *gqp, *gkp, *gvp, *attnp, *h0p, *t1p, *t2p, *tbp;
    cudaGetSymbolAddress((void**)&qp,  g_q);
    cudaGetSymbolAddress((void**)&kp,  g_k);
    cudaGetSymbolAddress((void**)&vp,  g_v);
    cudaGetSymbolAddress((void**)&gqp, g_gq);
    cudaGetSymbolAddress((void**)&gkp, g_gk);
    cudaGetSymbolAddress((void**)&gvp, g_gv);
    cudaGetSymbolAddress((void**)&attnp, g_attn);
    cudaGetSymbolAddress((void**)&h0p, g_h0);
    cudaGetSymbolAddress((void**)&t1p, g_t1);
    cudaGetSymbolAddress((void**)&t2p, g_t2);
    cudaGetSymbolAddress((void**)&tbp, g_tbuf);

    mask_cumsum_kernel<<<BB, 256>>>(am, gm, tbp);

    GemmArgs pa = {};
    pa.A = x; pa.N = EE; pa.K = EE; pa.epi = 1;
    pa.Wm[0] = Wq;  pa.bias[0] = bq;  pa.out[0] = qp;  pa.scale[0] = 0.125f;
    pa.Wm[1] = Wk;  pa.bias[1] = bk;  pa.out[1] = kp;  pa.scale[1] = 1.f;
    pa.Wm[2] = Wv;  pa.bias[2] = bv;  pa.out[2] = vp;  pa.scale[2] = 1.f;
    pa.Wm[3] = Wqg; pa.bias[3] = bqg; pa.out[3] = gqp; pa.scale[3] = 0.125f;
    pa.Wm[4] = Wkg; pa.bias[4] = bkg; pa.out[4] = gkp; pa.scale[4] = 1.f;
    pa.Wm[5] = Wvg; pa.bias[5] = bvg; pa.out[5] = gvp; pa.scale[5] = 1.f;
    tf32gemm_kernel<<<dim3(32, 6, 6), 256>>>(pa);

    rope_kernel<<<(BB*HH*SS*32 + 255)/256, 256>>>(qp, kp, tbp);

    band_attn_kernel<<<dim3(SS/16, HH, BB), 256>>>(qp, kp, vp, am, gm, attnp);
    global_attn_kernel<<<dim3(GG, HH, BB), 256>>>(gqp, gkp, gvp, am, gm, attnp);

    add_ln_kernel<<<BB*SS, 256>>>(x, attnp, ln0g, ln0b, h0p);

    GemmArgs f1 = {};
    f1.A = h0p; f1.N = FFD; f1.K = EE; f1.epi = 0;
    f1.Wm[0] = W1; f1.bias[0] = nullptr; f1.out[0] = t1p; f1.scale[0] = 1.f;
    f1.Wm[1] = W3; f1.bias[1] = nullptr; f1.out[1] = t2p; f1.scale[1] = 1.f;
    tf32gemm_kernel<<<dim3(32, 24, 2), 256>>>(f1);

    silu_mul_kernel<<<(NFF + 255)/256, 256>>>(t1p, t2p, NFF);

    GemmArgs f2 = {};
    f2.A = t1p; f2.N = EE; f2.K = FFD; f2.epi = 0;
    f2.Wm[0] = W2; f2.bias[0] = nullptr; f2.out[0] = attnp; f2.scale[0] = 1.f;
    tf32gemm_kernel<<<dim3(32, 6, 1), 256>>>(f2);

    add_ln_kernel<<<BB*SS, 256>>>(h0p, attnp, ln1g, ln1b, out);
}

// round 11
// speedup vs baseline: 2.9420x; 1.3246x over previous
#include <cuda_runtime.h>
#include <cuda_bf16.h>
#include <math.h>

#define BB 2
#define SS 2048
#define EE 768
#define HH 12
#define DHH 64
#define WW 256
#define GG 16
#define FFD 3072
#define NEGV (-1e9f)

#define NQKV (BB*HH*SS*DHH)
#define NXE  (BB*SS*EE)
#define NFF  (BB*SS*FFD)

// ---------------- device scratch ----------------
__device__ float g_q[NQKV];
__device__ float g_k[NQKV];
__device__ float g_v[NQKV];
__device__ float g_gq[NQKV];
__device__ float g_gk[NQKV];
__device__ float g_gv[NQKV];
__device__ float g_attn[NXE];
__device__ float g_h0[NXE];
__device__ float g_t1[NFF];
__device__ float g_t2[NFF];
__device__ float g_tbuf[BB*SS];

// ---------------- mma / cp.async helpers ----------------
__device__ __forceinline__ void mma_tf32(float (&d)[4], const unsigned* a, const unsigned* b) {
    asm volatile(
        "mma.sync.aligned.m16n8k8.row.col.f32.tf32.tf32.f32 "
        "{%0,%1,%2,%3}, {%4,%5,%6,%7}, {%8,%9}, {%0,%1,%2,%3};\n"
        : "+f"(d[0]), "+f"(d[1]), "+f"(d[2]), "+f"(d[3])
        : "r"(a[0]), "r"(a[1]), "r"(a[2]), "r"(a[3]), "r"(b[0]), "r"(b[1]));
}
__device__ __forceinline__ void cpasync16(unsigned dst, const void* src) {
    asm volatile("cp.async.cg.shared.global [%0], [%1], 16;\n" :: "r"(dst), "l"(src));
}
__device__ __forceinline__ void cp_commit() {
    asm volatile("cp.async.commit_group;\n");
}
template <int N> __device__ __forceinline__ void cp_wait() {
    asm volatile("cp.async.wait_group %0;\n" :: "n"(N));
}
// RNA round fp32 -> tf32 (kept in fp32 container)
__device__ __forceinline__ float tfr(float x) {
    unsigned r; asm("cvt.rna.tf32.f32 %0, %1;" : "=r"(r) : "f"(x));
    return __uint_as_float(r);
}

// ---------------- cumsum of global flags -> t ----------------
__global__ void mask_cumsum_kernel(const int* __restrict__ am,
                                   const int* __restrict__ gm,
                                   float* __restrict__ tb) {
    int b = blockIdx.x;
    __shared__ int mg[SS];
    for (int i = threadIdx.x; i < SS; i += blockDim.x)
        mg[i] = am[b*SS + i] * (gm[b*SS + i] + 1);
    __syncthreads();
    if (threadIdx.x == 0) {
        int c = 0;
        for (int i = 0; i < SS; i++) {
            c += (mg[i] == 2);
            tb[b*SS + i] = (mg[i] == 0) ? 0.f : (float)c;
        }
    }
}

// ---------------- tf32 tensor-core GEMM (cp.async + padded smem) ----------------
struct GemmArgs {
    const float* A;
    const float* Wm[6];
    const float* bias[6];
    float* out[6];
    float scale[6];
    int N, K, epi;
};

#define APAD 20
#define BPAD 136

__global__ __launch_bounds__(256, 2) void tf32gemm_kernel(GemmArgs g) {
    const int z = blockIdx.z;
    const float* __restrict__ A = g.A;
    const float* __restrict__ W = g.Wm[z];
    const float* __restrict__ bias = g.bias[z];
    float* __restrict__ out = g.out[z];
    const int N = g.N, K = g.K;
    const int bm = blockIdx.x << 7, bn = blockIdx.y << 7;

    const int tid = threadIdx.x;
    const int lane = tid & 31, warp = tid >> 5;
    const int wm = (warp >> 2) << 6;
    const int wn = (warp & 3) << 5;
    const int gl = lane >> 2, qd = lane & 3;

    __shared__ float As[2][128][APAD];
    __shared__ float Bs[2][16][BPAD];

    float acc[4][4][4];
#pragma unroll
    for (int i = 0; i < 4; i++)
#pragma unroll
        for (int j = 0; j < 4; j++)
#pragma unroll
            for (int r = 0; r < 4; r++) acc[i][j][r] = 0.f;

    const int am0 = tid >> 2,           akc0 = tid & 3;
    const int am1 = (tid + 256) >> 2,   akc1 = tid & 3;
    const int bk0 = tid >> 5,           bnc0 = tid & 31;
    const int bk1 = (tid + 256) >> 5,   bnc1 = tid & 31;

    const float* Agp0 = A + (size_t)(bm + am0) * K + (akc0 << 2);
    const float* Agp1 = A + (size_t)(bm + am1) * K + (akc1 << 2);
    const float* Wgp0 = W + (size_t)bk0 * N + bn + (bnc0 << 2);
    const float* Wgp1 = W + (size_t)bk1 * N + bn + (bnc1 << 2);

    unsigned sA0[2], sA1[2], sB0[2], sB1[2];
#pragma unroll
    for (int bf = 0; bf < 2; bf++) {
        sA0[bf] = (unsigned)__cvta_generic_to_shared(&As[bf][am0][akc0 << 2]);
        sA1[bf] = (unsigned)__cvta_generic_to_shared(&As[bf][am1][akc1 << 2]);
        sB0[bf] = (unsigned)__cvta_generic_to_shared(&Bs[bf][bk0][bnc0 << 2]);
        sB1[bf] = (unsigned)__cvta_generic_to_shared(&Bs[bf][bk1][bnc1 << 2]);
    }

    const int NIT = K >> 4;

    cpasync16(sA0[0], Agp0);
    cpasync16(sA1[0], Agp1);
    cpasync16(sB0[0], Wgp0);
    cpasync16(sB1[0], Wgp1);
    cp_commit();

    for (int it = 0; it < NIT; it++) {
        const int cur = it & 1;
        const bool more = (it + 1) < NIT;
        if (more) {
            const int nxt = cur ^ 1;
            int k0 = (it + 1) << 4;
            cpasync16(sA0[nxt], Agp0 + k0);
            cpasync16(sA1[nxt], Agp1 + k0);
            cpasync16(sB0[nxt], Wgp0 + (size_t)k0 * N);
            cpasync16(sB1[nxt], Wgp1 + (size_t)k0 * N);
            cp_commit();
            cp_wait<1>();
        } else {
            cp_wait<0>();
        }
        __syncthreads();

#pragma unroll
        for (int kt = 0; kt < 2; kt++) {
            const int k0 = kt << 3;
            unsigned afr[4][4], bfr[4][2];
#pragma unroll
            for (int mtl = 0; mtl < 4; mtl++) {
                int m = wm + (mtl << 4);
                afr[mtl][0] = __float_as_uint(As[cur][m + gl    ][k0 + qd    ]);
                afr[mtl][1] = __float_as_uint(As[cur][m + gl + 8][k0 + qd    ]);
                afr[mtl][2] = __float_as_uint(As[cur][m + gl    ][k0 + qd + 4]);
                afr[mtl][3] = __float_as_uint(As[cur][m + gl + 8][k0 + qd + 4]);
            }
#pragma unroll
            for (int ntl = 0; ntl < 4; ntl++) {
                int n = wn + (ntl << 3) + gl;
                bfr[ntl][0] = __float_as_uint(Bs[cur][k0 + qd    ][n]);
                bfr[ntl][1] = __float_as_uint(Bs[cur][k0 + qd + 4][n]);
            }
#pragma unroll
            for (int mtl = 0; mtl < 4; mtl++)
#pragma unroll
                for (int ntl = 0; ntl < 4; ntl++)
                    mma_tf32(acc[mtl][ntl], afr[mtl], bfr[ntl]);
        }
        __syncthreads();
    }

    const float sc = g.scale[z];
#pragma unroll
    for (int mtl = 0; mtl < 4; mtl++) {
        int row0 = bm + wm + (mtl << 4) + gl;
#pragma unroll
        for (int ntl = 0; ntl < 4; ntl++) {
            int col = bn + wn + (ntl << 3) + (qd << 1);
            float v0 = acc[mtl][ntl][0], v1 = acc[mtl][ntl][1];
            float v2 = acc[mtl][ntl][2], v3 = acc[mtl][ntl][3];
            if (bias) {
                float b0 = bias[col], b1 = bias[col + 1];
                v0 += b0; v1 += b1; v2 += b0; v3 += b1;
            }
            v0 *= sc; v1 *= sc; v2 *= sc; v3 *= sc;
            if (g.epi == 0) {
                *(float2*)(out + (size_t)row0 * N + col)       = make_float2(v0, v1);
                *(float2*)(out + (size_t)(row0 + 8) * N + col) = make_float2(v2, v3);
            } else {
                int h = col >> 6, d = col & 63;
                int b0i = row0 >> 11, s0 = row0 & (SS - 1);
                int row1 = row0 + 8;
                int b1i = row1 >> 11, s1 = row1 & (SS - 1);
                *(float2*)(out + (((size_t)(b0i*HH + h) * SS + s0) << 6) + d) = make_float2(v0, v1);
                *(float2*)(out + (((size_t)(b1i*HH + h) * SS + s1) << 6) + d) = make_float2(v2, v3);
            }
        }
    }
}

// ---------------- RoPE on q and k (in-place) ----------------
__global__ void rope_kernel(float* __restrict__ q, float* __restrict__ k,
                            const float* __restrict__ tb) {
    int idx = blockIdx.x * blockDim.x + threadIdx.x;
    const int total = BB*HH*SS*32;
    if (idx >= total) return;
    int d   = idx & 31;
    int rem = idx >> 5;
    int s   = rem & (SS-1);
    int rem2 = rem >> 11;
    int h   = rem2 % HH;
    int b   = rem2 / HH;
    float tt = tb[b*SS + s];
    float inv_freq = expf(-(float)d * 0.28782313662425574f);
    float sn, cs;
    sincosf(tt * inv_freq, &sn, &cs);
    size_t off = (((size_t)(b*HH + h) * SS + s) << 6) + d;
    float x1 = q[off], x2 = q[off + 32];
    q[off]      = x1*cs - x2*sn;
    q[off + 32] = x2*cs + x1*sn;
    x1 = k[off]; x2 = k[off + 32];
    k[off]      = x1*cs - x2*sn;
    k[off + 32] = x2*cs + x1*sn;
}

// ---------------- banded + global-key attention (tensor-core mma) ----------------
// one block = 16 queries of one (b,h). Scores S[16x529] and AV O[16x64] via
// mma.m16n8k8.tf32. K/V staged in 4-chunk rounds (32 keys/chunk, stride-72 rows).
// Dynamic smem layout (floats):
//   qs[16][68] | sc[16][536] | ks[4][32][72] | scl[16] | rmv[128] (ints)
#define BAND_SMEM ((1088 + 8576 + 9216 + 16) * 4 + 128 * 4)

__global__ __launch_bounds__(256) void band_attn_kernel(
    const float* __restrict__ q, const float* __restrict__ k, const float* __restrict__ v,
    const int* __restrict__ am, const int* __restrict__ gm,
    float* __restrict__ attn)
{
    extern __shared__ float sm[];
    float* qs  = sm;                    // [16][68]
    float* sc  = sm + 1088;             // [16][536]: [0..15]=global, [16+l] l in [0,512]
    float* ks  = sm + 1088 + 8576;      // [4][32][72]
    float* scl = ks + 9216;             // [16]
    int*   rmv = (int*)(scl + 16);      // [128]

    const int b = blockIdx.z, h = blockIdx.y, base = blockIdx.x << 4;
    const int tid = threadIdx.x;
    const int lane = tid & 31, warp = tid >> 5;
    const int gl = lane >> 2, qd = lane & 3;

    const float* qb = q + ((size_t)(b*HH + h) * SS) * DHH;
    const float* kb = k + ((size_t)(b*HH + h) * SS) * DHH;
    const float* vb = v + ((size_t)(b*HH + h) * SS) * DHH;

    // stage q tile (16x64, tf32-rounded) and the 16 global keys
    {
        int row = tid >> 4, d4 = tid & 15;
        float4 v4 = *(const float4*)(qb + (((size_t)(base + row)) << 6) + (d4 << 2));
        float* dq = qs + row*68 + (d4 << 2);
        dq[0] = tfr(v4.x); dq[1] = tfr(v4.y); dq[2] = tfr(v4.z); dq[3] = tfr(v4.w);
        float4 k4 = *(const float4*)(kb + (((size_t)row) << 6) + (d4 << 2));
        float* dk = ks + row*72 + (d4 << 2);
        dk[0] = tfr(k4.x); dk[1] = tfr(k4.y); dk[2] = tfr(k4.z); dk[3] = tfr(k4.w);
    }
    __syncthreads();

    // per-warp Q fragments (held across entire score phase)
    unsigned aq[8][4];
#pragma unroll
    for (int k8 = 0; k8 < 8; k8++) {
        int k0 = k8 << 3;
        aq[k8][0] = __float_as_uint(qs[gl*68       + k0 + qd    ]);
        aq[k8][1] = __float_as_uint(qs[(gl+8)*68   + k0 + qd    ]);
        aq[k8][2] = __float_as_uint(qs[gl*68       + k0 + qd + 4]);
        aq[k8][3] = __float_as_uint(qs[(gl+8)*68   + k0 + qd + 4]);
    }

    // global-key scores (unmasked per reference): warps 0,1 each do 8 keys
    if (warp < 2) {
        float acc[4] = {0.f, 0.f, 0.f, 0.f};
        unsigned bfr[2];
#pragma unroll
        for (int k8 = 0; k8 < 8; k8++) {
            int k0 = k8 << 3;
            bfr[0] = __float_as_uint(ks[(warp*8 + gl)*72 + k0 + qd    ]);
            bfr[1] = __float_as_uint(ks[(warp*8 + gl)*72 + k0 + qd + 4]);
            mma_tf32(acc, aq[k8], bfr);
        }
        int key = warp*8 + (qd << 1);
        sc[gl*536     + key    ] = acc[0];
        sc[gl*536     + key + 1] = acc[1];
        sc[(gl+8)*536 + key    ] = acc[2];
        sc[(gl+8)*536 + key + 1] = acc[3];
    }
    __syncthreads();

    const int jmin = base - WW;

    // band scores: 5 rounds of up to 4 chunks; warp (w>>1) owns chunk, (w&1) owns ntile pair
    for (int round = 0; round < 5; round++) {
        const int c0 = round << 2;
        const int nch = (round < 4) ? 4 : 1;
        for (int i = tid; i < (nch << 9); i += 256) {
            int cidx = i >> 9, rem = i & 511;
            int kk = rem >> 4, d4 = rem & 15;
            int j = jmin + ((c0 + cidx) << 5) + kk;
            float4 v4 = make_float4(0.f, 0.f, 0.f, 0.f);
            if (j >= 0 && j < SS) v4 = *(const float4*)(kb + (((size_t)j) << 6) + (d4 << 2));
            float* dst = ks + cidx*2304 + kk*72 + (d4 << 2);
            dst[0] = tfr(v4.x); dst[1] = tfr(v4.y); dst[2] = tfr(v4.z); dst[3] = tfr(v4.w);
        }
        for (int i = tid; i < (nch << 5); i += 256) {
            int j = jmin + (c0 << 5) + i;
            int rm = 1;
            if (j >= 0 && j < SS) { int m = am[b*SS + j] * (gm[b*SS + j] + 1); rm = (m != 1); }
            rmv[i] = rm;
        }
        __syncthreads();

        int cidx = warp >> 1;
        if (cidx < nch) {
            int cb = (c0 + cidx) << 5;
            const float* kc = ks + cidx*2304;
#pragma unroll
            for (int t = 0; t < 2; t++) {
                int ntile = ((warp & 1) << 1) + t;
                float acc[4] = {0.f, 0.f, 0.f, 0.f};
                unsigned bfr[2];
#pragma unroll
                for (int k8 = 0; k8 < 8; k8++) {
                    int k0 = k8 << 3;
                    bfr[0] = __float_as_uint(kc[(ntile*8 + gl)*72 + k0 + qd    ]);
                    bfr[1] = __float_as_uint(kc[(ntile*8 + gl)*72 + k0 + qd + 4]);
                    mma_tf32(acc, aq[k8], bfr);
                }
                int kkA = (ntile << 3) + (qd << 1);
                int r0 = rmv[(cidx << 5) + kkA];
                int r1 = rmv[(cidx << 5) + kkA + 1];
                int l0 = cb + kkA - gl;
                int l1 = l0 + 1;
                int l2 = l0 - 8;
                int l3 = l2 + 1;
                if (l0 >= 0 && l0 <= 512) sc[gl*536     + 16 + l0] = r0 ? NEGV : acc[0];
                if (l1 >= 0 && l1 <= 512) sc[gl*536     + 16 + l1] = r1 ? NEGV : acc[1];
                if (l2 >= 0 && l2 <= 512) sc[(gl+8)*536 + 16 + l2] = r0 ? NEGV : acc[2];
                if (l3 >= 0 && l3 <= 512) sc[(gl+8)*536 + 16 + l3] = r1 ? NEGV : acc[3];
            }
        }
        __syncthreads();
    }

    // softmax over 529 entries per query; store tf32-rounded probs + per-query scale
    {
        const int p = tid >> 4, r = tid & 15;
        float mx = -3.4e38f;
        for (int idx = r; idx < 529; idx += 16) mx = fmaxf(mx, sc[p*536 + idx]);
#pragma unroll
        for (int o = 8; o; o >>= 1) mx = fmaxf(mx, __shfl_xor_sync(0xffffffffu, mx, o, 16));
        float sum = 0.f;
        for (int idx = r; idx < 529; idx += 16) {
            float e = __expf(sc[p*536 + idx] - mx);
            sc[p*536 + idx] = tfr(e);
            sum += e;
        }
#pragma unroll
        for (int o = 8; o; o >>= 1) sum += __shfl_xor_sync(0xffffffffu, sum, o, 16);
        if (r == 0) {
            int iq = base + p;
            int mm = am[b*SS + iq] * (gm[b*SS + iq] + 1);
            scl[p] = (mm == 0) ? 0.f : (1.f / sum);
        }
    }
    __syncthreads();

    // AV: warp owns dims [warp*8, warp*8+8)
    float av[4] = {0.f, 0.f, 0.f, 0.f};
    const int nd = (warp << 3) + gl;

    // global V (16 rows) staged into ks
    {
        int row = tid >> 4, d4 = tid & 15;
        float4 v4 = *(const float4*)(vb + (((size_t)row) << 6) + (d4 << 2));
        float* dst = ks + row*72 + (d4 << 2);
        dst[0] = tfr(v4.x); dst[1] = tfr(v4.y); dst[2] = tfr(v4.z); dst[3] = tfr(v4.w);
    }
    __syncthreads();
    {
        unsigned afr[4], bfr[2];
#pragma unroll
        for (int k8 = 0; k8 < 2; k8++) {
            int k0 = k8 << 3;
            afr[0] = __float_as_uint(sc[gl*536     + k0 + qd    ]);
            afr[1] = __float_as_uint(sc[(gl+8)*536 + k0 + qd    ]);
            afr[2] = __float_as_uint(sc[gl*536     + k0 + qd + 4]);
            afr[3] = __float_as_uint(sc[(gl+8)*536 + k0 + qd + 4]);
            bfr[0] = __float_as_uint(ks[(k0 + qd    )*72 + nd]);
            bfr[1] = __float_as_uint(ks[(k0 + qd + 4)*72 + nd]);
            mma_tf32(av, afr, bfr);
        }
    }
    __syncthreads();

    for (int round = 0; round < 5; round++) {
        const int c0 = round << 2;
        const int nch = (round < 4) ? 4 : 1;
        for (int i = tid; i < (nch << 9); i += 256) {
            int cidx = i >> 9, rem = i & 511;
            int kk = rem >> 4, d4 = rem & 15;
            int j = jmin + ((c0 + cidx) << 5) + kk;
            float4 v4 = make_float4(0.f, 0.f, 0.f, 0.f);
            if (j >= 0 && j < SS) v4 = *(const float4*)(vb + (((size_t)j) << 6) + (d4 << 2));
            float* dst = ks + cidx*2304 + kk*72 + (d4 << 2);
            dst[0] = tfr(v4.x); dst[1] = tfr(v4.y); dst[2] = tfr(v4.z); dst[3] = tfr(v4.w);
        }
        __syncthreads();
        for (int cidx = 0; cidx < nch; cidx++) {
            int cb = (c0 + cidx) << 5;
            const float* vc = ks + cidx*2304;
            unsigned afr[4], bfr[2];
#pragma unroll
            for (int k8 = 0; k8 < 4; k8++) {
                int kA = (k8 << 3) + qd;
                int i0 = cb + kA - gl;      // (row gl,   key kA)
                int i1 = i0 - 8;            // (row gl+8, key kA)
                int i2 = i0 + 4;            // (row gl,   key kA+4)
                int i3 = i1 + 4;            // (row gl+8, key kA+4)
                afr[0] = (i0 >= 0 && i0 <= 512) ? __float_as_uint(sc[gl*536     + 16 + i0]) : 0u;
                afr[1] = (i1 >= 0 && i1 <= 512) ? __float_as_uint(sc[(gl+8)*536 + 16 + i1]) : 0u;
                afr[2] = (i2 >= 0 && i2 <= 512) ? __float_as_uint(sc[gl*536     + 16 + i2]) : 0u;
                afr[3] = (i3 >= 0 && i3 <= 512) ? __float_as_uint(sc[(gl+8)*536 + 16 + i3]) : 0u;
                bfr[0] = __float_as_uint(vc[kA*72       + nd]);
                bfr[1] = __float_as_uint(vc[(kA + 4)*72 + nd]);
                mma_tf32(av, afr, bfr);
            }
        }
        __syncthreads();
    }

    // epilogue: scale by per-query (mask * 1/sum) and store
    {
        float s0 = scl[gl], s1 = scl[gl + 8];
        int d = (warp << 3) + (qd << 1);
        int iq0 = base + gl, iq1 = base + gl + 8;
        *(float2*)(attn + ((size_t)b*SS + iq0)*EE + h*DHH + d) = make_float2(av[0]*s0, av[1]*s0);
        *(float2*)(attn + ((size_t)b*SS + iq1)*EE + h*DHH + d) = make_float2(av[2]*s1, av[3]*s1);
    }
}

// ---------------- global attention (overwrites attn rows < G) ----------------
__global__ __launch_bounds__(256) void global_attn_kernel(
    const float* __restrict__ gq, const float* __restrict__ gk, const float* __restrict__ gv,
    const int* __restrict__ am, const int* __restrict__ gm,
    float* __restrict__ attn)
{
    int g = blockIdx.x, h = blockIdx.y, b = blockIdx.z;
    int tid = threadIdx.x;
    __shared__ float sc[SS];
    __shared__ float qrow[64];
    __shared__ float red[8];
    __shared__ float redv[4][64];

    const float* gkb = gk + ((size_t)(b*HH + h) * SS) * DHH;
    const float* gvb = gv + ((size_t)(b*HH + h) * SS) * DHH;
    if (tid < 64) qrow[tid] = gq[(((size_t)(b*HH + h) * SS + g) << 6) + tid];
    __syncthreads();

    float lmax = -3.4e38f;
    for (int j = tid; j < SS; j += 256) {
        int m = am[b*SS + j] * (gm[b*SS + j] + 1);
        float s;
        if (m == 0) s = NEGV;
        else {
            float a0=0.f,a1=0.f,a2=0.f,a3=0.f;
            const float4* kp = (const float4*)(gkb + (size_t)j * DHH);
            const float4* qp = (const float4*)qrow;
#pragma unroll
            for (int d4 = 0; d4 < 16; d4++) {
                float4 a = qp[d4], bb = kp[d4];
                a0 += a.x*bb.x; a1 += a.y*bb.y; a2 += a.z*bb.z; a3 += a.w*bb.w;
            }
            s = (a0 + a1) + (a2 + a3);
        }
        sc[j] = s;
        lmax = fmaxf(lmax, s);
    }
#pragma unroll
    for (int o = 16; o; o >>= 1) lmax = fmaxf(lmax, __shfl_xor_sync(0xffffffffu, lmax, o));
    if ((tid & 31) == 0) red[tid >> 5] = lmax;
    __syncthreads();
    float bmax = red[0];
#pragma unroll
    for (int w = 1; w < 8; w++) bmax = fmaxf(bmax, red[w]);

    float lsum = 0.f;
    for (int j = tid; j < SS; j += 256) {
        float e = __expf(sc[j] - bmax);
        sc[j] = e;
        lsum += e;
    }
#pragma unroll
    for (int o = 16; o; o >>= 1) lsum += __shfl_xor_sync(0xffffffffu, lsum, o);
    __syncthreads();
    if ((tid & 31) == 0) red[tid >> 5] = lsum;
    __syncthreads();
    float ssum = 0.f;
#pragma unroll
    for (int w = 0; w < 8; w++) ssum += red[w];
    float inv = 1.f / ssum;

    int grp = tid >> 6, d = tid & 63;
    float acc0 = 0.f, acc1 = 0.f;
    for (int j = grp; j < SS; j += 8) {
        acc0 += sc[j] * gvb[(size_t)j * DHH + d];
        acc1 += sc[j + 4] * gvb[(size_t)(j + 4) * DHH + d];
    }
    redv[grp][d] = acc0 + acc1;
    __syncthreads();
    if (grp == 0) {
        float o = (redv[0][d] + redv[1][d] + redv[2][d] + redv[3][d]) * inv;
        attn[((size_t)b*SS + g)*EE + h*DHH + d] = o;
    }
}

// ---------------- fused add + LayerNorm ----------------
__global__ __launch_bounds__(256) void add_ln_kernel(
    const float* __restrict__ a, const float* __restrict__ c,
    const float* __restrict__ gamma, const float* __restrict__ beta,
    float* __restrict__ out)
{
    int row = blockIdx.x;
    int tid = threadIdx.x;
    __shared__ float buf[EE];
    __shared__ float red[8];

    float local = 0.f;
#pragma unroll
    for (int i = 0; i < 3; i++) {
        int idx = tid + i*256;
        float v = a[(size_t)row*EE + idx] + c[(size_t)row*EE + idx];
        buf[idx] = v;
        local += v;
    }
#pragma unroll
    for (int o = 16; o; o >>= 1) local += __shfl_xor_sync(0xffffffffu, local, o);
    if ((tid & 31) == 0) red[tid >> 5] = local;
    __syncthreads();
    float s = 0.f;
#pragma unroll
    for (int w = 0; w < 8; w++) s += red[w];
    float mean = s * (1.f/768.f);

    float lv = 0.f;
#pragma unroll
    for (int i = 0; i < 3; i++) {
        float dd = buf[tid + i*256] - mean;
        lv += dd*dd;
    }
#pragma unroll
    for (int o = 16; o; o >>= 1) lv += __shfl_xor_sync(0xffffffffu, lv, o);
    __syncthreads();
    if ((tid & 31) == 0) red[tid >> 5] = lv;
    __syncthreads();
    float vs = 0.f;
#pragma unroll
    for (int w = 0; w < 8; w++) vs += red[w];
    float invstd = rsqrtf(vs * (1.f/768.f) + 1e-5f);

#pragma unroll
    for (int i = 0; i < 3; i++) {
        int idx = tid + i*256;
        out[(size_t)row*EE + idx] = (buf[idx] - mean) * invstd * gamma[idx] + beta[idx];
    }
}

// ---------------- SiLU(t1) * t2 -> t1 ----------------
__global__ void silu_mul_kernel(float* __restrict__ t1, const float* __restrict__ t2, int n) {
    int i = blockIdx.x * blockDim.x + threadIdx.x;
    if (i < n) {
        float a = t1[i];
        t1[i] = a / (1.f + expf(-a)) * t2[i];
    }
}

// ---------------- launch ----------------
extern "C" void kernel_launch(void* const* d_in, const int* in_sizes, int n_in,
                              void* d_out, int out_size) {
    (void)in_sizes; (void)n_in; (void)out_size;
    const float* x    = (const float*)d_in[0];
    const int*   am   = (const int*)d_in[1];
    const int*   gm   = (const int*)d_in[2];
    const float* Wq   = (const float*)d_in[3];  const float* bq  = (const float*)d_in[4];
    const float* Wk   = (const float*)d_in[5];  const float* bk  = (const float*)d_in[6];
    const float* Wv   = (const float*)d_in[7];  const float* bv  = (const float*)d_in[8];
    const float* Wqg  = (const float*)d_in[9];  const float* bqg = (const float*)d_in[10];
    const float* Wkg  = (const float*)d_in[11]; const float* bkg = (const float*)d_in[12];
    const float* Wvg  = (const float*)d_in[13]; const float* bvg = (const float*)d_in[14];
    const float* ln0g = (const float*)d_in[15]; const float* ln0b = (const float*)d_in[16];
    const float* ln1g = (const float*)d_in[17]; const float* ln1b = (const float*)d_in[18];
    const float* W1   = (const float*)d_in[19];
    const float* W3   = (const float*)d_in[20];
    const float* W2   = (const float*)d_in[21];
    float* out = (float*)d_out;

    float *qp, *kp, *vp, *gqp, *gkp, *gvp, *attnp, *h0p, *t1p, *t2p, *tbp;
    cudaGetSymbolAddress((void**)&qp,  g_q);
    cudaGetSymbolAddress((void**)&kp,  g_k);
    cudaGetSymbolAddress((void**)&vp,  g_v);
    cudaGetSymbolAddress((void**)&gqp, g_gq);
    cudaGetSymbolAddress((void**)&gkp, g_gk);
    cudaGetSymbolAddress((void**)&gvp, g_gv);
    cudaGetSymbolAddress((void**)&attnp, g_attn);
    cudaGetSymbolAddress((void**)&h0p, g_h0);
    cudaGetSymbolAddress((void**)&t1p, g_t1);
    cudaGetSymbolAddress((void**)&t2p, g_t2);
    cudaGetSymbolAddress((void**)&tbp, g_tbuf);

    // opt-in to >48KB dynamic smem for the band kernel (idempotent, non-stream op)
    cudaFuncSetAttribute(band_attn_kernel,
                         cudaFuncAttributeMaxDynamicSharedMemorySize, BAND_SMEM);

    mask_cumsum_kernel<<<BB, 256>>>(am, gm, tbp);

    GemmArgs pa = {};
    pa.A = x; pa.N = EE; pa.K = EE; pa.epi = 1;
    pa.Wm[0] = Wq;  pa.bias[0] = bq;  pa.out[0] = qp;  pa.scale[0] = 0.125f;
    pa.Wm[1] = Wk;  pa.bias[1] = bk;  pa.out[1] = kp;  pa.scale[1] = 1.f;
    pa.Wm[2] = Wv;  pa.bias[2] = bv;  pa.out[2] = vp;  pa.scale[2] = 1.f;
    pa.Wm[3] = Wqg; pa.bias[3] = bqg; pa.out[3] = gqp; pa.scale[3] = 0.125f;
    pa.Wm[4] = Wkg; pa.bias[4] = bkg; pa.out[4] = gkp; pa.scale[4] = 1.f;
    pa.Wm[5] = Wvg; pa.bias[5] = bvg; pa.out[5] = gvp; pa.scale[5] = 1.f;
    tf32gemm_kernel<<<dim3(32, 6, 6), 256>>>(pa);

    rope_kernel<<<(BB*HH*SS*32 + 255)/256, 256>>>(qp, kp, tbp);

    band_attn_kernel<<<dim3(SS/16, HH, BB), 256, BAND_SMEM>>>(qp, kp, vp, am, gm, attnp);
    global_attn_kernel<<<dim3(GG, HH, BB), 256>>>(gqp, gkp, gvp, am, gm, attnp);

    add_ln_kernel<<<BB*SS, 256>>>(x, attnp, ln0g, ln0b, h0p);

    GemmArgs f1 = {};
    f1.A = h0p; f1.N = FFD; f1.K = EE; f1.epi = 0;
    f1.Wm[0] = W1; f1.bias[0] = nullptr; f1.out[0] = t1p; f1.scale[0] = 1.f;
    f1.Wm[1] = W3; f1.bias[1] = nullptr; f1.out[1] = t2p; f1.scale[1] = 1.f;
    tf32gemm_kernel<<<dim3(32, 24, 2), 256>>>(f1);

    silu_mul_kernel<<<(NFF + 255)/256, 256>>>(t1p, t2p, NFF);

    GemmArgs f2 = {};
    f2.A = t1p; f2.N = EE; f2.K = FFD; f2.epi = 0;
    f2.Wm[0] = W2; f2.bias[0] = nullptr; f2.out[0] = attnp; f2.scale[0] = 1.f;
    tf32gemm_kernel<<<dim3(32, 6, 1), 256>>>(f2);

    add_ln_kernel<<<BB*SS, 256>>>(h0p, attnp, ln1g, ln1b, out);
}

// round 12
// speedup vs baseline: 3.1697x; 1.0774x over previous
#include <cuda_runtime.h>
#include <cuda_bf16.h>
#include <math.h>

#define BB 2
#define SS 2048
#define EE 768
#define HH 12
#define DHH 64
#define WW 256
#define GG 16
#define FFD 3072
#define NEGV (-1e9f)

#define NQKV (BB*HH*SS*DHH)
#define NXE  (BB*SS*EE)
#define NFF  (BB*SS*FFD)

// ---------------- device scratch ----------------
__device__ float g_q[NQKV];
__device__ float g_k[NQKV];
__device__ float g_v[NQKV];
__device__ float g_gq[NQKV];
__device__ float g_gk[NQKV];
__device__ float g_gv[NQKV];
__device__ float g_attn[NXE];
__device__ float g_h0[NXE];
__device__ float g_t1[NFF];
__device__ float g_t2[NFF];
__device__ float g_tbuf[BB*SS];

// ---------------- mma / cp.async helpers ----------------
__device__ __forceinline__ void mma_tf32(float (&d)[4], const unsigned* a, const unsigned* b) {
    asm volatile(
        "mma.sync.aligned.m16n8k8.row.col.f32.tf32.tf32.f32 "
        "{%0,%1,%2,%3}, {%4,%5,%6,%7}, {%8,%9}, {%0,%1,%2,%3};\n"
        : "+f"(d[0]), "+f"(d[1]), "+f"(d[2]), "+f"(d[3])
        : "r"(a[0]), "r"(a[1]), "r"(a[2]), "r"(a[3]), "r"(b[0]), "r"(b[1]));
}
__device__ __forceinline__ void cpasync16(unsigned dst, const void* src) {
    asm volatile("cp.async.cg.shared.global [%0], [%1], 16;\n" :: "r"(dst), "l"(src));
}
// zero-fill variant: src_size=0 -> 16 bytes of zeros
__device__ __forceinline__ void cpasync16z(unsigned dst, const void* src, unsigned ssz) {
    asm volatile("cp.async.cg.shared.global [%0], [%1], 16, %2;\n" :: "r"(dst), "l"(src), "r"(ssz));
}
__device__ __forceinline__ void cp_commit() {
    asm volatile("cp.async.commit_group;\n");
}
template <int N> __device__ __forceinline__ void cp_wait() {
    asm volatile("cp.async.wait_group %0;\n" :: "n"(N));
}
__device__ __forceinline__ float tfr(float x) {
    unsigned r; asm("cvt.rna.tf32.f32 %0, %1;" : "=r"(r) : "f"(x));
    return __uint_as_float(r);
}
__device__ __forceinline__ unsigned s2u(const void* p) {
    return (unsigned)__cvta_generic_to_shared(p);
}

// ---------------- cumsum of global flags -> t ----------------
__global__ void mask_cumsum_kernel(const int* __restrict__ am,
                                   const int* __restrict__ gm,
                                   float* __restrict__ tb) {
    int b = blockIdx.x;
    __shared__ int mg[SS];
    for (int i = threadIdx.x; i < SS; i += blockDim.x)
        mg[i] = am[b*SS + i] * (gm[b*SS + i] + 1);
    __syncthreads();
    if (threadIdx.x == 0) {
        int c = 0;
        for (int i = 0; i < SS; i++) {
            c += (mg[i] == 2);
            tb[b*SS + i] = (mg[i] == 0) ? 0.f : (float)c;
        }
    }
}

// ---------------- tf32 tensor-core GEMM: 4 warps, 64x64 warp tiles ----------------
struct GemmArgs {
    const float* A;
    const float* Wm[6];
    const float* bias[6];
    float* out[6];
    float scale[6];
    int N, K, epi;
};

#define APAD 20
#define BPAD 136

__global__ __launch_bounds__(128, 2) void tf32gemm_kernel(GemmArgs g) {
    const int z = blockIdx.z;
    const float* __restrict__ A = g.A;
    const float* __restrict__ W = g.Wm[z];
    const float* __restrict__ bias = g.bias[z];
    float* __restrict__ out = g.out[z];
    const int N = g.N, K = g.K;
    const int bm = blockIdx.x << 7, bn = blockIdx.y << 7;

    const int tid = threadIdx.x;
    const int lane = tid & 31, warp = tid >> 5;
    const int wm = (warp >> 1) << 6;   // 0 / 64
    const int wn = (warp & 1) << 6;    // 0 / 64
    const int gl = lane >> 2, qd = lane & 3;

    __shared__ float As[2][128][APAD];   // 20.0 KB
    __shared__ float Bs[2][16][BPAD];    // 17.4 KB

    float acc[4][8][4];
#pragma unroll
    for (int i = 0; i < 4; i++)
#pragma unroll
        for (int j = 0; j < 8; j++)
#pragma unroll
            for (int r = 0; r < 4; r++) acc[i][j][r] = 0.f;

    // staging: 4 float4 for A (128x16 = 512 chunks), 4 for B (16x128)
    const float* Agp0 = A + (size_t)(bm + (tid >> 2)) * K + ((tid & 3) << 2);
    const float* Wgp0 = W + (size_t)(tid >> 5) * N + bn + ((tid & 31) << 2);
    const size_t AgS = (size_t)32 * K;   // +32 rows per t
    const size_t WgS = (size_t)4 * N;    // +4 k-rows per t
    const unsigned sAb = s2u(&As[0][tid >> 2][(tid & 3) << 2]);
    const unsigned sBb = s2u(&Bs[0][tid >> 5][(tid & 31) << 2]);
    const unsigned ABUF = 128 * APAD * 4;   // 10240
    const unsigned BBUF = 16 * BPAD * 4;    // 8704
    const unsigned AT = 32 * APAD * 4;      // 2560 per t
    const unsigned BT = 4 * BPAD * 4;       // 2176 per t

    const int NIT = K >> 4;

#pragma unroll
    for (int t = 0; t < 4; t++) {
        cpasync16(sAb + t*AT, Agp0 + (size_t)t*AgS);
        cpasync16(sBb + t*BT, Wgp0 + (size_t)t*WgS);
    }
    cp_commit();

    for (int it = 0; it < NIT; it++) {
        const int cur = it & 1;
        const bool more = (it + 1) < NIT;
        if (more) {
            const unsigned oa = (cur ^ 1) * ABUF, ob = (cur ^ 1) * BBUF;
            int k0n = (it + 1) << 4;
#pragma unroll
            for (int t = 0; t < 4; t++) {
                cpasync16(sAb + oa + t*AT, Agp0 + k0n + (size_t)t*AgS);
                cpasync16(sBb + ob + t*BT, Wgp0 + (size_t)k0n*N + (size_t)t*WgS);
            }
            cp_commit();
            cp_wait<1>();
        } else {
            cp_wait<0>();
        }
        __syncthreads();

#pragma unroll
        for (int kt = 0; kt < 2; kt++) {
            const int k0 = kt << 3;
            unsigned afr[4][4], bfr[8][2];
#pragma unroll
            for (int mtl = 0; mtl < 4; mtl++) {
                int m = wm + (mtl << 4);
                afr[mtl][0] = __float_as_uint(As[cur][m + gl    ][k0 + qd    ]);
                afr[mtl][1] = __float_as_uint(As[cur][m + gl + 8][k0 + qd    ]);
                afr[mtl][2] = __float_as_uint(As[cur][m + gl    ][k0 + qd + 4]);
                afr[mtl][3] = __float_as_uint(As[cur][m + gl + 8][k0 + qd + 4]);
            }
#pragma unroll
            for (int ntl = 0; ntl < 8; ntl++) {
                int n = wn + (ntl << 3) + gl;
                bfr[ntl][0] = __float_as_uint(Bs[cur][k0 + qd    ][n]);
                bfr[ntl][1] = __float_as_uint(Bs[cur][k0 + qd + 4][n]);
            }
#pragma unroll
            for (int mtl = 0; mtl < 4; mtl++)
#pragma unroll
                for (int ntl = 0; ntl < 8; ntl++)
                    mma_tf32(acc[mtl][ntl], afr[mtl], bfr[ntl]);
        }
        __syncthreads();
    }

    const float sc = g.scale[z];
#pragma unroll
    for (int mtl = 0; mtl < 4; mtl++) {
        int row0 = bm + wm + (mtl << 4) + gl;
#pragma unroll
        for (int ntl = 0; ntl < 8; ntl++) {
            int col = bn + wn + (ntl << 3) + (qd << 1);
            float v0 = acc[mtl][ntl][0], v1 = acc[mtl][ntl][1];
            float v2 = acc[mtl][ntl][2], v3 = acc[mtl][ntl][3];
            if (bias) {
                float b0 = bias[col], b1 = bias[col + 1];
                v0 += b0; v1 += b1; v2 += b0; v3 += b1;
            }
            v0 *= sc; v1 *= sc; v2 *= sc; v3 *= sc;
            if (g.epi == 0) {
                *(float2*)(out + (size_t)row0 * N + col)       = make_float2(v0, v1);
                *(float2*)(out + (size_t)(row0 + 8) * N + col) = make_float2(v2, v3);
            } else {
                int h = col >> 6, d = col & 63;
                int b0i = row0 >> 11, s0 = row0 & (SS - 1);
                int row1 = row0 + 8;
                int b1i = row1 >> 11, s1 = row1 & (SS - 1);
                *(float2*)(out + (((size_t)(b0i*HH + h) * SS + s0) << 6) + d) = make_float2(v0, v1);
                *(float2*)(out + (((size_t)(b1i*HH + h) * SS + s1) << 6) + d) = make_float2(v2, v3);
            }
        }
    }
}

// ---------------- RoPE on q and k (in-place) ----------------
__global__ void rope_kernel(float* __restrict__ q, float* __restrict__ k,
                            const float* __restrict__ tb) {
    int idx = blockIdx.x * blockDim.x + threadIdx.x;
    const int total = BB*HH*SS*32;
    if (idx >= total) return;
    int d   = idx & 31;
    int rem = idx >> 5;
    int s   = rem & (SS-1);
    int rem2 = rem >> 11;
    int h   = rem2 % HH;
    int b   = rem2 / HH;
    float tt = tb[b*SS + s];
    float inv_freq = expf(-(float)d * 0.28782313662425574f);
    float sn, cs;
    sincosf(tt * inv_freq, &sn, &cs);
    size_t off = (((size_t)(b*HH + h) * SS + s) << 6) + d;
    float x1 = q[off], x2 = q[off + 32];
    q[off]      = x1*cs - x2*sn;
    q[off + 32] = x2*cs + x1*sn;
    x1 = k[off]; x2 = k[off + 32];
    k[off]      = x1*cs - x2*sn;
    k[off + 32] = x2*cs + x1*sn;
}

// ---------------- banded + global-key attention (tensor mma, guard-free) ----------------
// sc row layout (width 584): [0..15] global scores; band score l at [40+l];
// scatter writes span [25,583]; AV reads span [17,583]; dead zones
// [16,39] & [553,583] zeroed before AV so OOB prob reads are exact 0.
#define SCW 584
#define BOFF 40
#define BAND_SMEM ((1088 + 16*SCW + 9216 + 16) * 4 + 128 * 4)

__global__ __launch_bounds__(256) void band_attn_kernel(
    const float* __restrict__ q, const float* __restrict__ k, const float* __restrict__ v,
    const int* __restrict__ am, const int* __restrict__ gm,
    float* __restrict__ attn)
{
    extern __shared__ float sm[];
    float* qs  = sm;                    // [16][68]
    float* sc  = sm + 1088;             // [16][SCW]
    float* ks  = sc + 16*SCW;           // [4][32][72]
    float* scl = ks + 9216;             // [16]
    int*   rmv = (int*)(scl + 16);      // [128]

    const int b = blockIdx.z, h = blockIdx.y, base = blockIdx.x << 4;
    const int tid = threadIdx.x;
    const int lane = tid & 31, warp = tid >> 5;
    const int gl = lane >> 2, qd = lane & 3;

    const float* qb = q + ((size_t)(b*HH + h) * SS) * DHH;
    const float* kb = k + ((size_t)(b*HH + h) * SS) * DHH;
    const float* vb = v + ((size_t)(b*HH + h) * SS) * DHH;

    // stage q tile (16x64) and the 16 global keys via cp.async (raw fp32 = trunc tf32)
    {
        int row = tid >> 4, d4 = tid & 15;
        cpasync16(s2u(qs + row*68 + (d4 << 2)), qb + (((size_t)(base + row)) << 6) + (d4 << 2));
        cpasync16(s2u(ks + row*72 + (d4 << 2)), kb + (((size_t)row) << 6) + (d4 << 2));
        cp_commit(); cp_wait<0>();
    }
    __syncthreads();

    // per-warp Q fragments
    unsigned aq[8][4];
#pragma unroll
    for (int k8 = 0; k8 < 8; k8++) {
        int k0 = k8 << 3;
        aq[k8][0] = __float_as_uint(qs[gl*68     + k0 + qd    ]);
        aq[k8][1] = __float_as_uint(qs[(gl+8)*68 + k0 + qd    ]);
        aq[k8][2] = __float_as_uint(qs[gl*68     + k0 + qd + 4]);
        aq[k8][3] = __float_as_uint(qs[(gl+8)*68 + k0 + qd + 4]);
    }

    // global-key scores (unmasked per reference): warps 0,1
    if (warp < 2) {
        float acc[4] = {0.f, 0.f, 0.f, 0.f};
        unsigned bfr[2];
#pragma unroll
        for (int k8 = 0; k8 < 8; k8++) {
            int k0 = k8 << 3;
            bfr[0] = __float_as_uint(ks[(warp*8 + gl)*72 + k0 + qd    ]);
            bfr[1] = __float_as_uint(ks[(warp*8 + gl)*72 + k0 + qd + 4]);
            mma_tf32(acc, aq[k8], bfr);
        }
        int key = warp*8 + (qd << 1);
        sc[gl*SCW     + key    ] = acc[0];
        sc[gl*SCW     + key + 1] = acc[1];
        sc[(gl+8)*SCW + key    ] = acc[2];
        sc[(gl+8)*SCW + key + 1] = acc[3];
    }
    __syncthreads();

    const int jmin = base - WW;

    // band scores: 5 rounds of up to 4 chunks (32 keys each)
    for (int round = 0; round < 5; round++) {
        const int c0 = round << 2;
        const int nch = (round < 4) ? 4 : 1;
        for (int i = tid; i < (nch << 9); i += 256) {
            int cidx = i >> 9, rem = i & 511;
            int kk = rem >> 4, d4 = rem & 15;
            int j = jmin + ((c0 + cidx) << 5) + kk;
            bool valid = (j >= 0 && j < SS);
            int jc = valid ? j : 0;
            cpasync16z(s2u(ks + cidx*2304 + kk*72 + (d4 << 2)),
                       kb + (((size_t)jc) << 6) + (d4 << 2), valid ? 16u : 0u);
        }
        for (int i = tid; i < (nch << 5); i += 256) {
            int j = jmin + (c0 << 5) + i;
            int rm = 1;
            if (j >= 0 && j < SS) { int m = am[b*SS + j] * (gm[b*SS + j] + 1); rm = (m != 1); }
            rmv[i] = rm;
        }
        cp_commit(); cp_wait<0>();
        __syncthreads();

        int cidx = warp >> 1;
        if (cidx < nch) {
            int cb = (c0 + cidx) << 5;
            const float* kc = ks + cidx*2304;
#pragma unroll
            for (int t = 0; t < 2; t++) {
                int ntile = ((warp & 1) << 1) + t;
                float acc[4] = {0.f, 0.f, 0.f, 0.f};
                unsigned bfr[2];
#pragma unroll
                for (int k8 = 0; k8 < 8; k8++) {
                    int k0 = k8 << 3;
                    bfr[0] = __float_as_uint(kc[(ntile*8 + gl)*72 + k0 + qd    ]);
                    bfr[1] = __float_as_uint(kc[(ntile*8 + gl)*72 + k0 + qd + 4]);
                    mma_tf32(acc, aq[k8], bfr);
                }
                int kkA = (ntile << 3) + (qd << 1);
                int r0 = rmv[(cidx << 5) + kkA];
                int r1 = rmv[(cidx << 5) + kkA + 1];
                int l0 = cb + kkA - gl;
                // unconditional scatter: all indices land inside the 584-wide row
                sc[gl*SCW     + BOFF + l0    ] = r0 ? NEGV : acc[0];
                sc[gl*SCW     + BOFF + l0 + 1] = r1 ? NEGV : acc[1];
                sc[(gl+8)*SCW + BOFF + l0 - 8] = r0 ? NEGV : acc[2];
                sc[(gl+8)*SCW + BOFF + l0 - 7] = r1 ? NEGV : acc[3];
            }
        }
        __syncthreads();
    }

    // softmax over 16 global + 513 band entries per query
    {
        const int p = tid >> 4, r = tid & 15;
        float mx = sc[p*SCW + r];
        for (int l = r; l <= 512; l += 16) mx = fmaxf(mx, sc[p*SCW + BOFF + l]);
#pragma unroll
        for (int o = 8; o; o >>= 1) mx = fmaxf(mx, __shfl_xor_sync(0xffffffffu, mx, o, 16));
        float gv0 = __expf(sc[p*SCW + r] - mx);
        sc[p*SCW + r] = tfr(gv0);
        float sum = gv0;
        for (int l = r; l <= 512; l += 16) {
            float e = __expf(sc[p*SCW + BOFF + l] - mx);
            sc[p*SCW + BOFF + l] = tfr(e);
            sum += e;
        }
#pragma unroll
        for (int o = 8; o; o >>= 1) sum += __shfl_xor_sync(0xffffffffu, sum, o, 16);
        if (r == 0) {
            int iq = base + p;
            int mm = am[b*SS + iq] * (gm[b*SS + iq] + 1);
            scl[p] = (mm == 0) ? 0.f : (1.f / sum);
        }
    }
    // zero dead zones [16,39] and [553,583] of each row (55 entries x 16 rows)
    for (int i = tid; i < 880; i += 256) {
        int pp = i / 55, o = i % 55;
        int idx = (o < 24) ? (16 + o) : (553 + (o - 24));
        sc[pp*SCW + idx] = 0.f;
    }
    __syncthreads();

    // AV: warp owns dims [warp*8, warp*8+8)
    float av[4] = {0.f, 0.f, 0.f, 0.f};
    const int nd = (warp << 3) + gl;

    {   // global V staged
        int row = tid >> 4, d4 = tid & 15;
        cpasync16(s2u(ks + row*72 + (d4 << 2)), vb + (((size_t)row) << 6) + (d4 << 2));
        cp_commit(); cp_wait<0>();
    }
    __syncthreads();
    {
        unsigned afr[4], bfr[2];
#pragma unroll
        for (int k8 = 0; k8 < 2; k8++) {
            int k0 = k8 << 3;
            afr[0] = __float_as_uint(sc[gl*SCW     + k0 + qd    ]);
            afr[1] = __float_as_uint(sc[(gl+8)*SCW + k0 + qd    ]);
            afr[2] = __float_as_uint(sc[gl*SCW     + k0 + qd + 4]);
            afr[3] = __float_as_uint(sc[(gl+8)*SCW + k0 + qd + 4]);
            bfr[0] = __float_as_uint(ks[(k0 + qd    )*72 + nd]);
            bfr[1] = __float_as_uint(ks[(k0 + qd + 4)*72 + nd]);
            mma_tf32(av, afr, bfr);
        }
    }
    __syncthreads();

    for (int round = 0; round < 5; round++) {
        const int c0 = round << 2;
        const int nch = (round < 4) ? 4 : 1;
        for (int i = tid; i < (nch << 9); i += 256) {
            int cidx = i >> 9, rem = i & 511;
            int kk = rem >> 4, d4 = rem & 15;
            int j = jmin + ((c0 + cidx) << 5) + kk;
            bool valid = (j >= 0 && j < SS);
            int jc = valid ? j : 0;
            cpasync16z(s2u(ks + cidx*2304 + kk*72 + (d4 << 2)),
                       vb + (((size_t)jc) << 6) + (d4 << 2), valid ? 16u : 0u);
        }
        cp_commit(); cp_wait<0>();
        __syncthreads();
        for (int cidx = 0; cidx < nch; cidx++) {
            int cb = (c0 + cidx) << 5;
            const float* vc = ks + cidx*2304;
            unsigned afr[4], bfr[2];
#pragma unroll
            for (int k8 = 0; k8 < 4; k8++) {
                int kA = (k8 << 3) + qd;
                int i0 = cb + kA - gl;   // guard-free: dead zones are zero
                afr[0] = __float_as_uint(sc[gl*SCW     + BOFF + i0    ]);
                afr[1] = __float_as_uint(sc[(gl+8)*SCW + BOFF + i0 - 8]);
                afr[2] = __float_as_uint(sc[gl*SCW     + BOFF + i0 + 4]);
                afr[3] = __float_as_uint(sc[(gl+8)*SCW + BOFF + i0 - 4]);
                bfr[0] = __float_as_uint(vc[kA*72       + nd]);
                bfr[1] = __float_as_uint(vc[(kA + 4)*72 + nd]);
                mma_tf32(av, afr, bfr);
            }
        }
        __syncthreads();
    }

    {
        float s0 = scl[gl], s1 = scl[gl + 8];
        int d = (warp << 3) + (qd << 1);
        int iq0 = base + gl, iq1 = base + gl + 8;
        *(float2*)(attn + ((size_t)b*SS + iq0)*EE + h*DHH + d) = make_float2(av[0]*s0, av[1]*s0);
        *(float2*)(attn + ((size_t)b*SS + iq1)*EE + h*DHH + d) = make_float2(av[2]*s1, av[3]*s1);
    }
}

// ---------------- global attention (overwrites attn rows < G) ----------------
__global__ __launch_bounds__(256) void global_attn_kernel(
    const float* __restrict__ gq, const float* __restrict__ gk, const float* __restrict__ gv,
    const int* __restrict__ am, const int* __restrict__ gm,
    float* __restrict__ attn)
{
    int g = blockIdx.x, h = blockIdx.y, b = blockIdx.z;
    int tid = threadIdx.x;
    __shared__ float sc[SS];
    __shared__ float qrow[64];
    __shared__ float red[8];
    __shared__ float redv[4][64];

    const float* gkb = gk + ((size_t)(b*HH + h) * SS) * DHH;
    const float* gvb = gv + ((size_t)(b*HH + h) * SS) * DHH;
    if (tid < 64) qrow[tid] = gq[(((size_t)(b*HH + h) * SS + g) << 6) + tid];
    __syncthreads();

    float lmax = -3.4e38f;
    for (int j = tid; j < SS; j += 256) {
        int m = am[b*SS + j] * (gm[b*SS + j] + 1);
        float s;
        if (m == 0) s = NEGV;
        else {
            float a0=0.f,a1=0.f,a2=0.f,a3=0.f;
            const float4* kp = (const float4*)(gkb + (size_t)j * DHH);
            const float4* qp = (const float4*)qrow;
#pragma unroll
            for (int d4 = 0; d4 < 16; d4++) {
                float4 a = qp[d4], bb = kp[d4];
                a0 += a.x*bb.x; a1 += a.y*bb.y; a2 += a.z*bb.z; a3 += a.w*bb.w;
            }
            s = (a0 + a1) + (a2 + a3);
        }
        sc[j] = s;
        lmax = fmaxf(lmax, s);
    }
#pragma unroll
    for (int o = 16; o; o >>= 1) lmax = fmaxf(lmax, __shfl_xor_sync(0xffffffffu, lmax, o));
    if ((tid & 31) == 0) red[tid >> 5] = lmax;
    __syncthreads();
    float bmax = red[0];
#pragma unroll
    for (int w = 1; w < 8; w++) bmax = fmaxf(bmax, red[w]);

    float lsum = 0.f;
    for (int j = tid; j < SS; j += 256) {
        float e = __expf(sc[j] - bmax);
        sc[j] = e;
        lsum += e;
    }
#pragma unroll
    for (int o = 16; o; o >>= 1) lsum += __shfl_xor_sync(0xffffffffu, lsum, o);
    __syncthreads();
    if ((tid & 31) == 0) red[tid >> 5] = lsum;
    __syncthreads();
    float ssum = 0.f;
#pragma unroll
    for (int w = 0; w < 8; w++) ssum += red[w];
    float inv = 1.f / ssum;

    int grp = tid >> 6, d = tid & 63;
    float acc0 = 0.f, acc1 = 0.f;
    for (int j = grp; j < SS; j += 8) {
        acc0 += sc[j] * gvb[(size_t)j * DHH + d];
        acc1 += sc[j + 4] * gvb[(size_t)(j + 4) * DHH + d];
    }
    redv[grp][d] = acc0 + acc1;
    __syncthreads();
    if (grp == 0) {
        float o = (redv[0][d] + redv[1][d] + redv[2][d] + redv[3][d]) * inv;
        attn[((size_t)b*SS + g)*EE + h*DHH + d] = o;
    }
}

// ---------------- fused add + LayerNorm ----------------
__global__ __launch_bounds__(256) void add_ln_kernel(
    const float* __restrict__ a, const float* __restrict__ c,
    const float* __restrict__ gamma, const float* __restrict__ beta,
    float* __restrict__ out)
{
    int row = blockIdx.x;
    int tid = threadIdx.x;
    __shared__ float buf[EE];
    __shared__ float red[8];

    float local = 0.f;
#pragma unroll
    for (int i = 0; i < 3; i++) {
        int idx = tid + i*256;
        float v = a[(size_t)row*EE + idx] + c[(size_t)row*EE + idx];
        buf[idx] = v;
        local += v;
    }
#pragma unroll
    for (int o = 16; o; o >>= 1) local += __shfl_xor_sync(0xffffffffu, local, o);
    if ((tid & 31) == 0) red[tid >> 5] = local;
    __syncthreads();
    float s = 0.f;
#pragma unroll
    for (int w = 0; w < 8; w++) s += red[w];
    float mean = s * (1.f/768.f);

    float lv = 0.f;
#pragma unroll
    for (int i = 0; i < 3; i++) {
        float dd = buf[tid + i*256] - mean;
        lv += dd*dd;
    }
#pragma unroll
    for (int o = 16; o; o >>= 1) lv += __shfl_xor_sync(0xffffffffu, lv, o);
    __syncthreads();
    if ((tid & 31) == 0) red[tid >> 5] = lv;
    __syncthreads();
    float vs = 0.f;
#pragma unroll
    for (int w = 0; w < 8; w++) vs += red[w];
    float invstd = rsqrtf(vs * (1.f/768.f) + 1e-5f);

#pragma unroll
    for (int i = 0; i < 3; i++) {
        int idx = tid + i*256;
        out[(size_t)row*EE + idx] = (buf[idx] - mean) * invstd * gamma[idx] + beta[idx];
    }
}

// ---------------- SiLU(t1) * t2 -> t1 ----------------
__global__ void silu_mul_kernel(float* __restrict__ t1, const float* __restrict__ t2, int n) {
    int i = blockIdx.x * blockDim.x + threadIdx.x;
    if (i < n) {
        float a = t1[i];
        t1[i] = a / (1.f + expf(-a)) * t2[i];
    }
}

// ---------------- launch ----------------
extern "C" void kernel_launch(void* const* d_in, const int* in_sizes, int n_in,
                              void* d_out, int out_size) {
    (void)in_sizes; (void)n_in; (void)out_size;
    const float* x    = (const float*)d_in[0];
    const int*   am   = (const int*)d_in[1];
    const int*   gm   = (const int*)d_in[2];
    const float* Wq   = (const float*)d_in[3];  const float* bq  = (const float*)d_in[4];
    const float* Wk   = (const float*)d_in[5];  const float* bk  = (const float*)d_in[6];
    const float* Wv   = (const float*)d_in[7];  const float* bv  = (const float*)d_in[8];
    const float* Wqg  = (const float*)d_in[9];  const float* bqg = (const float*)d_in[10];
    const float* Wkg  = (const float*)d_in[11]; const float* bkg = (const float*)d_in[12];
    const float* Wvg  = (const float*)d_in[13]; const float* bvg = (const float*)d_in[14];
    const float* ln0g = (const float*)d_in[15]; const float* ln0b = (const float*)d_in[16];
    const float* ln1g = (const float*)d_in[17]; const float* ln1b = (const float*)d_in[18];
    const float* W1   = (const float*)d_in[19];
    const float* W3   = (const float*)d_in[20];
    const float* W2   = (const float*)d_in[21];
    float* out = (float*)d_out;

    float *qp, *kp, *vp, *gqp, *gkp, *gvp, *attnp, *h0p, *t1p, *t2p, *tbp;
    cudaGetSymbolAddress((void**)&qp,  g_q);
    cudaGetSymbolAddress((void**)&kp,  g_k);
    cudaGetSymbolAddress((void**)&vp,  g_v);
    cudaGetSymbolAddress((void**)&gqp, g_gq);
    cudaGetSymbolAddress((void**)&gkp, g_gk);
    cudaGetSymbolAddress((void**)&gvp, g_gv);
    cudaGetSymbolAddress((void**)&attnp, g_attn);
    cudaGetSymbolAddress((void**)&h0p, g_h0);
    cudaGetSymbolAddress((void**)&t1p, g_t1);
    cudaGetSymbolAddress((void**)&t2p, g_t2);
    cudaGetSymbolAddress((void**)&tbp, g_tbuf);

    cudaFuncSetAttribute(band_attn_kernel,
                         cudaFuncAttributeMaxDynamicSharedMemorySize, BAND_SMEM);

    mask_cumsum_kernel<<<BB, 256>>>(am, gm, tbp);

    GemmArgs pa = {};
    pa.A = x; pa.N = EE; pa.K = EE; pa.epi = 1;
    pa.Wm[0] = Wq;  pa.bias[0] = bq;  pa.out[0] = qp;  pa.scale[0] = 0.125f;
    pa.Wm[1] = Wk;  pa.bias[1] = bk;  pa.out[1] = kp;  pa.scale[1] = 1.f;
    pa.Wm[2] = Wv;  pa.bias[2] = bv;  pa.out[2] = vp;  pa.scale[2] = 1.f;
    pa.Wm[3] = Wqg; pa.bias[3] = bqg; pa.out[3] = gqp; pa.scale[3] = 0.125f;
    pa.Wm[4] = Wkg; pa.bias[4] = bkg; pa.out[4] = gkp; pa.scale[4] = 1.f;
    pa.Wm[5] = Wvg; pa.bias[5] = bvg; pa.out[5] = gvp; pa.scale[5] = 1.f;
    tf32gemm_kernel<<<dim3(32, 6, 6), 128>>>(pa);

    rope_kernel<<<(BB*HH*SS*32 + 255)/256, 256>>>(qp, kp, tbp);

    band_attn_kernel<<<dim3(SS/16, HH, BB), 256, BAND_SMEM>>>(qp, kp, vp, am, gm, attnp);
    global_attn_kernel<<<dim3(GG, HH, BB), 256>>>(gqp, gkp, gvp, am, gm, attnp);

    add_ln_kernel<<<BB*SS, 256>>>(x, attnp, ln0g, ln0b, h0p);

    GemmArgs f1 = {};
    f1.A = h0p; f1.N = FFD; f1.K = EE; f1.epi = 0;
    f1.Wm[0] = W1; f1.bias[0] = nullptr; f1.out[0] = t1p; f1.scale[0] = 1.f;
    f1.Wm[1] = W3; f1.bias[1] = nullptr; f1.out[1] = t2p; f1.scale[1] = 1.f;
    tf32gemm_kernel<<<dim3(32, 24, 2), 128>>>(f1);

    silu_mul_kernel<<<(NFF + 255)/256, 256>>>(t1p, t2p, NFF);

    GemmArgs f2 = {};
    f2.A = t1p; f2.N = EE; f2.K = FFD; f2.epi = 0;
    f2.Wm[0] = W2; f2.bias[0] = nullptr; f2.out[0] = attnp; f2.scale[0] = 1.f;
    tf32gemm_kernel<<<dim3(32, 6, 1), 128>>>(f2);

    add_ln_kernel<<<BB*SS, 256>>>(h0p, attnp, ln1g, ln1b, out);
}

// round 13
// speedup vs baseline: 3.2365x; 1.0211x over previous
#include <cuda_runtime.h>
#include <cuda_bf16.h>
#include <math.h>

#define BB 2
#define SS 2048
#define EE 768
#define HH 12
#define DHH 64
#define WW 256
#define GG 16
#define FFD 3072
#define NEGV (-1e9f)

#define NQKV (BB*HH*SS*DHH)
#define NXE  (BB*SS*EE)
#define NFF  (BB*SS*FFD)

// ---------------- device scratch ----------------
__device__ float g_q[NQKV];
__device__ float g_k[NQKV];
__device__ float g_v[NQKV];
__device__ float g_gq[NQKV];
__device__ float g_gk[NQKV];
__device__ float g_gv[NQKV];
__device__ float g_attn[NXE];
__device__ float g_h0[NXE];
__device__ float g_t1[NFF];
__device__ float g_t2[NFF];
__device__ float g_tbuf[BB*SS];

// ---------------- mma / cp.async helpers ----------------
__device__ __forceinline__ void mma_tf32(float (&d)[4], const unsigned* a, const unsigned* b) {
    asm volatile(
        "mma.sync.aligned.m16n8k8.row.col.f32.tf32.tf32.f32 "
        "{%0,%1,%2,%3}, {%4,%5,%6,%7}, {%8,%9}, {%0,%1,%2,%3};\n"
        : "+f"(d[0]), "+f"(d[1]), "+f"(d[2]), "+f"(d[3])
        : "r"(a[0]), "r"(a[1]), "r"(a[2]), "r"(a[3]), "r"(b[0]), "r"(b[1]));
}
__device__ __forceinline__ void cpasync16(unsigned dst, const void* src) {
    asm volatile("cp.async.cg.shared.global [%0], [%1], 16;\n" :: "r"(dst), "l"(src));
}
__device__ __forceinline__ void cpasync16z(unsigned dst, const void* src, unsigned ssz) {
    asm volatile("cp.async.cg.shared.global [%0], [%1], 16, %2;\n" :: "r"(dst), "l"(src), "r"(ssz));
}
__device__ __forceinline__ void cp_commit() {
    asm volatile("cp.async.commit_group;\n");
}
template <int N> __device__ __forceinline__ void cp_wait() {
    asm volatile("cp.async.wait_group %0;\n" :: "n"(N));
}
__device__ __forceinline__ float tfr(float x) {
    unsigned r; asm("cvt.rna.tf32.f32 %0, %1;" : "=r"(r) : "f"(x));
    return __uint_as_float(r);
}
__device__ __forceinline__ unsigned s2u(const void* p) {
    return (unsigned)__cvta_generic_to_shared(p);
}

// ---------------- cumsum of global flags -> t ----------------
__global__ void mask_cumsum_kernel(const int* __restrict__ am,
                                   const int* __restrict__ gm,
                                   float* __restrict__ tb) {
    int b = blockIdx.x;
    __shared__ int mg[SS];
    for (int i = threadIdx.x; i < SS; i += blockDim.x)
        mg[i] = am[b*SS + i] * (gm[b*SS + i] + 1);
    __syncthreads();
    if (threadIdx.x == 0) {
        int c = 0;
        for (int i = 0; i < SS; i++) {
            c += (mg[i] == 2);
            tb[b*SS + i] = (mg[i] == 0) ? 0.f : (float)c;
        }
    }
}

// ---------------- tf32 GEMM: 3-stage cp.async pipeline, 4 warps 64x64 ----------------
struct GemmArgs {
    const float* A;
    const float* Wm[6];
    const float* bias[6];
    float* out[6];
    float scale[6];
    int N, K, epi;
};

#define APAD 20
#define BPAD 136
#define GEMM_SMEM ((3*128*APAD + 3*16*BPAD) * 4)   /* 56832 bytes */

__global__ __launch_bounds__(128, 2) void tf32gemm_kernel(GemmArgs g) {
    extern __shared__ float gsm[];
    float* Ab = gsm;                     // 3 stages [128][APAD]
    float* Bb = gsm + 3*128*APAD;        // 3 stages [16][BPAD]

    const int z = blockIdx.z;
    const float* __restrict__ A = g.A;
    const float* __restrict__ W = g.Wm[z];
    const float* __restrict__ bias = g.bias[z];
    float* __restrict__ out = g.out[z];
    const int N = g.N, K = g.K;
    const int bm = blockIdx.x << 7, bn = blockIdx.y << 7;

    const int tid = threadIdx.x;
    const int lane = tid & 31, warp = tid >> 5;
    const int wm = (warp >> 1) << 6;
    const int wn = (warp & 1) << 6;
    const int gl = lane >> 2, qd = lane & 3;

    float acc[4][8][4];
#pragma unroll
    for (int i = 0; i < 4; i++)
#pragma unroll
        for (int j = 0; j < 8; j++)
#pragma unroll
            for (int r = 0; r < 4; r++) acc[i][j][r] = 0.f;

    const float* Agp0 = A + (size_t)(bm + (tid >> 2)) * K + ((tid & 3) << 2);
    const float* Wgp0 = W + (size_t)(tid >> 5) * N + bn + ((tid & 31) << 2);
    const size_t AgS = (size_t)32 * K;
    const size_t WgS = (size_t)4 * N;
    const unsigned sAb = s2u(Ab + (tid >> 2)*APAD + ((tid & 3) << 2));
    const unsigned sBb = s2u(Bb + (tid >> 5)*BPAD + ((tid & 31) << 2));
    const unsigned ABUF = 128 * APAD * 4;
    const unsigned BBUF = 16 * BPAD * 4;
    const unsigned AT = 32 * APAD * 4;
    const unsigned BT = 4 * BPAD * 4;

    const int NIT = K >> 4;

#define G_STAGE(s, k0) do {                                                   \
        _Pragma("unroll")                                                     \
        for (int t = 0; t < 4; t++) {                                         \
            cpasync16(sAb + (s)*ABUF + t*AT, Agp0 + (k0) + (size_t)t*AgS);    \
            cpasync16(sBb + (s)*BBUF + t*BT, Wgp0 + (size_t)(k0)*N + (size_t)t*WgS); \
        }                                                                     \
        cp_commit();                                                          \
    } while (0)

    G_STAGE(0, 0);
    if (NIT > 1) G_STAGE(1, 16);
    int cur = 0;

    for (int it = 0; it < NIT; it++) {
        if (it + 2 < NIT) {
            int nx2 = cur + 2; if (nx2 >= 3) nx2 -= 3;
            G_STAGE(nx2, (it + 2) << 4);
            cp_wait<2>();
        } else if (it + 1 < NIT) {
            cp_wait<1>();
        } else {
            cp_wait<0>();
        }
        __syncthreads();

        const float* Ac = Ab + cur*128*APAD;
        const float* Bc = Bb + cur*16*BPAD;
#pragma unroll
        for (int kt = 0; kt < 2; kt++) {
            const int k0 = kt << 3;
            unsigned afr[4][4], bfr[8][2];
#pragma unroll
            for (int mtl = 0; mtl < 4; mtl++) {
                int m = wm + (mtl << 4);
                afr[mtl][0] = __float_as_uint(Ac[(m + gl    )*APAD + k0 + qd    ]);
                afr[mtl][1] = __float_as_uint(Ac[(m + gl + 8)*APAD + k0 + qd    ]);
                afr[mtl][2] = __float_as_uint(Ac[(m + gl    )*APAD + k0 + qd + 4]);
                afr[mtl][3] = __float_as_uint(Ac[(m + gl + 8)*APAD + k0 + qd + 4]);
            }
#pragma unroll
            for (int ntl = 0; ntl < 8; ntl++) {
                int n = wn + (ntl << 3) + gl;
                bfr[ntl][0] = __float_as_uint(Bc[(k0 + qd    )*BPAD + n]);
                bfr[ntl][1] = __float_as_uint(Bc[(k0 + qd + 4)*BPAD + n]);
            }
#pragma unroll
            for (int mtl = 0; mtl < 4; mtl++)
#pragma unroll
                for (int ntl = 0; ntl < 8; ntl++)
                    mma_tf32(acc[mtl][ntl], afr[mtl], bfr[ntl]);
        }
        __syncthreads();
        cur = (cur == 2) ? 0 : cur + 1;
    }
#undef G_STAGE

    const float sc = g.scale[z];
#pragma unroll
    for (int mtl = 0; mtl < 4; mtl++) {
        int row0 = bm + wm + (mtl << 4) + gl;
#pragma unroll
        for (int ntl = 0; ntl < 8; ntl++) {
            int col = bn + wn + (ntl << 3) + (qd << 1);
            float v0 = acc[mtl][ntl][0], v1 = acc[mtl][ntl][1];
            float v2 = acc[mtl][ntl][2], v3 = acc[mtl][ntl][3];
            if (bias) {
                float b0 = bias[col], b1 = bias[col + 1];
                v0 += b0; v1 += b1; v2 += b0; v3 += b1;
            }
            v0 *= sc; v1 *= sc; v2 *= sc; v3 *= sc;
            if (g.epi == 0) {
                *(float2*)(out + (size_t)row0 * N + col)       = make_float2(v0, v1);
                *(float2*)(out + (size_t)(row0 + 8) * N + col) = make_float2(v2, v3);
            } else {
                int h = col >> 6, d = col & 63;
                int b0i = row0 >> 11, s0 = row0 & (SS - 1);
                int row1 = row0 + 8;
                int b1i = row1 >> 11, s1 = row1 & (SS - 1);
                *(float2*)(out + (((size_t)(b0i*HH + h) * SS + s0) << 6) + d) = make_float2(v0, v1);
                *(float2*)(out + (((size_t)(b1i*HH + h) * SS + s1) << 6) + d) = make_float2(v2, v3);
            }
        }
    }
}

// ---------------- RoPE on q and k (in-place) ----------------
__global__ void rope_kernel(float* __restrict__ q, float* __restrict__ k,
                            const float* __restrict__ tb) {
    int idx = blockIdx.x * blockDim.x + threadIdx.x;
    const int total = BB*HH*SS*32;
    if (idx >= total) return;
    int d   = idx & 31;
    int rem = idx >> 5;
    int s   = rem & (SS-1);
    int rem2 = rem >> 11;
    int h   = rem2 % HH;
    int b   = rem2 / HH;
    float tt = tb[b*SS + s];
    float inv_freq = expf(-(float)d * 0.28782313662425574f);
    float sn, cs;
    sincosf(tt * inv_freq, &sn, &cs);
    size_t off = (((size_t)(b*HH + h) * SS + s) << 6) + d;
    float x1 = q[off], x2 = q[off + 32];
    q[off]      = x1*cs - x2*sn;
    q[off + 32] = x2*cs + x1*sn;
    x1 = k[off]; x2 = k[off + 32];
    k[off]      = x1*cs - x2*sn;
    k[off + 32] = x2*cs + x1*sn;
}

// ---------------- banded + global-key attention (pipelined tensor mma) ----------------
// sc row width 584: [0..15] global; band l at [40+l]; dead zones [16,39],[553,583].
// K/V staged in nine 2-chunk rounds through a 2-deep ring (overlapped with mma).
#define SCW 584
#define BOFF 40
#define BAND_SMEM ((1088 + 16*SCW + 9216 + 1152 + 16) * 4 + 64 * 4)

__global__ __launch_bounds__(256) void band_attn_kernel(
    const float* __restrict__ q, const float* __restrict__ k, const float* __restrict__ v,
    const int* __restrict__ am, const int* __restrict__ gm,
    float* __restrict__ attn)
{
    extern __shared__ float sm[];
    float* qs  = sm;                    // [16][68]
    float* sc  = sm + 1088;             // [16][SCW]
    float* ks  = sc + 16*SCW;           // ring [2][2][32][72]
    float* gvs = ks + 9216;             // [16][72] global K, later global V
    float* scl = gvs + 1152;            // [16]
    int*   rmv = (int*)(scl + 16);      // [64]

    const int b = blockIdx.z, h = blockIdx.y, base = blockIdx.x << 4;
    const int tid = threadIdx.x;
    const int lane = tid & 31, warp = tid >> 5;
    const int gl = lane >> 2, qd = lane & 3;

    const float* qb = q + ((size_t)(b*HH + h) * SS) * DHH;
    const float* kb = k + ((size_t)(b*HH + h) * SS) * DHH;
    const float* vb = v + ((size_t)(b*HH + h) * SS) * DHH;

    const int jmin = base - WW;

    // stage one 2-chunk round (64 keys) of src into ring buffer (r&1)
    auto stage_round = [&](const float* src, int r) {
        int nch = (r < 8) ? 2 : 1;
        float* dst = ks + (r & 1) * 4608;
        for (int i = tid; i < (nch << 9); i += 256) {
            int cidx = i >> 9, rem = i & 511;
            int kk = rem >> 4, d4 = rem & 15;
            int j = jmin + (r << 6) + (cidx << 5) + kk;
            bool valid = (j >= 0 && j < SS);
            cpasync16z(s2u(dst + cidx*2304 + kk*72 + (d4 << 2)),
                       src + (((size_t)(valid ? j : 0)) << 6) + (d4 << 2),
                       valid ? 16u : 0u);
        }
        cp_commit();
    };

    // ---- prologue: q tile + global K (group), then score round 0 (group) ----
    {
        int row = tid >> 4, d4 = tid & 15;
        cpasync16(s2u(qs + row*68 + (d4 << 2)), qb + (((size_t)(base + row)) << 6) + (d4 << 2));
        cpasync16(s2u(gvs + row*72 + (d4 << 2)), kb + (((size_t)row) << 6) + (d4 << 2));
        cp_commit();
    }
    stage_round(kb, 0);
    cp_wait<1>();           // q + global K done; round 0 in flight
    __syncthreads();

    // per-warp Q fragments
    unsigned aq[8][4];
#pragma unroll
    for (int k8 = 0; k8 < 8; k8++) {
        int k0 = k8 << 3;
        aq[k8][0] = __float_as_uint(qs[gl*68     + k0 + qd    ]);
        aq[k8][1] = __float_as_uint(qs[(gl+8)*68 + k0 + qd    ]);
        aq[k8][2] = __float_as_uint(qs[gl*68     + k0 + qd + 4]);
        aq[k8][3] = __float_as_uint(qs[(gl+8)*68 + k0 + qd + 4]);
    }

    // global-key scores (warps 0,1) — overlaps with round-0 staging
    if (warp < 2) {
        float acc[4] = {0.f, 0.f, 0.f, 0.f};
        unsigned bfr[2];
#pragma unroll
        for (int k8 = 0; k8 < 8; k8++) {
            int k0 = k8 << 3;
            bfr[0] = __float_as_uint(gvs[(warp*8 + gl)*72 + k0 + qd    ]);
            bfr[1] = __float_as_uint(gvs[(warp*8 + gl)*72 + k0 + qd + 4]);
            mma_tf32(acc, aq[k8], bfr);
        }
        int key = warp*8 + (qd << 1);
        sc[gl*SCW     + key    ] = acc[0];
        sc[gl*SCW     + key + 1] = acc[1];
        sc[(gl+8)*SCW + key    ] = acc[2];
        sc[(gl+8)*SCW + key + 1] = acc[3];
    }

    // ---- score rounds 0..8 (pipelined) ----
    for (int r = 0; r < 9; r++) {
        if (r < 8) { stage_round(kb, r + 1); cp_wait<1>(); }
        else       { cp_wait<0>(); }
        if (tid < 64) {
            int j = jmin + (r << 6) + tid;
            int rm = 1;
            if (j >= 0 && j < SS) { int m = am[b*SS + j] * (gm[b*SS + j] + 1); rm = (m != 1); }
            rmv[tid] = rm;
        }
        __syncthreads();

        int cidx = warp >> 2;
        int cglob = (r << 1) + cidx;
        if (cglob <= 16) {
            const float* kc = ks + (r & 1)*4608 + cidx*2304;
            int cb = cglob << 5;
            int ntile = warp & 3;
            float acc[4] = {0.f, 0.f, 0.f, 0.f};
            unsigned bfr[2];
#pragma unroll
            for (int k8 = 0; k8 < 8; k8++) {
                int k0 = k8 << 3;
                bfr[0] = __float_as_uint(kc[(ntile*8 + gl)*72 + k0 + qd    ]);
                bfr[1] = __float_as_uint(kc[(ntile*8 + gl)*72 + k0 + qd + 4]);
                mma_tf32(acc, aq[k8], bfr);
            }
            int kkA = (ntile << 3) + (qd << 1);
            int r0 = rmv[(cidx << 5) + kkA];
            int r1 = rmv[(cidx << 5) + kkA + 1];
            int l0 = cb + kkA - gl;
            sc[gl*SCW     + BOFF + l0    ] = r0 ? NEGV : acc[0];
            sc[gl*SCW     + BOFF + l0 + 1] = r1 ? NEGV : acc[1];
            sc[(gl+8)*SCW + BOFF + l0 - 8] = r0 ? NEGV : acc[2];
            sc[(gl+8)*SCW + BOFF + l0 - 7] = r1 ? NEGV : acc[3];
        }
        __syncthreads();
    }

    // ---- softmax over 16 global + 513 band ----
    {
        const int p = tid >> 4, r = tid & 15;
        float mx = sc[p*SCW + r];
        for (int l = r; l <= 512; l += 16) mx = fmaxf(mx, sc[p*SCW + BOFF + l]);
#pragma unroll
        for (int o = 8; o; o >>= 1) mx = fmaxf(mx, __shfl_xor_sync(0xffffffffu, mx, o, 16));
        float gv0 = __expf(sc[p*SCW + r] - mx);
        sc[p*SCW + r] = tfr(gv0);
        float sum = gv0;
        for (int l = r; l <= 512; l += 16) {
            float e = __expf(sc[p*SCW + BOFF + l] - mx);
            sc[p*SCW + BOFF + l] = tfr(e);
            sum += e;
        }
#pragma unroll
        for (int o = 8; o; o >>= 1) sum += __shfl_xor_sync(0xffffffffu, sum, o, 16);
        if (r == 0) {
            int iq = base + p;
            int mm = am[b*SS + iq] * (gm[b*SS + iq] + 1);
            scl[p] = (mm == 0) ? 0.f : (1.f / sum);
        }
    }
    // zero dead zones [16,39] and [553,583]
    for (int i = tid; i < 880; i += 256) {
        int pp = i / 55, o = i % 55;
        int idx = (o < 24) ? (16 + o) : (553 + (o - 24));
        sc[pp*SCW + idx] = 0.f;
    }
    __syncthreads();

    // ---- AV prologue: global V (group) + AV round 0 (group) ----
    {
        int row = tid >> 4, d4 = tid & 15;
        cpasync16(s2u(gvs + row*72 + (d4 << 2)), vb + (((size_t)row) << 6) + (d4 << 2));
        cp_commit();
    }
    stage_round(vb, 0);
    cp_wait<1>();           // global V done; AV round 0 in flight
    __syncthreads();

    float av[4] = {0.f, 0.f, 0.f, 0.f};
    const int nd = (warp << 3) + gl;
    {
        unsigned afr[4], bfr[2];
#pragma unroll
        for (int k8 = 0; k8 < 2; k8++) {
            int k0 = k8 << 3;
            afr[0] = __float_as_uint(sc[gl*SCW     + k0 + qd    ]);
            afr[1] = __float_as_uint(sc[(gl+8)*SCW + k0 + qd    ]);
            afr[2] = __float_as_uint(sc[gl*SCW     + k0 + qd + 4]);
            afr[3] = __float_as_uint(sc[(gl+8)*SCW + k0 + qd + 4]);
            bfr[0] = __float_as_uint(gvs[(k0 + qd    )*72 + nd]);
            bfr[1] = __float_as_uint(gvs[(k0 + qd + 4)*72 + nd]);
            mma_tf32(av, afr, bfr);
        }
    }

    // ---- AV rounds 0..8 (pipelined) ----
    for (int r = 0; r < 9; r++) {
        if (r < 8) { stage_round(vb, r + 1); cp_wait<1>(); }
        else       { cp_wait<0>(); }
        __syncthreads();
        int nch = (r < 8) ? 2 : 1;
        const float* vbuf = ks + (r & 1)*4608;
        for (int cidx = 0; cidx < nch; cidx++) {
            int cb = ((r << 1) + cidx) << 5;
            const float* vc = vbuf + cidx*2304;
            unsigned afr[4], bfr[2];
#pragma unroll
            for (int k8 = 0; k8 < 4; k8++) {
                int kA = (k8 << 3) + qd;
                int i0 = cb + kA - gl;
                afr[0] = __float_as_uint(sc[gl*SCW     + BOFF + i0    ]);
                afr[1] = __float_as_uint(sc[(gl+8)*SCW + BOFF + i0 - 8]);
                afr[2] = __float_as_uint(sc[gl*SCW     + BOFF + i0 + 4]);
                afr[3] = __float_as_uint(sc[(gl+8)*SCW + BOFF + i0 - 4]);
                bfr[0] = __float_as_uint(vc[kA*72       + nd]);
                bfr[1] = __float_as_uint(vc[(kA + 4)*72 + nd]);
                mma_tf32(av, afr, bfr);
            }
        }
        __syncthreads();
    }

    {
        float s0 = scl[gl], s1 = scl[gl + 8];
        int d = (warp << 3) + (qd << 1);
        int iq0 = base + gl, iq1 = base + gl + 8;
        *(float2*)(attn + ((size_t)b*SS + iq0)*EE + h*DHH + d) = make_float2(av[0]*s0, av[1]*s0);
        *(float2*)(attn + ((size_t)b*SS + iq1)*EE + h*DHH + d) = make_float2(av[2]*s1, av[3]*s1);
    }
}

// ---------------- global attention (overwrites attn rows < G) ----------------
__global__ __launch_bounds__(256) void global_attn_kernel(
    const float* __restrict__ gq, const float* __restrict__ gk, const float* __restrict__ gv,
    const int* __restrict__ am, const int* __restrict__ gm,
    float* __restrict__ attn)
{
    int g = blockIdx.x, h = blockIdx.y, b = blockIdx.z;
    int tid = threadIdx.x;
    __shared__ float sc[SS];
    __shared__ float qrow[64];
    __shared__ float red[8];
    __shared__ float redv[4][64];

    const float* gkb = gk + ((size_t)(b*HH + h) * SS) * DHH;
    const float* gvb = gv + ((size_t)(b*HH + h) * SS) * DHH;
    if (tid < 64) qrow[tid] = gq[(((size_t)(b*HH + h) * SS + g) << 6) + tid];
    __syncthreads();

    float lmax = -3.4e38f;
    for (int j = tid; j < SS; j += 256) {
        int m = am[b*SS + j] * (gm[b*SS + j] + 1);
        float s;
        if (m == 0) s = NEGV;
        else {
            float a0=0.f,a1=0.f,a2=0.f,a3=0.f;
            const float4* kp = (const float4*)(gkb + (size_t)j * DHH);
            const float4* qp = (const float4*)qrow;
#pragma unroll
            for (int d4 = 0; d4 < 16; d4++) {
                float4 a = qp[d4], bb = kp[d4];
                a0 += a.x*bb.x; a1 += a.y*bb.y; a2 += a.z*bb.z; a3 += a.w*bb.w;
            }
            s = (a0 + a1) + (a2 + a3);
        }
        sc[j] = s;
        lmax = fmaxf(lmax, s);
    }
#pragma unroll
    for (int o = 16; o; o >>= 1) lmax = fmaxf(lmax, __shfl_xor_sync(0xffffffffu, lmax, o));
    if ((tid & 31) == 0) red[tid >> 5] = lmax;
    __syncthreads();
    float bmax = red[0];
#pragma unroll
    for (int w = 1; w < 8; w++) bmax = fmaxf(bmax, red[w]);

    float lsum = 0.f;
    for (int j = tid; j < SS; j += 256) {
        float e = __expf(sc[j] - bmax);
        sc[j] = e;
        lsum += e;
    }
#pragma unroll
    for (int o = 16; o; o >>= 1) lsum += __shfl_xor_sync(0xffffffffu, lsum, o);
    __syncthreads();
    if ((tid & 31) == 0) red[tid >> 5] = lsum;
    __syncthreads();
    float ssum = 0.f;
#pragma unroll
    for (int w = 0; w < 8; w++) ssum += red[w];
    float inv = 1.f / ssum;

    int grp = tid >> 6, d = tid & 63;
    float acc0 = 0.f, acc1 = 0.f;
    for (int j = grp; j < SS; j += 8) {
        acc0 += sc[j] * gvb[(size_t)j * DHH + d];
        acc1 += sc[j + 4] * gvb[(size_t)(j + 4) * DHH + d];
    }
    redv[grp][d] = acc0 + acc1;
    __syncthreads();
    if (grp == 0) {
        float o = (redv[0][d] + redv[1][d] + redv[2][d] + redv[3][d]) * inv;
        attn[((size_t)b*SS + g)*EE + h*DHH + d] = o;
    }
}

// ---------------- fused add + LayerNorm ----------------
__global__ __launch_bounds__(256) void add_ln_kernel(
    const float* __restrict__ a, const float* __restrict__ c,
    const float* __restrict__ gamma, const float* __restrict__ beta,
    float* __restrict__ out)
{
    int row = blockIdx.x;
    int tid = threadIdx.x;
    __shared__ float buf[EE];
    __shared__ float red[8];

    float local = 0.f;
#pragma unroll
    for (int i = 0; i < 3; i++) {
        int idx = tid + i*256;
        float v = a[(size_t)row*EE + idx] + c[(size_t)row*EE + idx];
        buf[idx] = v;
        local += v;
    }
#pragma unroll
    for (int o = 16; o; o >>= 1) local += __shfl_xor_sync(0xffffffffu, local, o);
    if ((tid & 31) == 0) red[tid >> 5] = local;
    __syncthreads();
    float s = 0.f;
#pragma unroll
    for (int w = 0; w < 8; w++) s += red[w];
    float mean = s * (1.f/768.f);

    float lv = 0.f;
#pragma unroll
    for (int i = 0; i < 3; i++) {
        float dd = buf[tid + i*256] - mean;
        lv += dd*dd;
    }
#pragma unroll
    for (int o = 16; o; o >>= 1) lv += __shfl_xor_sync(0xffffffffu, lv, o);
    __syncthreads();
    if ((tid & 31) == 0) red[tid >> 5] = lv;
    __syncthreads();
    float vs = 0.f;
#pragma unroll
    for (int w = 0; w < 8; w++) vs += red[w];
    float invstd = rsqrtf(vs * (1.f/768.f) + 1e-5f);

#pragma unroll
    for (int i = 0; i < 3; i++) {
        int idx = tid + i*256;
        out[(size_t)row*EE + idx] = (buf[idx] - mean) * invstd * gamma[idx] + beta[idx];
    }
}

// ---------------- SiLU(t1) * t2 -> t1 ----------------
__global__ void silu_mul_kernel(float* __restrict__ t1, const float* __restrict__ t2, int n) {
    int i = blockIdx.x * blockDim.x + threadIdx.x;
    if (i < n) {
        float a = t1[i];
        t1[i] = a / (1.f + expf(-a)) * t2[i];
    }
}

// ---------------- launch ----------------
extern "C" void kernel_launch(void* const* d_in, const int* in_sizes, int n_in,
                              void* d_out, int out_size) {
    (void)in_sizes; (void)n_in; (void)out_size;
    const float* x    = (const float*)d_in[0];
    const int*   am   = (const int*)d_in[1];
    const int*   gm   = (const int*)d_in[2];
    const float* Wq   = (const float*)d_in[3];  const float* bq  = (const float*)d_in[4];
    const float* Wk   = (const float*)d_in[5];  const float* bk  = (const float*)d_in[6];
    const float* Wv   = (const float*)d_in[7];  const float* bv  = (const float*)d_in[8];
    const float* Wqg  = (const float*)d_in[9];  const float* bqg = (const float*)d_in[10];
    const float* Wkg  = (const float*)d_in[11]; const float* bkg = (const float*)d_in[12];
    const float* Wvg  = (const float*)d_in[13]; const float* bvg = (const float*)d_in[14];
    const float* ln0g = (const float*)d_in[15]; const float* ln0b = (const float*)d_in[16];
    const float* ln1g = (const float*)d_in[17]; const float* ln1b = (const float*)d_in[18];
    const float* W1   = (const float*)d_in[19];
    const float* W3   = (const float*)d_in[20];
    const float* W2   = (const float*)d_in[21];
    float* out = (float*)d_out;

    float *qp, *kp, *vp, *gqp, *gkp, *gvp, *attnp, *h0p, *t1p, *t2p, *tbp;
    cudaGetSymbolAddress((void**)&qp,  g_q);
    cudaGetSymbolAddress((void**)&kp,  g_k);
    cudaGetSymbolAddress((void**)&vp,  g_v);
    cudaGetSymbolAddress((void**)&gqp, g_gq);
    cudaGetSymbolAddress((void**)&gkp, g_gk);
    cudaGetSymbolAddress((void**)&gvp, g_gv);
    cudaGetSymbolAddress((void**)&attnp, g_attn);
    cudaGetSymbolAddress((void**)&h0p, g_h0);
    cudaGetSymbolAddress((void**)&t1p, g_t1);
    cudaGetSymbolAddress((void**)&t2p, g_t2);
    cudaGetSymbolAddress((void**)&tbp, g_tbuf);

    cudaFuncSetAttribute(band_attn_kernel,
                         cudaFuncAttributeMaxDynamicSharedMemorySize, BAND_SMEM);
    cudaFuncSetAttribute(tf32gemm_kernel,
                         cudaFuncAttributeMaxDynamicSharedMemorySize, GEMM_SMEM);

    mask_cumsum_kernel<<<BB, 256>>>(am, gm, tbp);

    GemmArgs pa = {};
    pa.A = x; pa.N = EE; pa.K = EE; pa.epi = 1;
    pa.Wm[0] = Wq;  pa.bias[0] = bq;  pa.out[0] = qp;  pa.scale[0] = 0.125f;
    pa.Wm[1] = Wk;  pa.bias[1] = bk;  pa.out[1] = kp;  pa.scale[1] = 1.f;
    pa.Wm[2] = Wv;  pa.bias[2] = bv;  pa.out[2] = vp;  pa.scale[2] = 1.f;
    pa.Wm[3] = Wqg; pa.bias[3] = bqg; pa.out[3] = gqp; pa.scale[3] = 0.125f;
    pa.Wm[4] = Wkg; pa.bias[4] = bkg; pa.out[4] = gkp; pa.scale[4] = 1.f;
    pa.Wm[5] = Wvg; pa.bias[5] = bvg; pa.out[5] = gvp; pa.scale[5] = 1.f;
    tf32gemm_kernel<<<dim3(32, 6, 6), 128, GEMM_SMEM>>>(pa);

    rope_kernel<<<(BB*HH*SS*32 + 255)/256, 256>>>(qp, kp, tbp);

    band_attn_kernel<<<dim3(SS/16, HH, BB), 256, BAND_SMEM>>>(qp, kp, vp, am, gm, attnp);
    global_attn_kernel<<<dim3(GG, HH, BB), 256>>>(gqp, gkp, gvp, am, gm, attnp);

    add_ln_kernel<<<BB*SS, 256>>>(x, attnp, ln0g, ln0b, h0p);

    GemmArgs f1 = {};
    f1.A = h0p; f1.N = FFD; f1.K = EE; f1.epi = 0;
    f1.Wm[0] = W1; f1.bias[0] = nullptr; f1.out[0] = t1p; f1.scale[0] = 1.f;
    f1.Wm[1] = W3; f1.bias[1] = nullptr; f1.out[1] = t2p; f1.scale[1] = 1.f;
    tf32gemm_kernel<<<dim3(32, 24, 2), 128, GEMM_SMEM>>>(f1);

    silu_mul_kernel<<<(NFF + 255)/256, 256>>>(t1p, t2p, NFF);

    GemmArgs f2 = {};
    f2.A = t1p; f2.N = EE; f2.K = FFD; f2.epi = 0;
    f2.Wm[0] = W2; f2.bias[0] = nullptr; f2.out[0] = attnp; f2.scale[0] = 1.f;
    tf32gemm_kernel<<<dim3(32, 6, 1), 128, GEMM_SMEM>>>(f2);

    add_ln_kernel<<<BB*SS, 256>>>(h0p, attnp, ln1g, ln1b, out);
}

// round 14
// speedup vs baseline: 3.3752x; 1.0428x over previous
#include <cuda_runtime.h>
#include <cuda_bf16.h>
#include <math.h>

#define BB 2
#define SS 2048
#define EE 768
#define HH 12
#define DHH 64
#define WW 256
#define GG 16
#define FFD 3072
#define NEGV (-1e9f)

#define NQKV (BB*HH*SS*DHH)
#define NXE  (BB*SS*EE)
#define NFF  (BB*SS*FFD)

// ---------------- device scratch ----------------
__device__ float g_q[NQKV];
__device__ float g_k[NQKV];
__device__ float g_v[NQKV];
__device__ float g_gq[NQKV];
__device__ float g_gk[NQKV];
__device__ float g_gv[NQKV];
__device__ float g_attn[NXE];
__device__ float g_h0[NXE];
__device__ float g_t1[NFF];
__device__ float g_t2[NFF];
__device__ float g_tbuf[BB*SS];

// ---------------- mma / cp.async helpers ----------------
__device__ __forceinline__ void mma_tf32(float (&d)[4], const unsigned* a, const unsigned* b) {
    asm volatile(
        "mma.sync.aligned.m16n8k8.row.col.f32.tf32.tf32.f32 "
        "{%0,%1,%2,%3}, {%4,%5,%6,%7}, {%8,%9}, {%0,%1,%2,%3};\n"
        : "+f"(d[0]), "+f"(d[1]), "+f"(d[2]), "+f"(d[3])
        : "r"(a[0]), "r"(a[1]), "r"(a[2]), "r"(a[3]), "r"(b[0]), "r"(b[1]));
}
__device__ __forceinline__ void cpasync16(unsigned dst, const void* src) {
    asm volatile("cp.async.cg.shared.global [%0], [%1], 16;\n" :: "r"(dst), "l"(src));
}
__device__ __forceinline__ void cpasync16z(unsigned dst, const void* src, unsigned ssz) {
    asm volatile("cp.async.cg.shared.global [%0], [%1], 16, %2;\n" :: "r"(dst), "l"(src), "r"(ssz));
}
__device__ __forceinline__ void cp_commit() {
    asm volatile("cp.async.commit_group;\n");
}
template <int N> __device__ __forceinline__ void cp_wait() {
    asm volatile("cp.async.wait_group %0;\n" :: "n"(N));
}
__device__ __forceinline__ float tfr(float x) {
    unsigned r; asm("cvt.rna.tf32.f32 %0, %1;" : "=r"(r) : "f"(x));
    return __uint_as_float(r);
}
__device__ __forceinline__ unsigned s2u(const void* p) {
    return (unsigned)__cvta_generic_to_shared(p);
}

// ---------------- parallel cumsum of global flags -> t ----------------
__global__ __launch_bounds__(256) void mask_cumsum_kernel(const int* __restrict__ am,
                                                          const int* __restrict__ gm,
                                                          float* __restrict__ tb) {
    int b = blockIdx.x;
    int tid = threadIdx.x;
    int lane = tid & 31, warp = tid >> 5;
    __shared__ int flg[SS];
    __shared__ int wsum[8];
    for (int i = tid; i < SS; i += 256)
        flg[i] = am[b*SS + i] * (gm[b*SS + i] + 1);
    __syncthreads();
    int base = tid << 3;
    int loc[8];
    int s = 0;
#pragma unroll
    for (int j = 0; j < 8; j++) { loc[j] = s; s += (flg[base + j] == 2); }
    int inc = s;
#pragma unroll
    for (int o = 1; o < 32; o <<= 1) {
        int v = __shfl_up_sync(0xffffffffu, inc, o);
        if (lane >= o) inc += v;
    }
    if (lane == 31) wsum[warp] = inc;
    __syncthreads();
    int woff = 0;
#pragma unroll
    for (int w = 0; w < 8; w++) if (w < warp) woff += wsum[w];
    int excl = woff + inc - s;
#pragma unroll
    for (int j = 0; j < 8; j++) {
        int idx = base + j;
        int m = flg[idx];
        int c = excl + loc[j] + (m == 2);
        tb[b*SS + idx] = (m == 0) ? 0.f : (float)c;
    }
}

// ---------------- tf32 GEMM: 3-stage cp.async pipeline, 4 warps 64x64 ----------------
struct GemmArgs {
    const float* A;
    const float* Wm[6];
    const float* bias[6];
    float* out[6];
    float scale[6];
    int N, K, epi;
};

#define APAD 20
#define BPAD 136
#define GEMM_SMEM ((3*128*APAD + 3*16*BPAD) * 4)

__global__ __launch_bounds__(128, 2) void tf32gemm_kernel(GemmArgs g) {
    extern __shared__ float gsm[];
    float* Ab = gsm;
    float* Bb = gsm + 3*128*APAD;

    const int z = blockIdx.z;
    const float* __restrict__ A = g.A;
    const float* __restrict__ W = g.Wm[z];
    const float* __restrict__ bias = g.bias[z];
    float* __restrict__ out = g.out[z];
    const int N = g.N, K = g.K;
    const int bm = blockIdx.x << 7, bn = blockIdx.y << 7;

    const int tid = threadIdx.x;
    const int lane = tid & 31, warp = tid >> 5;
    const int wm = (warp >> 1) << 6;
    const int wn = (warp & 1) << 6;
    const int gl = lane >> 2, qd = lane & 3;

    float acc[4][8][4];
#pragma unroll
    for (int i = 0; i < 4; i++)
#pragma unroll
        for (int j = 0; j < 8; j++)
#pragma unroll
            for (int r = 0; r < 4; r++) acc[i][j][r] = 0.f;

    const float* Agp0 = A + (size_t)(bm + (tid >> 2)) * K + ((tid & 3) << 2);
    const float* Wgp0 = W + (size_t)(tid >> 5) * N + bn + ((tid & 31) << 2);
    const size_t AgS = (size_t)32 * K;
    const size_t WgS = (size_t)4 * N;
    const unsigned sAb = s2u(Ab + (tid >> 2)*APAD + ((tid & 3) << 2));
    const unsigned sBb = s2u(Bb + (tid >> 5)*BPAD + ((tid & 31) << 2));
    const unsigned ABUF = 128 * APAD * 4;
    const unsigned BBUF = 16 * BPAD * 4;
    const unsigned AT = 32 * APAD * 4;
    const unsigned BT = 4 * BPAD * 4;

    const int NIT = K >> 4;

#define G_STAGE(s, k0) do {                                                   \
        _Pragma("unroll")                                                     \
        for (int t = 0; t < 4; t++) {                                         \
            cpasync16(sAb + (s)*ABUF + t*AT, Agp0 + (k0) + (size_t)t*AgS);    \
            cpasync16(sBb + (s)*BBUF + t*BT, Wgp0 + (size_t)(k0)*N + (size_t)t*WgS); \
        }                                                                     \
        cp_commit();                                                          \
    } while (0)

    G_STAGE(0, 0);
    if (NIT > 1) G_STAGE(1, 16);
    int cur = 0;

    for (int it = 0; it < NIT; it++) {
        if (it + 2 < NIT) {
            int nx2 = cur + 2; if (nx2 >= 3) nx2 -= 3;
            G_STAGE(nx2, (it + 2) << 4);
            cp_wait<2>();
        } else if (it + 1 < NIT) {
            cp_wait<1>();
        } else {
            cp_wait<0>();
        }
        __syncthreads();

        const float* Ac = Ab + cur*128*APAD;
        const float* Bc = Bb + cur*16*BPAD;
#pragma unroll
        for (int kt = 0; kt < 2; kt++) {
            const int k0 = kt << 3;
            unsigned afr[4][4], bfr[8][2];
#pragma unroll
            for (int mtl = 0; mtl < 4; mtl++) {
                int m = wm + (mtl << 4);
                afr[mtl][0] = __float_as_uint(Ac[(m + gl    )*APAD + k0 + qd    ]);
                afr[mtl][1] = __float_as_uint(Ac[(m + gl + 8)*APAD + k0 + qd    ]);
                afr[mtl][2] = __float_as_uint(Ac[(m + gl    )*APAD + k0 + qd + 4]);
                afr[mtl][3] = __float_as_uint(Ac[(m + gl + 8)*APAD + k0 + qd + 4]);
            }
#pragma unroll
            for (int ntl = 0; ntl < 8; ntl++) {
                int n = wn + (ntl << 3) + gl;
                bfr[ntl][0] = __float_as_uint(Bc[(k0 + qd    )*BPAD + n]);
                bfr[ntl][1] = __float_as_uint(Bc[(k0 + qd + 4)*BPAD + n]);
            }
#pragma unroll
            for (int mtl = 0; mtl < 4; mtl++)
#pragma unroll
                for (int ntl = 0; ntl < 8; ntl++)
                    mma_tf32(acc[mtl][ntl], afr[mtl], bfr[ntl]);
        }
        __syncthreads();
        cur = (cur == 2) ? 0 : cur + 1;
    }
#undef G_STAGE

    const float sc = g.scale[z];
#pragma unroll
    for (int mtl = 0; mtl < 4; mtl++) {
        int row0 = bm + wm + (mtl << 4) + gl;
#pragma unroll
        for (int ntl = 0; ntl < 8; ntl++) {
            int col = bn + wn + (ntl << 3) + (qd << 1);
            float v0 = acc[mtl][ntl][0], v1 = acc[mtl][ntl][1];
            float v2 = acc[mtl][ntl][2], v3 = acc[mtl][ntl][3];
            if (bias) {
                float b0 = bias[col], b1 = bias[col + 1];
                v0 += b0; v1 += b1; v2 += b0; v3 += b1;
            }
            v0 *= sc; v1 *= sc; v2 *= sc; v3 *= sc;
            if (g.epi == 0) {
                *(float2*)(out + (size_t)row0 * N + col)       = make_float2(v0, v1);
                *(float2*)(out + (size_t)(row0 + 8) * N + col) = make_float2(v2, v3);
            } else {
                int h = col >> 6, d = col & 63;
                int b0i = row0 >> 11, s0 = row0 & (SS - 1);
                int row1 = row0 + 8;
                int b1i = row1 >> 11, s1 = row1 & (SS - 1);
                *(float2*)(out + (((size_t)(b0i*HH + h) * SS + s0) << 6) + d) = make_float2(v0, v1);
                *(float2*)(out + (((size_t)(b1i*HH + h) * SS + s1) << 6) + d) = make_float2(v2, v3);
            }
        }
    }
}

// ---------------- RoPE on q and k (in-place) ----------------
__global__ void rope_kernel(float* __restrict__ q, float* __restrict__ k,
                            const float* __restrict__ tb) {
    int idx = blockIdx.x * blockDim.x + threadIdx.x;
    const int total = BB*HH*SS*32;
    if (idx >= total) return;
    int d   = idx & 31;
    int rem = idx >> 5;
    int s   = rem & (SS-1);
    int rem2 = rem >> 11;
    int h   = rem2 % HH;
    int b   = rem2 / HH;
    float tt = tb[b*SS + s];
    float inv_freq = expf(-(float)d * 0.28782313662425574f);
    float sn, cs;
    sincosf(tt * inv_freq, &sn, &cs);
    size_t off = (((size_t)(b*HH + h) * SS + s) << 6) + d;
    float x1 = q[off], x2 = q[off + 32];
    q[off]      = x1*cs - x2*sn;
    q[off + 32] = x2*cs + x1*sn;
    x1 = k[off]; x2 = k[off + 32];
    k[off]      = x1*cs - x2*sn;
    k[off + 32] = x2*cs + x1*sn;
}

// ---------------- banded + global-key attention (depth-2 pipelined mma) ----------------
// sc row width 584: [0..15] global; band l at [40+l]; dead zones [16,39],[553,583].
// K/V staged through a 3-deep ring (rounds r+1, r+2 in flight during round r).
#define SCW 584
#define BOFF 40
#define BAND_SMEM ((1088 + 16*SCW + 13824 + 1152 + 16) * 4 + 64 * 4)

__global__ __launch_bounds__(256) void band_attn_kernel(
    const float* __restrict__ q, const float* __restrict__ k, const float* __restrict__ v,
    const int* __restrict__ am, const int* __restrict__ gm,
    float* __restrict__ attn)
{
    extern __shared__ float sm[];
    float* qs  = sm;                    // [16][68]
    float* sc  = sm + 1088;             // [16][SCW]
    float* ks  = sc + 16*SCW;           // ring [3][2][32][72]
    float* gvs = ks + 13824;            // [16][72] global K, later global V
    float* scl = gvs + 1152;            // [16]
    int*   rmv = (int*)(scl + 16);      // [64]

    const int b = blockIdx.z, h = blockIdx.y, base = blockIdx.x << 4;
    const int tid = threadIdx.x;
    const int lane = tid & 31, warp = tid >> 5;
    const int gl = lane >> 2, qd = lane & 3;

    const float* qb = q + ((size_t)(b*HH + h) * SS) * DHH;
    const float* kb = k + ((size_t)(b*HH + h) * SS) * DHH;
    const float* vb = v + ((size_t)(b*HH + h) * SS) * DHH;

    const int jmin = base - WW;

    // stage one round (<=64 keys) of src into ring buffer (r%3); 1 commit group
    auto stage_round = [&](const float* src, int r) {
        int nch = (r < 8) ? 2 : 1;
        float* dst = ks + (r % 3) * 4608;
        for (int i = tid; i < (nch << 9); i += 256) {
            int cidx = i >> 9, rem = i & 511;
            int kk = rem >> 4, d4 = rem & 15;
            int j = jmin + (r << 6) + (cidx << 5) + kk;
            bool valid = (j >= 0 && j < SS);
            cpasync16z(s2u(dst + cidx*2304 + kk*72 + (d4 << 2)),
                       src + (((size_t)(valid ? j : 0)) << 6) + (d4 << 2),
                       valid ? 16u : 0u);
        }
        cp_commit();
    };

    // ---- prologue: q tile + global K, then score rounds 0,1 in flight ----
    {
        int row = tid >> 4, d4 = tid & 15;
        cpasync16(s2u(qs + row*68 + (d4 << 2)), qb + (((size_t)(base + row)) << 6) + (d4 << 2));
        cpasync16(s2u(gvs + row*72 + (d4 << 2)), kb + (((size_t)row) << 6) + (d4 << 2));
        cp_commit();
    }
    stage_round(kb, 0);
    stage_round(kb, 1);
    cp_wait<1>();           // q/gK + round0 done; round1 in flight
    __syncthreads();

    // per-warp Q fragments
    unsigned aq[8][4];
#pragma unroll
    for (int k8 = 0; k8 < 8; k8++) {
        int k0 = k8 << 3;
        aq[k8][0] = __float_as_uint(qs[gl*68     + k0 + qd    ]);
        aq[k8][1] = __float_as_uint(qs[(gl+8)*68 + k0 + qd    ]);
        aq[k8][2] = __float_as_uint(qs[gl*68     + k0 + qd + 4]);
        aq[k8][3] = __float_as_uint(qs[(gl+8)*68 + k0 + qd + 4]);
    }

    // global-key scores (warps 0,1)
    if (warp < 2) {
        float acc[4] = {0.f, 0.f, 0.f, 0.f};
        unsigned bfr[2];
#pragma unroll
        for (int k8 = 0; k8 < 8; k8++) {
            int k0 = k8 << 3;
            bfr[0] = __float_as_uint(gvs[(warp*8 + gl)*72 + k0 + qd    ]);
            bfr[1] = __float_as_uint(gvs[(warp*8 + gl)*72 + k0 + qd + 4]);
            mma_tf32(acc, aq[k8], bfr);
        }
        int key = warp*8 + (qd << 1);
        sc[gl*SCW     + key    ] = acc[0];
        sc[gl*SCW     + key + 1] = acc[1];
        sc[(gl+8)*SCW + key    ] = acc[2];
        sc[(gl+8)*SCW + key + 1] = acc[3];
    }

    // ---- score rounds 0..8, depth-2 pipeline ----
    for (int r = 0; r < 9; r++) {
        if (r + 2 <= 8) stage_round(kb, r + 2);
        if (r + 1 <= 8) cp_wait<1>(); else cp_wait<0>();
        if (tid < 64) {
            int j = jmin + (r << 6) + tid;
            int rm = 1;
            if (j >= 0 && j < SS) { int m = am[b*SS + j] * (gm[b*SS + j] + 1); rm = (m != 1); }
            rmv[tid] = rm;
        }
        __syncthreads();

        int cidx = warp >> 2;
        int cglob = (r << 1) + cidx;
        if (cglob <= 16) {
            const float* kc = ks + (r % 3)*4608 + cidx*2304;
            int cb = cglob << 5;
            int ntile = warp & 3;
            float acc[4] = {0.f, 0.f, 0.f, 0.f};
            unsigned bfr[2];
#pragma unroll
            for (int k8 = 0; k8 < 8; k8++) {
                int k0 = k8 << 3;
                bfr[0] = __float_as_uint(kc[(ntile*8 + gl)*72 + k0 + qd    ]);
                bfr[1] = __float_as_uint(kc[(ntile*8 + gl)*72 + k0 + qd + 4]);
                mma_tf32(acc, aq[k8], bfr);
            }
            int kkA = (ntile << 3) + (qd << 1);
            int r0 = rmv[(cidx << 5) + kkA];
            int r1 = rmv[(cidx << 5) + kkA + 1];
            int l0 = cb + kkA - gl;
            sc[gl*SCW     + BOFF + l0    ] = r0 ? NEGV : acc[0];
            sc[gl*SCW     + BOFF + l0 + 1] = r1 ? NEGV : acc[1];
            sc[(gl+8)*SCW + BOFF + l0 - 8] = r0 ? NEGV : acc[2];
            sc[(gl+8)*SCW + BOFF + l0 - 7] = r1 ? NEGV : acc[3];
        }
        __syncthreads();
    }

    // ---- prefetch global V + AV rounds 0,1 (lands during softmax) ----
    {
        int row = tid >> 4, d4 = tid & 15;
        cpasync16(s2u(gvs + row*72 + (d4 << 2)), vb + (((size_t)row) << 6) + (d4 << 2));
        cp_commit();
    }
    stage_round(vb, 0);
    stage_round(vb, 1);

    // ---- softmax over 16 global + 513 band ----
    {
        const int p = tid >> 4, r = tid & 15;
        float mx = sc[p*SCW + r];
        for (int l = r; l <= 512; l += 16) mx = fmaxf(mx, sc[p*SCW + BOFF + l]);
#pragma unroll
        for (int o = 8; o; o >>= 1) mx = fmaxf(mx, __shfl_xor_sync(0xffffffffu, mx, o, 16));
        float gv0 = __expf(sc[p*SCW + r] - mx);
        sc[p*SCW + r] = tfr(gv0);
        float sum = gv0;
        for (int l = r; l <= 512; l += 16) {
            float e = __expf(sc[p*SCW + BOFF + l] - mx);
            sc[p*SCW + BOFF + l] = tfr(e);
            sum += e;
        }
#pragma unroll
        for (int o = 8; o; o >>= 1) sum += __shfl_xor_sync(0xffffffffu, sum, o, 16);
        if (r == 0) {
            int iq = base + p;
            int mm = am[b*SS + iq] * (gm[b*SS + iq] + 1);
            scl[p] = (mm == 0) ? 0.f : (1.f / sum);
        }
    }
    // zero dead zones [16,39] and [553,583]
    for (int i = tid; i < 880; i += 256) {
        int pp = i / 55, o = i % 55;
        int idx = (o < 24) ? (16 + o) : (553 + (o - 24));
        sc[pp*SCW + idx] = 0.f;
    }
    cp_wait<1>();           // global V + AV round0 done; round1 in flight
    __syncthreads();

    float av[4] = {0.f, 0.f, 0.f, 0.f};
    const int nd = (warp << 3) + gl;
    {   // global-V contribution
        unsigned afr[4], bfr[2];
#pragma unroll
        for (int k8 = 0; k8 < 2; k8++) {
            int k0 = k8 << 3;
            afr[0] = __float_as_uint(sc[gl*SCW     + k0 + qd    ]);
            afr[1] = __float_as_uint(sc[(gl+8)*SCW + k0 + qd    ]);
            afr[2] = __float_as_uint(sc[gl*SCW     + k0 + qd + 4]);
            afr[3] = __float_as_uint(sc[(gl+8)*SCW + k0 + qd + 4]);
            bfr[0] = __float_as_uint(gvs[(k0 + qd    )*72 + nd]);
            bfr[1] = __float_as_uint(gvs[(k0 + qd + 4)*72 + nd]);
            mma_tf32(av, afr, bfr);
        }
    }

    // ---- AV rounds 0..8, depth-2 pipeline ----
    for (int r = 0; r < 9; r++) {
        if (r + 2 <= 8) stage_round(vb, r + 2);
        if (r + 1 <= 8) cp_wait<1>(); else cp_wait<0>();
        __syncthreads();
        int nch = (r < 8) ? 2 : 1;
        const float* vbuf = ks + (r % 3)*4608;
        for (int cidx = 0; cidx < nch; cidx++) {
            int cb = ((r << 1) + cidx) << 5;
            const float* vc = vbuf + cidx*2304;
            unsigned afr[4], bfr[2];
#pragma unroll
            for (int k8 = 0; k8 < 4; k8++) {
                int kA = (k8 << 3) + qd;
                int i0 = cb + kA - gl;
                afr[0] = __float_as_uint(sc[gl*SCW     + BOFF + i0    ]);
                afr[1] = __float_as_uint(sc[(gl+8)*SCW + BOFF + i0 - 8]);
                afr[2] = __float_as_uint(sc[gl*SCW     + BOFF + i0 + 4]);
                afr[3] = __float_as_uint(sc[(gl+8)*SCW + BOFF + i0 - 4]);
                bfr[0] = __float_as_uint(vc[kA*72       + nd]);
                bfr[1] = __float_as_uint(vc[(kA + 4)*72 + nd]);
                mma_tf32(av, afr, bfr);
            }
        }
        __syncthreads();
    }

    {
        float s0 = scl[gl], s1 = scl[gl + 8];
        int d = (warp << 3) + (qd << 1);
        int iq0 = base + gl, iq1 = base + gl + 8;
        *(float2*)(attn + ((size_t)b*SS + iq0)*EE + h*DHH + d) = make_float2(av[0]*s0, av[1]*s0);
        *(float2*)(attn + ((size_t)b*SS + iq1)*EE + h*DHH + d) = make_float2(av[2]*s1, av[3]*s1);
    }
}

// ---------------- global attention (overwrites attn rows < G) ----------------
__global__ __launch_bounds__(256) void global_attn_kernel(
    const float* __restrict__ gq, const float* __restrict__ gk, const float* __restrict__ gv,
    const int* __restrict__ am, const int* __restrict__ gm,
    float* __restrict__ attn)
{
    int g = blockIdx.x, h = blockIdx.y, b = blockIdx.z;
    int tid = threadIdx.x;
    __shared__ float sc[SS];
    __shared__ float qrow[64];
    __shared__ float red[8];
    __shared__ float redv[4][64];

    const float* gkb = gk + ((size_t)(b*HH + h) * SS) * DHH;
    const float* gvb = gv + ((size_t)(b*HH + h) * SS) * DHH;
    if (tid < 64) qrow[tid] = gq[(((size_t)(b*HH + h) * SS + g) << 6) + tid];
    __syncthreads();

    float lmax = -3.4e38f;
    for (int j = tid; j < SS; j += 256) {
        int m = am[b*SS + j] * (gm[b*SS + j] + 1);
        float s;
        if (m == 0) s = NEGV;
        else {
            float a0=0.f,a1=0.f,a2=0.f,a3=0.f;
            const float4* kp = (const float4*)(gkb + (size_t)j * DHH);
            const float4* qp = (const float4*)qrow;
#pragma unroll
            for (int d4 = 0; d4 < 16; d4++) {
                float4 a = qp[d4], bb = kp[d4];
                a0 += a.x*bb.x; a1 += a.y*bb.y; a2 += a.z*bb.z; a3 += a.w*bb.w;
            }
            s = (a0 + a1) + (a2 + a3);
        }
        sc[j] = s;
        lmax = fmaxf(lmax, s);
    }
#pragma unroll
    for (int o = 16; o; o >>= 1) lmax = fmaxf(lmax, __shfl_xor_sync(0xffffffffu, lmax, o));
    if ((tid & 31) == 0) red[tid >> 5] = lmax;
    __syncthreads();
    float bmax = red[0];
#pragma unroll
    for (int w = 1; w < 8; w++) bmax = fmaxf(bmax, red[w]);

    float lsum = 0.f;
    for (int j = tid; j < SS; j += 256) {
        float e = __expf(sc[j] - bmax);
        sc[j] = e;
        lsum += e;
    }
#pragma unroll
    for (int o = 16; o; o >>= 1) lsum += __shfl_xor_sync(0xffffffffu, lsum, o);
    __syncthreads();
    if ((tid & 31) == 0) red[tid >> 5] = lsum;
    __syncthreads();
    float ssum = 0.f;
#pragma unroll
    for (int w = 0; w < 8; w++) ssum += red[w];
    float inv = 1.f / ssum;

    int grp = tid >> 6, d = tid & 63;
    float acc0 = 0.f, acc1 = 0.f;
    for (int j = grp; j < SS; j += 8) {
        acc0 += sc[j] * gvb[(size_t)j * DHH + d];
        acc1 += sc[j + 4] * gvb[(size_t)(j + 4) * DHH + d];
    }
    redv[grp][d] = acc0 + acc1;
    __syncthreads();
    if (grp == 0) {
        float o = (redv[0][d] + redv[1][d] + redv[2][d] + redv[3][d]) * inv;
        attn[((size_t)b*SS + g)*EE + h*DHH + d] = o;
    }
}

// ---------------- fused add + LayerNorm ----------------
__global__ __launch_bounds__(256) void add_ln_kernel(
    const float* __restrict__ a, const float* __restrict__ c,
    const float* __restrict__ gamma, const float* __restrict__ beta,
    float* __restrict__ out)
{
    int row = blockIdx.x;
    int tid = threadIdx.x;
    __shared__ float buf[EE];
    __shared__ float red[8];

    float local = 0.f;
#pragma unroll
    for (int i = 0; i < 3; i++) {
        int idx = tid + i*256;
        float v = a[(size_t)row*EE + idx] + c[(size_t)row*EE + idx];
        buf[idx] = v;
        local += v;
    }
#pragma unroll
    for (int o = 16; o; o >>= 1) local += __shfl_xor_sync(0xffffffffu, local, o);
    if ((tid & 31) == 0) red[tid >> 5] = local;
    __syncthreads();
    float s = 0.f;
#pragma unroll
    for (int w = 0; w < 8; w++) s += red[w];
    float mean = s * (1.f/768.f);

    float lv = 0.f;
#pragma unroll
    for (int i = 0; i < 3; i++) {
        float dd = buf[tid + i*256] - mean;
        lv += dd*dd;
    }
#pragma unroll
    for (int o = 16; o; o >>= 1) lv += __shfl_xor_sync(0xffffffffu, lv, o);
    __syncthreads();
    if ((tid & 31) == 0) red[tid >> 5] = lv;
    __syncthreads();
    float vs = 0.f;
#pragma unroll
    for (int w = 0; w < 8; w++) vs += red[w];
    float invstd = rsqrtf(vs * (1.f/768.f) + 1e-5f);

#pragma unroll
    for (int i = 0; i < 3; i++) {
        int idx = tid + i*256;
        out[(size_t)row*EE + idx] = (buf[idx] - mean) * invstd * gamma[idx] + beta[idx];
    }
}

// ---------------- SiLU(t1) * t2 -> t1 (vectorized) ----------------
__global__ void silu_mul_kernel(float4* __restrict__ t1, const float4* __restrict__ t2, int n4) {
    int i = blockIdx.x * blockDim.x + threadIdx.x;
    if (i < n4) {
        float4 a = t1[i], b = t2[i];
        a.x = a.x / (1.f + __expf(-a.x)) * b.x;
        a.y = a.y / (1.f + __expf(-a.y)) * b.y;
        a.z = a.z / (1.f + __expf(-a.z)) * b.z;
        a.w = a.w / (1.f + __expf(-a.w)) * b.w;
        t1[i] = a;
    }
}

// ---------------- launch ----------------
extern "C" void kernel_launch(void* const* d_in, const int* in_sizes, int n_in,
                              void* d_out, int out_size) {
    (void)in_sizes; (void)n_in; (void)out_size;
    const float* x    = (const float*)d_in[0];
    const int*   am   = (const int*)d_in[1];
    const int*   gm   = (const int*)d_in[2];
    const float* Wq   = (const float*)d_in[3];  const float* bq  = (const float*)d_in[4];
    const float* Wk   = (const float*)d_in[5];  const float* bk  = (const float*)d_in[6];
    const float* Wv   = (const float*)d_in[7];  const float* bv  = (const float*)d_in[8];
    const float* Wqg  = (const float*)d_in[9];  const float* bqg = (const float*)d_in[10];
    const float* Wkg  = (const float*)d_in[11]; const float* bkg = (const float*)d_in[12];
    const float* Wvg  = (const float*)d_in[13]; const float* bvg = (const float*)d_in[14];
    const float* ln0g = (const float*)d_in[15]; const float* ln0b = (const float*)d_in[16];
    const float* ln1g = (const float*)d_in[17]; const float* ln1b = (const float*)d_in[18];
    const float* W1   = (const float*)d_in[19];
    const float* W3   = (const float*)d_in[20];
    const float* W2   = (const float*)d_in[21];
    float* out = (float*)d_out;

    float *qp, *kp, *vp, *gqp, *gkp, *gvp, *attnp, *h0p, *t1p, *t2p, *tbp;
    cudaGetSymbolAddress((void**)&qp,  g_q);
    cudaGetSymbolAddress((void**)&kp,  g_k);
    cudaGetSymbolAddress((void**)&vp,  g_v);
    cudaGetSymbolAddress((void**)&gqp, g_gq);
    cudaGetSymbolAddress((void**)&gkp, g_gk);
    cudaGetSymbolAddress((void**)&gvp, g_gv);
    cudaGetSymbolAddress((void**)&attnp, g_attn);
    cudaGetSymbolAddress((void**)&h0p, g_h0);
    cudaGetSymbolAddress((void**)&t1p, g_t1);
    cudaGetSymbolAddress((void**)&t2p, g_t2);
    cudaGetSymbolAddress((void**)&tbp, g_tbuf);

    cudaFuncSetAttribute(band_attn_kernel,
                         cudaFuncAttributeMaxDynamicSharedMemorySize, BAND_SMEM);
    cudaFuncSetAttribute(tf32gemm_kernel,
                         cudaFuncAttributeMaxDynamicSharedMemorySize, GEMM_SMEM);

    mask_cumsum_kernel<<<BB, 256>>>(am, gm, tbp);

    GemmArgs pa = {};
    pa.A = x; pa.N = EE; pa.K = EE; pa.epi = 1;
    pa.Wm[0] = Wq;  pa.bias[0] = bq;  pa.out[0] = qp;  pa.scale[0] = 0.125f;
    pa.Wm[1] = Wk;  pa.bias[1] = bk;  pa.out[1] = kp;  pa.scale[1] = 1.f;
    pa.Wm[2] = Wv;  pa.bias[2] = bv;  pa.out[2] = vp;  pa.scale[2] = 1.f;
    pa.Wm[3] = Wqg; pa.bias[3] = bqg; pa.out[3] = gqp; pa.scale[3] = 0.125f;
    pa.Wm[4] = Wkg; pa.bias[4] = bkg; pa.out[4] = gkp; pa.scale[4] = 1.f;
    pa.Wm[5] = Wvg; pa.bias[5] = bvg; pa.out[5] = gvp; pa.scale[5] = 1.f;
    tf32gemm_kernel<<<dim3(32, 6, 6), 128, GEMM_SMEM>>>(pa);

    rope_kernel<<<(BB*HH*SS*32 + 255)/256, 256>>>(qp, kp, tbp);

    band_attn_kernel<<<dim3(SS/16, HH, BB), 256, BAND_SMEM>>>(qp, kp, vp, am, gm, attnp);
    global_attn_kernel<<<dim3(GG, HH, BB), 256>>>(gqp, gkp, gvp, am, gm, attnp);

    add_ln_kernel<<<BB*SS, 256>>>(x, attnp, ln0g, ln0b, h0p);

    GemmArgs f1 = {};
    f1.A = h0p; f1.N = FFD; f1.K = EE; f1.epi = 0;
    f1.Wm[0] = W1; f1.bias[0] = nullptr; f1.out[0] = t1p; f1.scale[0] = 1.f;
    f1.Wm[1] = W3; f1.bias[1] = nullptr; f1.out[1] = t2p; f1.scale[1] = 1.f;
    tf32gemm_kernel<<<dim3(32, 24, 2), 128, GEMM_SMEM>>>(f1);

    silu_mul_kernel<<<(NFF/4 + 255)/256, 256>>>((float4*)t1p, (const float4*)t2p, NFF/4);

    GemmArgs f2 = {};
    f2.A = t1p; f2.N = EE; f2.K = FFD; f2.epi = 0;
    f2.Wm[0] = W2; f2.bias[0] = nullptr; f2.out[0] = attnp; f2.scale[0] = 1.f;
    tf32gemm_kernel<<<dim3(32, 6, 1), 128, GEMM_SMEM>>>(f2);

    add_ln_kernel<<<BB*SS, 256>>>(h0p, attnp, ln1g, ln1b, out);
}

// round 15
// speedup vs baseline: 3.6365x; 1.0774x over previous
#include <cuda_runtime.h>
#include <cuda_bf16.h>
#include <math.h>

#define BB 2
#define SS 2048
#define EE 768
#define HH 12
#define DHH 64
#define WW 256
#define GG 16
#define FFD 3072
#define NEGV (-1e9f)

#define NQKV (BB*HH*SS*DHH)
#define NXE  (BB*SS*EE)
#define NFF  (BB*SS*FFD)

// ---------------- device scratch ----------------
__device__ float g_q[NQKV];
__device__ float g_k[NQKV];
__device__ float g_v[NQKV];
__device__ float g_gq[NQKV];
__device__ float g_gk[NQKV];
__device__ float g_gv[NQKV];
__device__ float g_attn[NXE];
__device__ float g_h0[NXE];
__device__ float g_t1[NFF];
__device__ float g_t2[NFF];
__device__ float g_tbuf[BB*SS];

// ---------------- mma / cp.async helpers ----------------
__device__ __forceinline__ void mma_tf32(float (&d)[4], const unsigned* a, const unsigned* b) {
    asm volatile(
        "mma.sync.aligned.m16n8k8.row.col.f32.tf32.tf32.f32 "
        "{%0,%1,%2,%3}, {%4,%5,%6,%7}, {%8,%9}, {%0,%1,%2,%3};\n"
        : "+f"(d[0]), "+f"(d[1]), "+f"(d[2]), "+f"(d[3])
        : "r"(a[0]), "r"(a[1]), "r"(a[2]), "r"(a[3]), "r"(b[0]), "r"(b[1]));
}
__device__ __forceinline__ void cpasync16(unsigned dst, const void* src) {
    asm volatile("cp.async.cg.shared.global [%0], [%1], 16;\n" :: "r"(dst), "l"(src));
}
__device__ __forceinline__ void cpasync16z(unsigned dst, const void* src, unsigned ssz) {
    asm volatile("cp.async.cg.shared.global [%0], [%1], 16, %2;\n" :: "r"(dst), "l"(src), "r"(ssz));
}
__device__ __forceinline__ void cp_commit() {
    asm volatile("cp.async.commit_group;\n");
}
template <int N> __device__ __forceinline__ void cp_wait() {
    asm volatile("cp.async.wait_group %0;\n" :: "n"(N));
}
__device__ __forceinline__ float tfr(float x) {
    unsigned r; asm("cvt.rna.tf32.f32 %0, %1;" : "=r"(r) : "f"(x));
    return __uint_as_float(r);
}
__device__ __forceinline__ unsigned s2u(const void* p) {
    return (unsigned)__cvta_generic_to_shared(p);
}

// ---------------- parallel cumsum of global flags -> t ----------------
__global__ __launch_bounds__(256) void mask_cumsum_kernel(const int* __restrict__ am,
                                                          const int* __restrict__ gm,
                                                          float* __restrict__ tb) {
    int b = blockIdx.x;
    int tid = threadIdx.x;
    int lane = tid & 31, warp = tid >> 5;
    __shared__ int flg[SS];
    __shared__ int wsum[8];
    for (int i = tid; i < SS; i += 256)
        flg[i] = am[b*SS + i] * (gm[b*SS + i] + 1);
    __syncthreads();
    int base = tid << 3;
    int loc[8];
    int s = 0;
#pragma unroll
    for (int j = 0; j < 8; j++) { loc[j] = s; s += (flg[base + j] == 2); }
    int inc = s;
#pragma unroll
    for (int o = 1; o < 32; o <<= 1) {
        int v = __shfl_up_sync(0xffffffffu, inc, o);
        if (lane >= o) inc += v;
    }
    if (lane == 31) wsum[warp] = inc;
    __syncthreads();
    int woff = 0;
#pragma unroll
    for (int w = 0; w < 8; w++) if (w < warp) woff += wsum[w];
    int excl = woff + inc - s;
#pragma unroll
    for (int j = 0; j < 8; j++) {
        int idx = base + j;
        int m = flg[idx];
        int c = excl + loc[j] + (m == 2);
        tb[b*SS + idx] = (m == 0) ? 0.f : (float)c;
    }
}

// ---------------- tf32 GEMM: 3-stage pipeline, single barrier per k-tile ----------------
struct GemmArgs {
    const float* A;
    const float* Wm[6];
    const float* bias[6];
    float* out[6];
    float scale[6];
    int N, K, epi;
};

#define APAD 20
#define BPAD 136
#define GEMM_SMEM ((3*128*APAD + 3*16*BPAD) * 4)

__global__ __launch_bounds__(128, 2) void tf32gemm_kernel(GemmArgs g) {
    extern __shared__ float gsm[];
    float* Ab = gsm;
    float* Bb = gsm + 3*128*APAD;

    const int z = blockIdx.z;
    const float* __restrict__ A = g.A;
    const float* __restrict__ W = g.Wm[z];
    const float* __restrict__ bias = g.bias[z];
    float* __restrict__ out = g.out[z];
    const int N = g.N, K = g.K;
    const int bm = blockIdx.x << 7, bn = blockIdx.y << 7;

    const int tid = threadIdx.x;
    const int lane = tid & 31, warp = tid >> 5;
    const int wm = (warp >> 1) << 6;
    const int wn = (warp & 1) << 6;
    const int gl = lane >> 2, qd = lane & 3;

    float acc[4][8][4];
#pragma unroll
    for (int i = 0; i < 4; i++)
#pragma unroll
        for (int j = 0; j < 8; j++)
#pragma unroll
            for (int r = 0; r < 4; r++) acc[i][j][r] = 0.f;

    const float* Agp0 = A + (size_t)(bm + (tid >> 2)) * K + ((tid & 3) << 2);
    const float* Wgp0 = W + (size_t)(tid >> 5) * N + bn + ((tid & 31) << 2);
    const size_t AgS = (size_t)32 * K;
    const size_t WgS = (size_t)4 * N;
    const unsigned sAb = s2u(Ab + (tid >> 2)*APAD + ((tid & 3) << 2));
    const unsigned sBb = s2u(Bb + (tid >> 5)*BPAD + ((tid & 31) << 2));
    const unsigned ABUF = 128 * APAD * 4;
    const unsigned BBUF = 16 * BPAD * 4;
    const unsigned AT = 32 * APAD * 4;
    const unsigned BT = 4 * BPAD * 4;

    const int NIT = K >> 4;

#define G_STAGE(s, k0) do {                                                   \
        _Pragma("unroll")                                                     \
        for (int t = 0; t < 4; t++) {                                         \
            cpasync16(sAb + (s)*ABUF + t*AT, Agp0 + (k0) + (size_t)t*AgS);    \
            cpasync16(sBb + (s)*BBUF + t*BT, Wgp0 + (size_t)(k0)*N + (size_t)t*WgS); \
        }                                                                     \
        cp_commit();                                                          \
    } while (0)

    G_STAGE(0, 0);
    if (NIT > 1) G_STAGE(1, 16);
    int cur = 0;

    for (int it = 0; it < NIT; it++) {
        if (it + 1 < NIT) cp_wait<1>(); else cp_wait<0>();
        __syncthreads();

        const float* Ac = Ab + cur*128*APAD;
        const float* Bc = Bb + cur*16*BPAD;
#pragma unroll
        for (int kt = 0; kt < 2; kt++) {
            const int k0 = kt << 3;
            unsigned afr[4][4], bfr[8][2];
#pragma unroll
            for (int mtl = 0; mtl < 4; mtl++) {
                int m = wm + (mtl << 4);
                afr[mtl][0] = __float_as_uint(Ac[(m + gl    )*APAD + k0 + qd    ]);
                afr[mtl][1] = __float_as_uint(Ac[(m + gl + 8)*APAD + k0 + qd    ]);
                afr[mtl][2] = __float_as_uint(Ac[(m + gl    )*APAD + k0 + qd + 4]);
                afr[mtl][3] = __float_as_uint(Ac[(m + gl + 8)*APAD + k0 + qd + 4]);
            }
#pragma unroll
            for (int ntl = 0; ntl < 8; ntl++) {
                int n = wn + (ntl << 3) + gl;
                bfr[ntl][0] = __float_as_uint(Bc[(k0 + qd    )*BPAD + n]);
                bfr[ntl][1] = __float_as_uint(Bc[(k0 + qd + 4)*BPAD + n]);
            }
#pragma unroll
            for (int mtl = 0; mtl < 4; mtl++)
#pragma unroll
                for (int ntl = 0; ntl < 8; ntl++)
                    mma_tf32(acc[mtl][ntl], afr[mtl], bfr[ntl]);
        }
        if (it + 2 < NIT) {
            int nx2 = cur + 2; if (nx2 >= 3) nx2 -= 3;
            G_STAGE(nx2, (it + 2) << 4);
        }
        cur = (cur == 2) ? 0 : cur + 1;
    }
#undef G_STAGE

    const float sc = g.scale[z];
#pragma unroll
    for (int mtl = 0; mtl < 4; mtl++) {
        int row0 = bm + wm + (mtl << 4) + gl;
#pragma unroll
        for (int ntl = 0; ntl < 8; ntl++) {
            int col = bn + wn + (ntl << 3) + (qd << 1);
            float v0 = acc[mtl][ntl][0], v1 = acc[mtl][ntl][1];
            float v2 = acc[mtl][ntl][2], v3 = acc[mtl][ntl][3];
            if (bias) {
                float b0 = bias[col], b1 = bias[col + 1];
                v0 += b0; v1 += b1; v2 += b0; v3 += b1;
            }
            v0 *= sc; v1 *= sc; v2 *= sc; v3 *= sc;
            if (g.epi == 0) {
                *(float2*)(out + (size_t)row0 * N + col)       = make_float2(v0, v1);
                *(float2*)(out + (size_t)(row0 + 8) * N + col) = make_float2(v2, v3);
            } else {
                int h = col >> 6, d = col & 63;
                int b0i = row0 >> 11, s0 = row0 & (SS - 1);
                int row1 = row0 + 8;
                int b1i = row1 >> 11, s1 = row1 & (SS - 1);
                *(float2*)(out + (((size_t)(b0i*HH + h) * SS + s0) << 6) + d) = make_float2(v0, v1);
                *(float2*)(out + (((size_t)(b1i*HH + h) * SS + s1) << 6) + d) = make_float2(v2, v3);
            }
        }
    }
}

// ---------------- RoPE on q and k (in-place) ----------------
__global__ void rope_kernel(float* __restrict__ q, float* __restrict__ k,
                            const float* __restrict__ tb) {
    int idx = blockIdx.x * blockDim.x + threadIdx.x;
    const int total = BB*HH*SS*32;
    if (idx >= total) return;
    int d   = idx & 31;
    int rem = idx >> 5;
    int s   = rem & (SS-1);
    int rem2 = rem >> 11;
    int h   = rem2 % HH;
    int b   = rem2 / HH;
    float tt = tb[b*SS + s];
    float inv_freq = expf(-(float)d * 0.28782313662425574f);
    float sn, cs;
    sincosf(tt * inv_freq, &sn, &cs);
    size_t off = (((size_t)(b*HH + h) * SS + s) << 6) + d;
    float x1 = q[off], x2 = q[off + 32];
    q[off]      = x1*cs - x2*sn;
    q[off + 32] = x2*cs + x1*sn;
    x1 = k[off]; x2 = k[off + 32];
    k[off]      = x1*cs - x2*sn;
    k[off + 32] = x2*cs + x1*sn;
}

// ---------------- banded + global-key attention ----------------
// jrel-indexed prob layout: pb[16][548] (548 % 32 == 4 -> conflict-free frag loads),
// globals in pg[16][20]. Ring row stride 76 (76 % 32 == 12 -> conflict-free B frags).
// Single barrier per round: wait -> sync -> compute -> stage(r+2).
#define PBW 548
#define PGW 20
#define KST 76
#define CHB (32*KST)            /* 2432 floats per chunk */
#define RNGB (2*CHB)            /* 4864 floats per ring slot */
#define BAND_SMEM ((1088 + 16*PGW + 16*PBW + 3*RNGB + 16*KST + 16) * 4 + 544 * 4)

__global__ __launch_bounds__(256) void band_attn_kernel(
    const float* __restrict__ q, const float* __restrict__ k, const float* __restrict__ v,
    const int* __restrict__ am, const int* __restrict__ gm,
    float* __restrict__ attn)
{
    extern __shared__ float sm[];
    float* qs  = sm;                        // [16][68]
    float* pg  = sm + 1088;                 // [16][20] global scores/probs
    float* pb  = pg + 16*PGW;               // [16][548] band scores/probs by jrel
    float* ks  = pb + 16*PBW;               // ring [3][2][32][76]
    float* gvs = ks + 3*RNGB;               // [16][76] global K then global V
    float* scl = gvs + 16*KST;              // [16]
    int*   rmv = (int*)(scl + 16);          // [544]

    const int b = blockIdx.z, h = blockIdx.y, base = blockIdx.x << 4;
    const int tid = threadIdx.x;
    const int lane = tid & 31, warp = tid >> 5;
    const int gl = lane >> 2, qd = lane & 3;

    const float* qb = q + ((size_t)(b*HH + h) * SS) * DHH;
    const float* kb = k + ((size_t)(b*HH + h) * SS) * DHH;
    const float* vb = v + ((size_t)(b*HH + h) * SS) * DHH;

    const int jmin = base - WW;

    auto stage_round = [&](const float* src, int r) {
        int nch = (r < 8) ? 2 : 1;
        float* dst = ks + (r % 3) * RNGB;
        for (int i = tid; i < (nch << 9); i += 256) {
            int cidx = i >> 9, rem = i & 511;
            int kk = rem >> 4, d4 = rem & 15;
            int j = jmin + (r << 6) + (cidx << 5) + kk;
            bool valid = (j >= 0 && j < SS);
            cpasync16z(s2u(dst + cidx*CHB + kk*KST + (d4 << 2)),
                       src + (((size_t)(valid ? j : 0)) << 6) + (d4 << 2),
                       valid ? 16u : 0u);
        }
        cp_commit();
    };

    // ---- prologue: q + global K, rounds 0,1 in flight; rmv precompute ----
    {
        int row = tid >> 4, d4 = tid & 15;
        cpasync16(s2u(qs + row*68 + (d4 << 2)), qb + (((size_t)(base + row)) << 6) + (d4 << 2));
        cpasync16(s2u(gvs + row*KST + (d4 << 2)), kb + (((size_t)row) << 6) + (d4 << 2));
        cp_commit();
    }
    stage_round(kb, 0);
    stage_round(kb, 1);
    for (int i = tid; i < 544; i += 256) {
        int j = jmin + i;
        int rm = 1;
        if (j >= 0 && j < SS) { int m = am[b*SS + j] * (gm[b*SS + j] + 1); rm = (m != 1); }
        rmv[i] = rm;
    }
    cp_wait<1>();           // q/gK + round0 done
    __syncthreads();

    // per-warp Q fragments
    unsigned aq[8][4];
#pragma unroll
    for (int k8 = 0; k8 < 8; k8++) {
        int k0 = k8 << 3;
        aq[k8][0] = __float_as_uint(qs[gl*68     + k0 + qd    ]);
        aq[k8][1] = __float_as_uint(qs[(gl+8)*68 + k0 + qd    ]);
        aq[k8][2] = __float_as_uint(qs[gl*68     + k0 + qd + 4]);
        aq[k8][3] = __float_as_uint(qs[(gl+8)*68 + k0 + qd + 4]);
    }

    // global-key scores (warps 0,1) -> pg
    if (warp < 2) {
        float acc[4] = {0.f, 0.f, 0.f, 0.f};
        unsigned bfr[2];
#pragma unroll
        for (int k8 = 0; k8 < 8; k8++) {
            int k0 = k8 << 3;
            bfr[0] = __float_as_uint(gvs[(warp*8 + gl)*KST + k0 + qd    ]);
            bfr[1] = __float_as_uint(gvs[(warp*8 + gl)*KST + k0 + qd + 4]);
            mma_tf32(acc, aq[k8], bfr);
        }
        int key = warp*8 + (qd << 1);
        *(float2*)&pg[gl*PGW     + key] = make_float2(acc[0], acc[1]);
        *(float2*)&pg[(gl+8)*PGW + key] = make_float2(acc[2], acc[3]);
    }

    // ---- score rounds 0..8: wait -> sync -> compute -> stage ----
    for (int r = 0; r < 9; r++) {
        if (r + 1 <= 8) cp_wait<1>(); else cp_wait<0>();
        __syncthreads();

        int cidx = warp >> 2;
        int cglob = (r << 1) + cidx;
        if (cglob <= 16) {
            const float* kc = ks + (r % 3)*RNGB + cidx*CHB;
            int ntile = warp & 3;
            float acc[4] = {0.f, 0.f, 0.f, 0.f};
            unsigned bfr[2];
#pragma unroll
            for (int k8 = 0; k8 < 8; k8++) {
                int k0 = k8 << 3;
                bfr[0] = __float_as_uint(kc[(ntile*8 + gl)*KST + k0 + qd    ]);
                bfr[1] = __float_as_uint(kc[(ntile*8 + gl)*KST + k0 + qd + 4]);
                mma_tf32(acc, aq[k8], bfr);
            }
            int c = (cglob << 5) + (ntile << 3) + (qd << 1);   // jrel column
            int r0 = rmv[c], r1 = rmv[c + 1];
            float v0 = r0 ? NEGV : acc[0];
            float v1 = r1 ? NEGV : acc[1];
            float v2 = r0 ? NEGV : acc[2];
            float v3 = r1 ? NEGV : acc[3];
            *(float2*)&pb[gl*PBW     + c] = make_float2(v0, v1);
            *(float2*)&pb[(gl+8)*PBW + c] = make_float2(v2, v3);
        }
        if (r + 2 <= 8) stage_round(kb, r + 2);
    }
    __syncthreads();   // pb/pg complete before softmax

    // ---- prefetch global V + AV rounds 0,1 (overlap with softmax) ----
    {
        int row = tid >> 4, d4 = tid & 15;
        cpasync16(s2u(gvs + row*KST + (d4 << 2)), vb + (((size_t)row) << 6) + (d4 << 2));
        cp_commit();
    }
    stage_round(vb, 0);
    stage_round(vb, 1);

    // ---- softmax: row p over pg[p][0..15] and pb[p][p+l], l in [0,512] ----
    {
        const int p = tid >> 4, r = tid & 15;
        float mx = pg[p*PGW + r];
        for (int l = r; l <= 512; l += 16) mx = fmaxf(mx, pb[p*PBW + p + l]);
#pragma unroll
        for (int o = 8; o; o >>= 1) mx = fmaxf(mx, __shfl_xor_sync(0xffffffffu, mx, o, 16));
        float gv0 = __expf(pg[p*PGW + r] - mx);
        pg[p*PGW + r] = tfr(gv0);
        float sum = gv0;
        for (int l = r; l <= 512; l += 16) {
            float e = __expf(pb[p*PBW + p + l] - mx);
            pb[p*PBW + p + l] = tfr(e);
            sum += e;
        }
#pragma unroll
        for (int o = 8; o; o >>= 1) sum += __shfl_xor_sync(0xffffffffu, sum, o, 16);
        if (r == 0) {
            int iq = base + p;
            int mm = am[b*SS + iq] * (gm[b*SS + iq] + 1);
            scl[p] = (mm == 0) ? 0.f : (1.f / sum);
        }
    }
    // zero invalid cells: row p, jrel in [0,p) U (p+512, 543]  (31 per row)
    for (int i = tid; i < 496; i += 256) {
        int p = i / 31, o = i % 31;
        int jr = (o < p) ? o : (513 + o);
        pb[p*PBW + jr] = 0.f;
    }
    cp_wait<1>();           // global V + AV round0 done
    __syncthreads();

    float av[4] = {0.f, 0.f, 0.f, 0.f};
    const int nd = (warp << 3) + gl;
    {   // global-V contribution (probs from pg)
        unsigned afr[4], bfr[2];
#pragma unroll
        for (int k8 = 0; k8 < 2; k8++) {
            int k0 = k8 << 3;
            afr[0] = __float_as_uint(pg[gl*PGW     + k0 + qd    ]);
            afr[1] = __float_as_uint(pg[(gl+8)*PGW + k0 + qd    ]);
            afr[2] = __float_as_uint(pg[gl*PGW     + k0 + qd + 4]);
            afr[3] = __float_as_uint(pg[(gl+8)*PGW + k0 + qd + 4]);
            bfr[0] = __float_as_uint(gvs[(k0 + qd    )*KST + nd]);
            bfr[1] = __float_as_uint(gvs[(k0 + qd + 4)*KST + nd]);
            mma_tf32(av, afr, bfr);
        }
    }

    // ---- AV rounds 0..8: wait -> sync -> compute -> stage ----
    for (int r = 0; r < 9; r++) {
        if (r + 1 <= 8) cp_wait<1>(); else cp_wait<0>();
        __syncthreads();
        int nch = (r < 8) ? 2 : 1;
        const float* vbuf = ks + (r % 3)*RNGB;
        for (int cidx = 0; cidx < nch; cidx++) {
            int cb = ((r << 1) + cidx) << 5;
            const float* vc = vbuf + cidx*CHB;
            unsigned afr[4], bfr[2];
#pragma unroll
            for (int k8 = 0; k8 < 4; k8++) {
                int kA = (k8 << 3) + qd;
                int col = cb + kA;          // jrel; invalid cells are exact 0
                afr[0] = __float_as_uint(pb[gl*PBW     + col    ]);
                afr[1] = __float_as_uint(pb[(gl+8)*PBW + col    ]);
                afr[2] = __float_as_uint(pb[gl*PBW     + col + 4]);
                afr[3] = __float_as_uint(pb[(gl+8)*PBW + col + 4]);
                bfr[0] = __float_as_uint(vc[kA*KST       + nd]);
                bfr[1] = __float_as_uint(vc[(kA + 4)*KST + nd]);
                mma_tf32(av, afr, bfr);
            }
        }
        if (r + 2 <= 8) stage_round(vb, r + 2);
    }

    {
        float s0 = scl[gl], s1 = scl[gl + 8];
        int d = (warp << 3) + (qd << 1);
        int iq0 = base + gl, iq1 = base + gl + 8;
        *(float2*)(attn + ((size_t)b*SS + iq0)*EE + h*DHH + d) = make_float2(av[0]*s0, av[1]*s0);
        *(float2*)(attn + ((size_t)b*SS + iq1)*EE + h*DHH + d) = make_float2(av[2]*s1, av[3]*s1);
    }
}

// ---------------- global attention (overwrites attn rows < G) ----------------
__global__ __launch_bounds__(256) void global_attn_kernel(
    const float* __restrict__ gq, const float* __restrict__ gk, const float* __restrict__ gv,
    const int* __restrict__ am, const int* __restrict__ gm,
    float* __restrict__ attn)
{
    int g = blockIdx.x, h = blockIdx.y, b = blockIdx.z;
    int tid = threadIdx.x;
    __shared__ float sc[SS];
    __shared__ float qrow[64];
    __shared__ float red[8];
    __shared__ float redv[4][64];

    const float* gkb = gk + ((size_t)(b*HH + h) * SS) * DHH;
    const float* gvb = gv + ((size_t)(b*HH + h) * SS) * DHH;
    if (tid < 64) qrow[tid] = gq[(((size_t)(b*HH + h) * SS + g) << 6) + tid];
    __syncthreads();

    float lmax = -3.4e38f;
    for (int j = tid; j < SS; j += 256) {
        int m = am[b*SS + j] * (gm[b*SS + j] + 1);
        float s;
        if (m == 0) s = NEGV;
        else {
            float a0=0.f,a1=0.f,a2=0.f,a3=0.f;
            const float4* kp = (const float4*)(gkb + (size_t)j * DHH);
            const float4* qp = (const float4*)qrow;
#pragma unroll
            for (int d4 = 0; d4 < 16; d4++) {
                float4 a = qp[d4], bb = kp[d4];
                a0 += a.x*bb.x; a1 += a.y*bb.y; a2 += a.z*bb.z; a3 += a.w*bb.w;
            }
            s = (a0 + a1) + (a2 + a3);
        }
        sc[j] = s;
        lmax = fmaxf(lmax, s);
    }
#pragma unroll
    for (int o = 16; o; o >>= 1) lmax = fmaxf(lmax, __shfl_xor_sync(0xffffffffu, lmax, o));
    if ((tid & 31) == 0) red[tid >> 5] = lmax;
    __syncthreads();
    float bmax = red[0];
#pragma unroll
    for (int w = 1; w < 8; w++) bmax = fmaxf(bmax, red[w]);

    float lsum = 0.f;
    for (int j = tid; j < SS; j += 256) {
        float e = __expf(sc[j] - bmax);
        sc[j] = e;
        lsum += e;
    }
#pragma unroll
    for (int o = 16; o; o >>= 1) lsum += __shfl_xor_sync(0xffffffffu, lsum, o);
    __syncthreads();
    if ((tid & 31) == 0) red[tid >> 5] = lsum;
    __syncthreads();
    float ssum = 0.f;
#pragma unroll
    for (int w = 0; w < 8; w++) ssum += red[w];
    float inv = 1.f / ssum;

    int grp = tid >> 6, d = tid & 63;
    float acc0 = 0.f, acc1 = 0.f;
    for (int j = grp; j < SS; j += 8) {
        acc0 += sc[j] * gvb[(size_t)j * DHH + d];
        acc1 += sc[j + 4] * gvb[(size_t)(j + 4) * DHH + d];
    }
    redv[grp][d] = acc0 + acc1;
    __syncthreads();
    if (grp == 0) {
        float o = (redv[0][d] + redv[1][d] + redv[2][d] + redv[3][d]) * inv;
        attn[((size_t)b*SS + g)*EE + h*DHH + d] = o;
    }
}

// ---------------- fused add + LayerNorm ----------------
__global__ __launch_bounds__(256) void add_ln_kernel(
    const float* __restrict__ a, const float* __restrict__ c,
    const float* __restrict__ gamma, const float* __restrict__ beta,
    float* __restrict__ out)
{
    int row = blockIdx.x;
    int tid = threadIdx.x;
    __shared__ float buf[EE];
    __shared__ float red[8];

    float local = 0.f;
#pragma unroll
    for (int i = 0; i < 3; i++) {
        int idx = tid + i*256;
        float v = a[(size_t)row*EE + idx] + c[(size_t)row*EE + idx];
        buf[idx] = v;
        local += v;
    }
#pragma unroll
    for (int o = 16; o; o >>= 1) local += __shfl_xor_sync(0xffffffffu, local, o);
    if ((tid & 31) == 0) red[tid >> 5] = local;
    __syncthreads();
    float s = 0.f;
#pragma unroll
    for (int w = 0; w < 8; w++) s += red[w];
    float mean = s * (1.f/768.f);

    float lv = 0.f;
#pragma unroll
    for (int i = 0; i < 3; i++) {
        float dd = buf[tid + i*256] - mean;
        lv += dd*dd;
    }
#pragma unroll
    for (int o = 16; o; o >>= 1) lv += __shfl_xor_sync(0xffffffffu, lv, o);
    __syncthreads();
    if ((tid & 31) == 0) red[tid >> 5] = lv;
    __syncthreads();
    float vs = 0.f;
#pragma unroll
    for (int w = 0; w < 8; w++) vs += red[w];
    float invstd = rsqrtf(vs * (1.f/768.f) + 1e-5f);

#pragma unroll
    for (int i = 0; i < 3; i++) {
        int idx = tid + i*256;
        out[(size_t)row*EE + idx] = (buf[idx] - mean) * invstd * gamma[idx] + beta[idx];
    }
}

// ---------------- SiLU(t1) * t2 -> t1 (vectorized) ----------------
__global__ void silu_mul_kernel(float4* __restrict__ t1, const float4* __restrict__ t2, int n4) {
    int i = blockIdx.x * blockDim.x + threadIdx.x;
    if (i < n4) {
        float4 a = t1[i], b = t2[i];
        a.x = a.x / (1.f + __expf(-a.x)) * b.x;
        a.y = a.y / (1.f + __expf(-a.y)) * b.y;
        a.z = a.z / (1.f + __expf(-a.z)) * b.z;
        a.w = a.w / (1.f + __expf(-a.w)) * b.w;
        t1[i] = a;
    }
}

// ---------------- launch ----------------
extern "C" void kernel_launch(void* const* d_in, const int* in_sizes, int n_in,
                              void* d_out, int out_size) {
    (void)in_sizes; (void)n_in; (void)out_size;
    const float* x    = (const float*)d_in[0];
    const int*   am   = (const int*)d_in[1];
    const int*   gm   = (const int*)d_in[2];
    const float* Wq   = (const float*)d_in[3];  const float* bq  = (const float*)d_in[4];
    const float* Wk   = (const float*)d_in[5];  const float* bk  = (const float*)d_in[6];
    const float* Wv   = (const float*)d_in[7];  const float* bv  = (const float*)d_in[8];
    const float* Wqg  = (const float*)d_in[9];  const float* bqg = (const float*)d_in[10];
    const float* Wkg  = (const float*)d_in[11]; const float* bkg = (const float*)d_in[12];
    const float* Wvg  = (const float*)d_in[13]; const float* bvg = (const float*)d_in[14];
    const float* ln0g = (const float*)d_in[15]; const float* ln0b = (const float*)d_in[16];
    const float* ln1g = (const float*)d_in[17]; const float* ln1b = (const float*)d_in[18];
    const float* W1   = (const float*)d_in[19];
    const float* W3   = (const float*)d_in[20];
    const float* W2   = (const float*)d_in[21];
    float* out = (float*)d_out;

    float *qp, *kp, *vp, *gqp, *gkp, *gvp, *attnp, *h0p, *t1p, *t2p, *tbp;
    cudaGetSymbolAddress((void**)&qp,  g_q);
    cudaGetSymbolAddress((void**)&kp,  g_k);
    cudaGetSymbolAddress((void**)&vp,  g_v);
    cudaGetSymbolAddress((void**)&gqp, g_gq);
    cudaGetSymbolAddress((void**)&gkp, g_gk);
    cudaGetSymbolAddress((void**)&gvp, g_gv);
    cudaGetSymbolAddress((void**)&attnp, g_attn);
    cudaGetSymbolAddress((void**)&h0p, g_h0);
    cudaGetSymbolAddress((void**)&t1p, g_t1);
    cudaGetSymbolAddress((void**)&t2p, g_t2);
    cudaGetSymbolAddress((void**)&tbp, g_tbuf);

    cudaFuncSetAttribute(band_attn_kernel,
                         cudaFuncAttributeMaxDynamicSharedMemorySize, BAND_SMEM);
    cudaFuncSetAttribute(tf32gemm_kernel,
                         cudaFuncAttributeMaxDynamicSharedMemorySize, GEMM_SMEM);

    mask_cumsum_kernel<<<BB, 256>>>(am, gm, tbp);

    GemmArgs pa = {};
    pa.A = x; pa.N = EE; pa.K = EE; pa.epi = 1;
    pa.Wm[0] = Wq;  pa.bias[0] = bq;  pa.out[0] = qp;  pa.scale[0] = 0.125f;
    pa.Wm[1] = Wk;  pa.bias[1] = bk;  pa.out[1] = kp;  pa.scale[1] = 1.f;
    pa.Wm[2] = Wv;  pa.bias[2] = bv;  pa.out[2] = vp;  pa.scale[2] = 1.f;
    pa.Wm[3] = Wqg; pa.bias[3] = bqg; pa.out[3] = gqp; pa.scale[3] = 0.125f;
    pa.Wm[4] = Wkg; pa.bias[4] = bkg; pa.out[4] = gkp; pa.scale[4] = 1.f;
    pa.Wm[5] = Wvg; pa.bias[5] = bvg; pa.out[5] = gvp; pa.scale[5] = 1.f;
    tf32gemm_kernel<<<dim3(32, 6, 6), 128, GEMM_SMEM>>>(pa);

    rope_kernel<<<(BB*HH*SS*32 + 255)/256, 256>>>(qp, kp, tbp);

    band_attn_kernel<<<dim3(SS/16, HH, BB), 256, BAND_SMEM>>>(qp, kp, vp, am, gm, attnp);
    global_attn_kernel<<<dim3(GG, HH, BB), 256>>>(gqp, gkp, gvp, am, gm, attnp);

    add_ln_kernel<<<BB*SS, 256>>>(x, attnp, ln0g, ln0b, h0p);

    GemmArgs f1 = {};
    f1.A = h0p; f1.N = FFD; f1.K = EE; f1.epi = 0;
    f1.Wm[0] = W1; f1.bias[0] = nullptr; f1.out[0] = t1p; f1.scale[0] = 1.f;
    f1.Wm[1] = W3; f1.bias[1] = nullptr; f1.out[1] = t2p; f1.scale[1] = 1.f;
    tf32gemm_kernel<<<dim3(32, 24, 2), 128, GEMM_SMEM>>>(f1);

    silu_mul_kernel<<<(NFF/4 + 255)/256, 256>>>((float4*)t1p, (const float4*)t2p, NFF/4);

    GemmArgs f2 = {};
    f2.A = t1p; f2.N = EE; f2.K = FFD; f2.epi = 0;
    f2.Wm[0] = W2; f2.bias[0] = nullptr; f2.out[0] = attnp; f2.scale[0] = 1.f;
    tf32gemm_kernel<<<dim3(32, 6, 1), 128, GEMM_SMEM>>>(f2);

    add_ln_kernel<<<BB*SS, 256>>>(h0p, attnp, ln1g, ln1b, out);
}

// round 16
// speedup vs baseline: 3.6479x; 1.0031x over previous
#include <cuda_runtime.h>
#include <cuda_bf16.h>
#include <math.h>

#define BB 2
#define SS 2048
#define EE 768
#define HH 12
#define DHH 64
#define WW 256
#define GG 16
#define FFD 3072
#define NEGV (-1e9f)

#define NQKV (BB*HH*SS*DHH)
#define NXE  (BB*SS*EE)
#define NFF  (BB*SS*FFD)

// ---------------- device scratch ----------------
__device__ float g_q[NQKV];
__device__ float g_k[NQKV];
__device__ float g_v[NQKV];
__device__ float g_gq[NQKV];
__device__ float g_gk[NQKV];
__device__ float g_gv[NQKV];
__device__ float g_attn[NXE];
__device__ float g_h0[NXE];
__device__ float g_t1[NFF];
__device__ float g_t2[NFF];
__device__ float g_tbuf[BB*SS];

// ---------------- mma / cp.async helpers ----------------
__device__ __forceinline__ void mma_tf32(float (&d)[4], const unsigned* a, const unsigned* b) {
    asm volatile(
        "mma.sync.aligned.m16n8k8.row.col.f32.tf32.tf32.f32 "
        "{%0,%1,%2,%3}, {%4,%5,%6,%7}, {%8,%9}, {%0,%1,%2,%3};\n"
        : "+f"(d[0]), "+f"(d[1]), "+f"(d[2]), "+f"(d[3])
        : "r"(a[0]), "r"(a[1]), "r"(a[2]), "r"(a[3]), "r"(b[0]), "r"(b[1]));
}
__device__ __forceinline__ void cpasync16(unsigned dst, const void* src) {
    asm volatile("cp.async.cg.shared.global [%0], [%1], 16;\n" :: "r"(dst), "l"(src));
}
__device__ __forceinline__ void cpasync16z(unsigned dst, const void* src, unsigned ssz) {
    asm volatile("cp.async.cg.shared.global [%0], [%1], 16, %2;\n" :: "r"(dst), "l"(src), "r"(ssz));
}
__device__ __forceinline__ void cp_commit() {
    asm volatile("cp.async.commit_group;\n");
}
template <int N> __device__ __forceinline__ void cp_wait() {
    asm volatile("cp.async.wait_group %0;\n" :: "n"(N));
}
__device__ __forceinline__ float tfr(float x) {
    unsigned r; asm("cvt.rna.tf32.f32 %0, %1;" : "=r"(r) : "f"(x));
    return __uint_as_float(r);
}
__device__ __forceinline__ unsigned s2u(const void* p) {
    return (unsigned)__cvta_generic_to_shared(p);
}

// ---------------- parallel cumsum of global flags -> t ----------------
__global__ __launch_bounds__(256) void mask_cumsum_kernel(const int* __restrict__ am,
                                                          const int* __restrict__ gm,
                                                          float* __restrict__ tb) {
    int b = blockIdx.x;
    int tid = threadIdx.x;
    int lane = tid & 31, warp = tid >> 5;
    __shared__ int flg[SS];
    __shared__ int wsum[8];
    for (int i = tid; i < SS; i += 256)
        flg[i] = am[b*SS + i] * (gm[b*SS + i] + 1);
    __syncthreads();
    int base = tid << 3;
    int loc[8];
    int s = 0;
#pragma unroll
    for (int j = 0; j < 8; j++) { loc[j] = s; s += (flg[base + j] == 2); }
    int inc = s;
#pragma unroll
    for (int o = 1; o < 32; o <<= 1) {
        int v = __shfl_up_sync(0xffffffffu, inc, o);
        if (lane >= o) inc += v;
    }
    if (lane == 31) wsum[warp] = inc;
    __syncthreads();
    int woff = 0;
#pragma unroll
    for (int w = 0; w < 8; w++) if (w < warp) woff += wsum[w];
    int excl = woff + inc - s;
#pragma unroll
    for (int j = 0; j < 8; j++) {
        int idx = base + j;
        int m = flg[idx];
        int c = excl + loc[j] + (m == 2);
        tb[b*SS + idx] = (m == 0) ? 0.f : (float)c;
    }
}

// ---------------- tf32 GEMM: 3-stage pipeline, single barrier per k-tile ----------------
struct GemmArgs {
    const float* A;
    const float* Wm[6];
    const float* bias[6];
    float* out[6];
    float scale[6];
    int N, K, epi;
};

#define APAD 20
#define BPAD 136
#define GEMM_SMEM ((3*128*APAD + 3*16*BPAD) * 4)

__global__ __launch_bounds__(128, 2) void tf32gemm_kernel(GemmArgs g) {
    extern __shared__ float gsm[];
    float* Ab = gsm;
    float* Bb = gsm + 3*128*APAD;

    const int z = blockIdx.z;
    const float* __restrict__ A = g.A;
    const float* __restrict__ W = g.Wm[z];
    const float* __restrict__ bias = g.bias[z];
    float* __restrict__ out = g.out[z];
    const int N = g.N, K = g.K;
    const int bm = blockIdx.x << 7, bn = blockIdx.y << 7;

    const int tid = threadIdx.x;
    const int lane = tid & 31, warp = tid >> 5;
    const int wm = (warp >> 1) << 6;
    const int wn = (warp & 1) << 6;
    const int gl = lane >> 2, qd = lane & 3;

    float acc[4][8][4];
#pragma unroll
    for (int i = 0; i < 4; i++)
#pragma unroll
        for (int j = 0; j < 8; j++)
#pragma unroll
            for (int r = 0; r < 4; r++) acc[i][j][r] = 0.f;

    const float* Agp0 = A + (size_t)(bm + (tid >> 2)) * K + ((tid & 3) << 2);
    const float* Wgp0 = W + (size_t)(tid >> 5) * N + bn + ((tid & 31) << 2);
    const size_t AgS = (size_t)32 * K;
    const size_t WgS = (size_t)4 * N;
    const unsigned sAb = s2u(Ab + (tid >> 2)*APAD + ((tid & 3) << 2));
    const unsigned sBb = s2u(Bb + (tid >> 5)*BPAD + ((tid & 31) << 2));
    const unsigned ABUF = 128 * APAD * 4;
    const unsigned BBUF = 16 * BPAD * 4;
    const unsigned AT = 32 * APAD * 4;
    const unsigned BT = 4 * BPAD * 4;

    const int NIT = K >> 4;

#define G_STAGE(s, k0) do {                                                   \
        _Pragma("unroll")                                                     \
        for (int t = 0; t < 4; t++) {                                         \
            cpasync16(sAb + (s)*ABUF + t*AT, Agp0 + (k0) + (size_t)t*AgS);    \
            cpasync16(sBb + (s)*BBUF + t*BT, Wgp0 + (size_t)(k0)*N + (size_t)t*WgS); \
        }                                                                     \
        cp_commit();                                                          \
    } while (0)

    G_STAGE(0, 0);
    if (NIT > 1) G_STAGE(1, 16);
    int cur = 0;

    for (int it = 0; it < NIT; it++) {
        if (it + 1 < NIT) cp_wait<1>(); else cp_wait<0>();
        __syncthreads();

        const float* Ac = Ab + cur*128*APAD;
        const float* Bc = Bb + cur*16*BPAD;
#pragma unroll
        for (int kt = 0; kt < 2; kt++) {
            const int k0 = kt << 3;
            unsigned afr[4][4], bfr[8][2];
#pragma unroll
            for (int mtl = 0; mtl < 4; mtl++) {
                int m = wm + (mtl << 4);
                afr[mtl][0] = __float_as_uint(Ac[(m + gl    )*APAD + k0 + qd    ]);
                afr[mtl][1] = __float_as_uint(Ac[(m + gl + 8)*APAD + k0 + qd    ]);
                afr[mtl][2] = __float_as_uint(Ac[(m + gl    )*APAD + k0 + qd + 4]);
                afr[mtl][3] = __float_as_uint(Ac[(m + gl + 8)*APAD + k0 + qd + 4]);
            }
#pragma unroll
            for (int ntl = 0; ntl < 8; ntl++) {
                int n = wn + (ntl << 3) + gl;
                bfr[ntl][0] = __float_as_uint(Bc[(k0 + qd    )*BPAD + n]);
                bfr[ntl][1] = __float_as_uint(Bc[(k0 + qd + 4)*BPAD + n]);
            }
#pragma unroll
            for (int mtl = 0; mtl < 4; mtl++)
#pragma unroll
                for (int ntl = 0; ntl < 8; ntl++)
                    mma_tf32(acc[mtl][ntl], afr[mtl], bfr[ntl]);
        }
        if (it + 2 < NIT) {
            int nx2 = cur + 2; if (nx2 >= 3) nx2 -= 3;
            G_STAGE(nx2, (it + 2) << 4);
        }
        cur = (cur == 2) ? 0 : cur + 1;
    }
#undef G_STAGE

    const float sc = g.scale[z];
#pragma unroll
    for (int mtl = 0; mtl < 4; mtl++) {
        int row0 = bm + wm + (mtl << 4) + gl;
#pragma unroll
        for (int ntl = 0; ntl < 8; ntl++) {
            int col = bn + wn + (ntl << 3) + (qd << 1);
            float v0 = acc[mtl][ntl][0], v1 = acc[mtl][ntl][1];
            float v2 = acc[mtl][ntl][2], v3 = acc[mtl][ntl][3];
            if (bias) {
                float b0 = bias[col], b1 = bias[col + 1];
                v0 += b0; v1 += b1; v2 += b0; v3 += b1;
            }
            v0 *= sc; v1 *= sc; v2 *= sc; v3 *= sc;
            if (g.epi == 0) {
                *(float2*)(out + (size_t)row0 * N + col)       = make_float2(v0, v1);
                *(float2*)(out + (size_t)(row0 + 8) * N + col) = make_float2(v2, v3);
            } else {
                int h = col >> 6, d = col & 63;
                int b0i = row0 >> 11, s0 = row0 & (SS - 1);
                int row1 = row0 + 8;
                int b1i = row1 >> 11, s1 = row1 & (SS - 1);
                *(float2*)(out + (((size_t)(b0i*HH + h) * SS + s0) << 6) + d) = make_float2(v0, v1);
                *(float2*)(out + (((size_t)(b1i*HH + h) * SS + s1) << 6) + d) = make_float2(v2, v3);
            }
        }
    }
}

// ---------------- RoPE on q and k (in-place) ----------------
__global__ void rope_kernel(float* __restrict__ q, float* __restrict__ k,
                            const float* __restrict__ tb) {
    int idx = blockIdx.x * blockDim.x + threadIdx.x;
    const int total = BB*HH*SS*32;
    if (idx >= total) return;
    int d   = idx & 31;
    int rem = idx >> 5;
    int s   = rem & (SS-1);
    int rem2 = rem >> 11;
    int h   = rem2 % HH;
    int b   = rem2 / HH;
    float tt = tb[b*SS + s];
    float inv_freq = expf(-(float)d * 0.28782313662425574f);
    float sn, cs;
    sincosf(tt * inv_freq, &sn, &cs);
    size_t off = (((size_t)(b*HH + h) * SS + s) << 6) + d;
    float x1 = q[off], x2 = q[off + 32];
    q[off]      = x1*cs - x2*sn;
    q[off + 32] = x2*cs + x1*sn;
    x1 = k[off]; x2 = k[off + 32];
    k[off]      = x1*cs - x2*sn;
    k[off + 32] = x2*cs + x1*sn;
}

// ---------------- banded + global-key attention: 32-query tiles ----------------
// 512 threads / 16 warps per block; 32 queries share one 544-key (17-chunk) K/V
// window (jrel = j - jmin in [0,543] covers all rows p in [0,31]).
// pb[32][548] jrel-indexed probs; ring [3][2][32][76]; single barrier per round.
#define PBW 548
#define PGW 20
#define KST 76
#define CHB (32*KST)
#define RNGB (2*CHB)
#define BAND_SMEM ((2176 + 32*PGW + 32*PBW + 3*RNGB + 16*KST + 32) * 4 + 544 * 4)

__global__ __launch_bounds__(512) void band_attn_kernel(
    const float* __restrict__ q, const float* __restrict__ k, const float* __restrict__ v,
    const int* __restrict__ am, const int* __restrict__ gm,
    float* __restrict__ attn)
{
    extern __shared__ float sm[];
    float* qs  = sm;                        // [32][68]
    float* pg  = sm + 2176;                 // [32][20]
    float* pb  = pg + 32*PGW;               // [32][548]
    float* ks  = pb + 32*PBW;               // ring [3][2][32][76]
    float* gvs = ks + 3*RNGB;               // [16][76] global K then global V
    float* scl = gvs + 16*KST;              // [32]
    int*   rmv = (int*)(scl + 32);          // [544]

    const int b = blockIdx.z, h = blockIdx.y, base = blockIdx.x << 5;
    const int tid = threadIdx.x;
    const int lane = tid & 31, warp = tid >> 5;
    const int gl = lane >> 2, qd = lane & 3;

    const float* qb = q + ((size_t)(b*HH + h) * SS) * DHH;
    const float* kb = k + ((size_t)(b*HH + h) * SS) * DHH;
    const float* vb = v + ((size_t)(b*HH + h) * SS) * DHH;

    const int jmin = base - WW;

    // stage one round (2 chunks = 64 keys; last round 1 chunk) into ring slot r%3
    auto stage_round = [&](const float* src, int r) {
        int nch = (r < 8) ? 2 : 1;
        float* dst = ks + (r % 3) * RNGB;
        for (int i = tid; i < (nch << 9); i += 512) {
            int cidx = i >> 9, rem = i & 511;
            int kk = (i >> 4) & 31, d4 = i & 15;
            (void)rem;
            int j = jmin + (r << 6) + (cidx << 5) + kk;
            bool valid = (j >= 0 && j < SS);
            cpasync16z(s2u(dst + cidx*CHB + kk*KST + (d4 << 2)),
                       src + (((size_t)(valid ? j : 0)) << 6) + (d4 << 2),
                       valid ? 16u : 0u);
        }
        cp_commit();
    };

    // ---- prologue: q tile (32 rows) + global K; rounds 0,1 in flight ----
    {
        int row = tid >> 4, d4 = tid & 15;   // 512 threads = 32 rows x 16 f4
        cpasync16(s2u(qs + row*68 + (d4 << 2)), qb + (((size_t)(base + row)) << 6) + (d4 << 2));
        if (tid < 256)
            cpasync16(s2u(gvs + row*KST + (d4 << 2)), kb + (((size_t)row) << 6) + (d4 << 2));
        cp_commit();
    }
    stage_round(kb, 0);
    stage_round(kb, 1);
    for (int i = tid; i < 544; i += 512) {
        int j = jmin + i;
        int rm = 1;
        if (j >= 0 && j < SS) { int m = am[b*SS + j] * (gm[b*SS + j] + 1); rm = (m != 1); }
        rmv[i] = rm;
    }
    cp_wait<1>();           // q/gK + round0 done; round1 in flight
    __syncthreads();

    // per-warp Q fragments for score phase: qg = (warp>>2)&1 -> rows 16qg+gl, +8
    const int qg = (warp >> 2) & 1;
    unsigned aq[8][4];
#pragma unroll
    for (int k8 = 0; k8 < 8; k8++) {
        int k0 = k8 << 3;
        int r0 = 16*qg + gl, r1 = r0 + 8;
        aq[k8][0] = __float_as_uint(qs[r0*68 + k0 + qd    ]);
        aq[k8][1] = __float_as_uint(qs[r1*68 + k0 + qd    ]);
        aq[k8][2] = __float_as_uint(qs[r0*68 + k0 + qd + 4]);
        aq[k8][3] = __float_as_uint(qs[r1*68 + k0 + qd + 4]);
    }

    // global-key scores on warps 0,1 (qg=0) and 4,5 (qg=1); nt = warp&1
    if ((warp & 2) == 0 && warp < 8) {
        int nt = warp & 1;
        float acc[4] = {0.f, 0.f, 0.f, 0.f};
        unsigned bfr[2];
#pragma unroll
        for (int k8 = 0; k8 < 8; k8++) {
            int k0 = k8 << 3;
            bfr[0] = __float_as_uint(gvs[(nt*8 + gl)*KST + k0 + qd    ]);
            bfr[1] = __float_as_uint(gvs[(nt*8 + gl)*KST + k0 + qd + 4]);
            mma_tf32(acc, aq[k8], bfr);
        }
        int key = nt*8 + (qd << 1);
        int r0 = 16*qg + gl, r1 = r0 + 8;
        *(float2*)&pg[r0*PGW + key] = make_float2(acc[0], acc[1]);
        *(float2*)&pg[r1*PGW + key] = make_float2(acc[2], acc[3]);
    }

    // ---- score rounds 0..8: wait -> sync -> compute -> stage(r+2) ----
    for (int r = 0; r < 9; r++) {
        if (r + 1 <= 8) cp_wait<1>(); else cp_wait<0>();
        __syncthreads();

        int cidx = warp >> 3;
        int cglob = (r << 1) + cidx;
        if (cglob <= 16) {
            const float* kc = ks + (r % 3)*RNGB + cidx*CHB;
            int ntile = warp & 3;
            float acc[4] = {0.f, 0.f, 0.f, 0.f};
            unsigned bfr[2];
#pragma unroll
            for (int k8 = 0; k8 < 8; k8++) {
                int k0 = k8 << 3;
                bfr[0] = __float_as_uint(kc[(ntile*8 + gl)*KST + k0 + qd    ]);
                bfr[1] = __float_as_uint(kc[(ntile*8 + gl)*KST + k0 + qd + 4]);
                mma_tf32(acc, aq[k8], bfr);
            }
            int c = (cglob << 5) + (ntile << 3) + (qd << 1);
            int m0 = rmv[c], m1 = rmv[c + 1];
            float v0 = m0 ? NEGV : acc[0];
            float v1 = m1 ? NEGV : acc[1];
            float v2 = m0 ? NEGV : acc[2];
            float v3 = m1 ? NEGV : acc[3];
            int r0 = 16*qg + gl, r1 = r0 + 8;
            *(float2*)&pb[r0*PBW + c] = make_float2(v0, v1);
            *(float2*)&pb[r1*PBW + c] = make_float2(v2, v3);
        }
        if (r + 2 <= 8) stage_round(kb, r + 2);
    }
    __syncthreads();   // all pb/pg writes visible

    // ---- prefetch global V + AV rounds 0,1 (overlap with softmax) ----
    if (tid < 256) {
        int row = tid >> 4, d4 = tid & 15;
        cpasync16(s2u(gvs + row*KST + (d4 << 2)), vb + (((size_t)row) << 6) + (d4 << 2));
    }
    cp_commit();
    stage_round(vb, 0);
    stage_round(vb, 1);

    // ---- softmax: row p over pg[p][0..15] and pb[p][p+l], l in [0,512] ----
    {
        const int p = tid >> 4, r = tid & 15;
        float mx = pg[p*PGW + r];
        for (int l = r; l <= 512; l += 16) mx = fmaxf(mx, pb[p*PBW + p + l]);
#pragma unroll
        for (int o = 8; o; o >>= 1) mx = fmaxf(mx, __shfl_xor_sync(0xffffffffu, mx, o, 16));
        float gv0 = __expf(pg[p*PGW + r] - mx);
        pg[p*PGW + r] = tfr(gv0);
        float sum = gv0;
        for (int l = r; l <= 512; l += 16) {
            float e = __expf(pb[p*PBW + p + l] - mx);
            pb[p*PBW + p + l] = tfr(e);
            sum += e;
        }
#pragma unroll
        for (int o = 8; o; o >>= 1) sum += __shfl_xor_sync(0xffffffffu, sum, o, 16);
        if (r == 0) {
            int iq = base + p;
            int mm = am[b*SS + iq] * (gm[b*SS + iq] + 1);
            scl[p] = (mm == 0) ? 0.f : (1.f / sum);
        }
    }
    // zero invalid cells: row p, jrel in [0,p) U (p+512, 547]  (35 per row)
    for (int i = tid; i < 1120; i += 512) {
        int p = i / 35, o = i % 35;
        int jr = (o < p) ? o : (513 + o);
        pb[p*PBW + jr] = 0.f;
    }
    cp_wait<1>();           // global V + AV round0 done; round1 in flight
    __syncthreads();

    // AV: warp owns (qgroup = warp>>3, dims (warp&7)*8 .. +8)
    const int qga = warp >> 3;
    const int nd = ((warp & 7) << 3) + gl;
    const int p0 = 16*qga + gl, p1 = p0 + 8;
    float av[4] = {0.f, 0.f, 0.f, 0.f};
    {   // global-V contribution
        unsigned afr[4], bfr[2];
#pragma unroll
        for (int k8 = 0; k8 < 2; k8++) {
            int k0 = k8 << 3;
            afr[0] = __float_as_uint(pg[p0*PGW + k0 + qd    ]);
            afr[1] = __float_as_uint(pg[p1*PGW + k0 + qd    ]);
            afr[2] = __float_as_uint(pg[p0*PGW + k0 + qd + 4]);
            afr[3] = __float_as_uint(pg[p1*PGW + k0 + qd + 4]);
            bfr[0] = __float_as_uint(gvs[(k0 + qd    )*KST + nd]);
            bfr[1] = __float_as_uint(gvs[(k0 + qd + 4)*KST + nd]);
            mma_tf32(av, afr, bfr);
        }
    }

    // ---- AV rounds 0..8: wait -> sync -> compute -> stage(r+2) ----
    for (int r = 0; r < 9; r++) {
        if (r + 1 <= 8) cp_wait<1>(); else cp_wait<0>();
        __syncthreads();
        int nch = (r < 8) ? 2 : 1;
        const float* vbuf = ks + (r % 3)*RNGB;
        for (int cidx = 0; cidx < nch; cidx++) {
            int cb = ((r << 1) + cidx) << 5;
            const float* vc = vbuf + cidx*CHB;
            unsigned afr[4], bfr[2];
#pragma unroll
            for (int k8 = 0; k8 < 4; k8++) {
                int kA = (k8 << 3) + qd;
                int col = cb + kA;          // jrel; invalid cells are exact 0
                afr[0] = __float_as_uint(pb[p0*PBW + col    ]);
                afr[1] = __float_as_uint(pb[p1*PBW + col    ]);
                afr[2] = __float_as_uint(pb[p0*PBW + col + 4]);
                afr[3] = __float_as_uint(pb[p1*PBW + col + 4]);
                bfr[0] = __float_as_uint(vc[kA*KST       + nd]);
                bfr[1] = __float_as_uint(vc[(kA + 4)*KST + nd]);
                mma_tf32(av, afr, bfr);
            }
        }
        if (r + 2 <= 8) stage_round(vb, r + 2);
    }

    {
        float s0 = scl[p0], s1 = scl[p1];
        int d = ((warp & 7) << 3) + (qd << 1);
        int iq0 = base + p0, iq1 = base + p1;
        *(float2*)(attn + ((size_t)b*SS + iq0)*EE + h*DHH + d) = make_float2(av[0]*s0, av[1]*s0);
        *(float2*)(attn + ((size_t)b*SS + iq1)*EE + h*DHH + d) = make_float2(av[2]*s1, av[3]*s1);
    }
}

// ---------------- global attention (overwrites attn rows < G) ----------------
__global__ __launch_bounds__(256) void global_attn_kernel(
    const float* __restrict__ gq, const float* __restrict__ gk, const float* __restrict__ gv,
    const int* __restrict__ am, const int* __restrict__ gm,
    float* __restrict__ attn)
{
    int g = blockIdx.x, h = blockIdx.y, b = blockIdx.z;
    int tid = threadIdx.x;
    __shared__ float sc[SS];
    __shared__ float qrow[64];
    __shared__ float red[8];
    __shared__ float redv[4][64];

    const float* gkb = gk + ((size_t)(b*HH + h) * SS) * DHH;
    const float* gvb = gv + ((size_t)(b*HH + h) * SS) * DHH;
    if (tid < 64) qrow[tid] = gq[(((size_t)(b*HH + h) * SS + g) << 6) + tid];
    __syncthreads();

    float lmax = -3.4e38f;
    for (int j = tid; j < SS; j += 256) {
        int m = am[b*SS + j] * (gm[b*SS + j] + 1);
        float s;
        if (m == 0) s = NEGV;
        else {
            float a0=0.f,a1=0.f,a2=0.f,a3=0.f;
            const float4* kp = (const float4*)(gkb + (size_t)j * DHH);
            const float4* qp = (const float4*)qrow;
#pragma unroll
            for (int d4 = 0; d4 < 16; d4++) {
                float4 a = qp[d4], bb = kp[d4];
                a0 += a.x*bb.x; a1 += a.y*bb.y; a2 += a.z*bb.z; a3 += a.w*bb.w;
            }
            s = (a0 + a1) + (a2 + a3);
        }
        sc[j] = s;
        lmax = fmaxf(lmax, s);
    }
#pragma unroll
    for (int o = 16; o; o >>= 1) lmax = fmaxf(lmax, __shfl_xor_sync(0xffffffffu, lmax, o));
    if ((tid & 31) == 0) red[tid >> 5] = lmax;
    __syncthreads();
    float bmax = red[0];
#pragma unroll
    for (int w = 1; w < 8; w++) bmax = fmaxf(bmax, red[w]);

    float lsum = 0.f;
    for (int j = tid; j < SS; j += 256) {
        float e = __expf(sc[j] - bmax);
        sc[j] = e;
        lsum += e;
    }
#pragma unroll
    for (int o = 16; o; o >>= 1) lsum += __shfl_xor_sync(0xffffffffu, lsum, o);
    __syncthreads();
    if ((tid & 31) == 0) red[tid >> 5] = lsum;
    __syncthreads();
    float ssum = 0.f;
#pragma unroll
    for (int w = 0; w < 8; w++) ssum += red[w];
    float inv = 1.f / ssum;

    int grp = tid >> 6, d = tid & 63;
    float acc0 = 0.f, acc1 = 0.f;
    for (int j = grp; j < SS; j += 8) {
        acc0 += sc[j] * gvb[(size_t)j * DHH + d];
        acc1 += sc[j + 4] * gvb[(size_t)(j + 4) * DHH + d];
    }
    redv[grp][d] = acc0 + acc1;
    __syncthreads();
    if (grp == 0) {
        float o = (redv[0][d] + redv[1][d] + redv[2][d] + redv[3][d]) * inv;
        attn[((size_t)b*SS + g)*EE + h*DHH + d] = o;
    }
}

// ---------------- fused add + LayerNorm ----------------
__global__ __launch_bounds__(256) void add_ln_kernel(
    const float* __restrict__ a, const float* __restrict__ c,
    const float* __restrict__ gamma, const float* __restrict__ beta,
    float* __restrict__ out)
{
    int row = blockIdx.x;
    int tid = threadIdx.x;
    __shared__ float buf[EE];
    __shared__ float red[8];

    float local = 0.f;
#pragma unroll
    for (int i = 0; i < 3; i++) {
        int idx = tid + i*256;
        float v = a[(size_t)row*EE + idx] + c[(size_t)row*EE + idx];
        buf[idx] = v;
        local += v;
    }
#pragma unroll
    for (int o = 16; o; o >>= 1) local += __shfl_xor_sync(0xffffffffu, local, o);
    if ((tid & 31) == 0) red[tid >> 5] = local;
    __syncthreads();
    float s = 0.f;
#pragma unroll
    for (int w = 0; w < 8; w++) s += red[w];
    float mean = s * (1.f/768.f);

    float lv = 0.f;
#pragma unroll
    for (int i = 0; i < 3; i++) {
        float dd = buf[tid + i*256] - mean;
        lv += dd*dd;
    }
#pragma unroll
    for (int o = 16; o; o >>= 1) lv += __shfl_xor_sync(0xffffffffu, lv, o);
    __syncthreads();
    if ((tid & 31) == 0) red[tid >> 5] = lv;
    __syncthreads();
    float vs = 0.f;
#pragma unroll
    for (int w = 0; w < 8; w++) vs += red[w];
    float invstd = rsqrtf(vs * (1.f/768.f) + 1e-5f);

#pragma unroll
    for (int i = 0; i < 3; i++) {
        int idx = tid + i*256;
        out[(size_t)row*EE + idx] = (buf[idx] - mean) * invstd * gamma[idx] + beta[idx];
    }
}

// ---------------- SiLU(t1) * t2 -> t1 (vectorized) ----------------
__global__ void silu_mul_kernel(float4* __restrict__ t1, const float4* __restrict__ t2, int n4) {
    int i = blockIdx.x * blockDim.x + threadIdx.x;
    if (i < n4) {
        float4 a = t1[i], b = t2[i];
        a.x = a.x / (1.f + __expf(-a.x)) * b.x;
        a.y = a.y / (1.f + __expf(-a.y)) * b.y;
        a.z = a.z / (1.f + __expf(-a.z)) * b.z;
        a.w = a.w / (1.f + __expf(-a.w)) * b.w;
        t1[i] = a;
    }
}

// ---------------- launch ----------------
extern "C" void kernel_launch(void* const* d_in, const int* in_sizes, int n_in,
                              void* d_out, int out_size) {
    (void)in_sizes; (void)n_in; (void)out_size;
    const float* x    = (const float*)d_in[0];
    const int*   am   = (const int*)d_in[1];
    const int*   gm   = (const int*)d_in[2];
    const float* Wq   = (const float*)d_in[3];  const float* bq  = (const float*)d_in[4];
    const float* Wk   = (const float*)d_in[5];  const float* bk  = (const float*)d_in[6];
    const float* Wv   = (const float*)d_in[7];  const float* bv  = (const float*)d_in[8];
    const float* Wqg  = (const float*)d_in[9];  const float* bqg = (const float*)d_in[10];
    const float* Wkg  = (const float*)d_in[11]; const float* bkg = (const float*)d_in[12];
    const float* Wvg  = (const float*)d_in[13]; const float* bvg = (const float*)d_in[14];
    const float* ln0g = (const float*)d_in[15]; const float* ln0b = (const float*)d_in[16];
    const float* ln1g = (const float*)d_in[17]; const float* ln1b = (const float*)d_in[18];
    const float* W1   = (const float*)d_in[19];
    const float* W3   = (const float*)d_in[20];
    const float* W2   = (const float*)d_in[21];
    float* out = (float*)d_out;

    float *qp, *kp, *vp, *gqp, *gkp, *gvp, *attnp, *h0p, *t1p, *t2p, *tbp;
    cudaGetSymbolAddress((void**)&qp,  g_q);
    cudaGetSymbolAddress((void**)&kp,  g_k);
    cudaGetSymbolAddress((void**)&vp,  g_v);
    cudaGetSymbolAddress((void**)&gqp, g_gq);
    cudaGetSymbolAddress((void**)&gkp, g_gk);
    cudaGetSymbolAddress((void**)&gvp, g_gv);
    cudaGetSymbolAddress((void**)&attnp, g_attn);
    cudaGetSymbolAddress((void**)&h0p, g_h0);
    cudaGetSymbolAddress((void**)&t1p, g_t1);
    cudaGetSymbolAddress((void**)&t2p, g_t2);
    cudaGetSymbolAddress((void**)&tbp, g_tbuf);

    cudaFuncSetAttribute(band_attn_kernel,
                         cudaFuncAttributeMaxDynamicSharedMemorySize, BAND_SMEM);
    cudaFuncSetAttribute(tf32gemm_kernel,
                         cudaFuncAttributeMaxDynamicSharedMemorySize, GEMM_SMEM);

    mask_cumsum_kernel<<<BB, 256>>>(am, gm, tbp);

    GemmArgs pa = {};
    pa.A = x; pa.N = EE; pa.K = EE; pa.epi = 1;
    pa.Wm[0] = Wq;  pa.bias[0] = bq;  pa.out[0] = qp;  pa.scale[0] = 0.125f;
    pa.Wm[1] = Wk;  pa.bias[1] = bk;  pa.out[1] = kp;  pa.scale[1] = 1.f;
    pa.Wm[2] = Wv;  pa.bias[2] = bv;  pa.out[2] = vp;  pa.scale[2] = 1.f;
    pa.Wm[3] = Wqg; pa.bias[3] = bqg; pa.out[3] = gqp; pa.scale[3] = 0.125f;
    pa.Wm[4] = Wkg; pa.bias[4] = bkg; pa.out[4] = gkp; pa.scale[4] = 1.f;
    pa.Wm[5] = Wvg; pa.bias[5] = bvg; pa.out[5] = gvp; pa.scale[5] = 1.f;
    tf32gemm_kernel<<<dim3(32, 6, 6), 128, GEMM_SMEM>>>(pa);

    rope_kernel<<<(BB*HH*SS*32 + 255)/256, 256>>>(qp, kp, tbp);

    band_attn_kernel<<<dim3(SS/32, HH, BB), 512, BAND_SMEM>>>(qp, kp, vp, am, gm, attnp);
    global_attn_kernel<<<dim3(GG, HH, BB), 256>>>(gqp, gkp, gvp, am, gm, attnp);

    add_ln_kernel<<<BB*SS, 256>>>(x, attnp, ln0g, ln0b, h0p);

    GemmArgs f1 = {};
    f1.A = h0p; f1.N = FFD; f1.K = EE; f1.epi = 0;
    f1.Wm[0] = W1; f1.bias[0] = nullptr; f1.out[0] = t1p; f1.scale[0] = 1.f;
    f1.Wm[1] = W3; f1.bias[1] = nullptr; f1.out[1] = t2p; f1.scale[1] = 1.f;
    tf32gemm_kernel<<<dim3(32, 24, 2), 128, GEMM_SMEM>>>(f1);

    silu_mul_kernel<<<(NFF/4 + 255)/256, 256>>>((float4*)t1p, (const float4*)t2p, NFF/4);

    GemmArgs f2 = {};
    f2.A = t1p; f2.N = EE; f2.K = FFD; f2.epi = 0;
    f2.Wm[0] = W2; f2.bias[0] = nullptr; f2.out[0] = attnp; f2.scale[0] = 1.f;
    tf32gemm_kernel<<<dim3(32, 6, 1), 128, GEMM_SMEM>>>(f2);

    add_ln_kernel<<<BB*SS, 256>>>(h0p, attnp, ln1g, ln1b, out);
}

// round 17
// speedup vs baseline: 3.7127x; 1.0178x over previous
#include <cuda_runtime.h>
#include <cuda_bf16.h>
#include <math.h>

#define BB 2
#define SS 2048
#define EE 768
#define HH 12
#define DHH 64
#define WW 256
#define GG 16
#define FFD 3072
#define NEGV (-1e9f)

#define NQKV (BB*HH*SS*DHH)
#define NXE  (BB*SS*EE)
#define NFF  (BB*SS*FFD)

// ---------------- device scratch ----------------
__device__ float g_q[NQKV];
__device__ float g_k[NQKV];
__device__ float g_v[NQKV];
__device__ float g_gq[NQKV];
__device__ float g_gk[NQKV];
__device__ float g_gv[NQKV];
__device__ float g_attn[NXE];
__device__ float g_h0[NXE];
__device__ float g_t1[NFF];
__device__ float g_tbuf[BB*SS];

// ---------------- mma / cp.async helpers ----------------
__device__ __forceinline__ void mma_tf32(float (&d)[4], const unsigned* a, const unsigned* b) {
    asm volatile(
        "mma.sync.aligned.m16n8k8.row.col.f32.tf32.tf32.f32 "
        "{%0,%1,%2,%3}, {%4,%5,%6,%7}, {%8,%9}, {%0,%1,%2,%3};\n"
        : "+f"(d[0]), "+f"(d[1]), "+f"(d[2]), "+f"(d[3])
        : "r"(a[0]), "r"(a[1]), "r"(a[2]), "r"(a[3]), "r"(b[0]), "r"(b[1]));
}
__device__ __forceinline__ void cpasync16(unsigned dst, const void* src) {
    asm volatile("cp.async.cg.shared.global [%0], [%1], 16;\n" :: "r"(dst), "l"(src));
}
__device__ __forceinline__ void cpasync16z(unsigned dst, const void* src, unsigned ssz) {
    asm volatile("cp.async.cg.shared.global [%0], [%1], 16, %2;\n" :: "r"(dst), "l"(src), "r"(ssz));
}
__device__ __forceinline__ void cp_commit() {
    asm volatile("cp.async.commit_group;\n");
}
template <int N> __device__ __forceinline__ void cp_wait() {
    asm volatile("cp.async.wait_group %0;\n" :: "n"(N));
}
__device__ __forceinline__ float tfr(float x) {
    unsigned r; asm("cvt.rna.tf32.f32 %0, %1;" : "=r"(r) : "f"(x));
    return __uint_as_float(r);
}
__device__ __forceinline__ unsigned s2u(const void* p) {
    return (unsigned)__cvta_generic_to_shared(p);
}

// ---------------- parallel cumsum of global flags -> t ----------------
__global__ __launch_bounds__(256) void mask_cumsum_kernel(const int* __restrict__ am,
                                                          const int* __restrict__ gm,
                                                          float* __restrict__ tb) {
    int b = blockIdx.x;
    int tid = threadIdx.x;
    int lane = tid & 31, warp = tid >> 5;
    __shared__ int flg[SS];
    __shared__ int wsum[8];
    for (int i = tid; i < SS; i += 256)
        flg[i] = am[b*SS + i] * (gm[b*SS + i] + 1);
    __syncthreads();
    int base = tid << 3;
    int loc[8];
    int s = 0;
#pragma unroll
    for (int j = 0; j < 8; j++) { loc[j] = s; s += (flg[base + j] == 2); }
    int inc = s;
#pragma unroll
    for (int o = 1; o < 32; o <<= 1) {
        int v = __shfl_up_sync(0xffffffffu, inc, o);
        if (lane >= o) inc += v;
    }
    if (lane == 31) wsum[warp] = inc;
    __syncthreads();
    int woff = 0;
#pragma unroll
    for (int w = 0; w < 8; w++) if (w < warp) woff += wsum[w];
    int excl = woff + inc - s;
#pragma unroll
    for (int j = 0; j < 8; j++) {
        int idx = base + j;
        int m = flg[idx];
        int c = excl + loc[j] + (m == 2);
        tb[b*SS + idx] = (m == 0) ? 0.f : (float)c;
    }
}

// ---------------- tf32 GEMM (3-stage pipeline) with optional fused RoPE ----------------
struct GemmArgs {
    const float* A;
    const float* Wm[6];
    const float* bias[6];
    float* out[6];
    float scale[6];
    const float* tb;
    int rope[6];
    int N, K, epi;
};

#define APAD 20
#define BPAD 136
#define GEMM_SMEM ((3*128*APAD + 3*16*BPAD) * 4)

__global__ __launch_bounds__(128, 2) void tf32gemm_kernel(GemmArgs g) {
    extern __shared__ float gsm[];
    float* Ab = gsm;
    float* Bb = gsm + 3*128*APAD;

    const int z = blockIdx.z;
    const float* __restrict__ A = g.A;
    const float* __restrict__ W = g.Wm[z];
    const float* __restrict__ bias = g.bias[z];
    float* __restrict__ out = g.out[z];
    const int N = g.N, K = g.K;
    const int bm = blockIdx.x << 7, bn = blockIdx.y << 7;

    const int tid = threadIdx.x;
    const int lane = tid & 31, warp = tid >> 5;
    const int wm = (warp >> 1) << 6;
    const int wn = (warp & 1) << 6;
    const int gl = lane >> 2, qd = lane & 3;

    float acc[4][8][4];
#pragma unroll
    for (int i = 0; i < 4; i++)
#pragma unroll
        for (int j = 0; j < 8; j++)
#pragma unroll
            for (int r = 0; r < 4; r++) acc[i][j][r] = 0.f;

    const float* Agp0 = A + (size_t)(bm + (tid >> 2)) * K + ((tid & 3) << 2);
    const float* Wgp0 = W + (size_t)(tid >> 5) * N + bn + ((tid & 31) << 2);
    const size_t AgS = (size_t)32 * K;
    const size_t WgS = (size_t)4 * N;
    const unsigned sAb = s2u(Ab + (tid >> 2)*APAD + ((tid & 3) << 2));
    const unsigned sBb = s2u(Bb + (tid >> 5)*BPAD + ((tid & 31) << 2));
    const unsigned ABUF = 128 * APAD * 4;
    const unsigned BBUF = 16 * BPAD * 4;
    const unsigned AT = 32 * APAD * 4;
    const unsigned BT = 4 * BPAD * 4;

    const int NIT = K >> 4;

#define G_STAGE(s, k0) do {                                                   \
        _Pragma("unroll")                                                     \
        for (int t = 0; t < 4; t++) {                                         \
            cpasync16(sAb + (s)*ABUF + t*AT, Agp0 + (k0) + (size_t)t*AgS);    \
            cpasync16(sBb + (s)*BBUF + t*BT, Wgp0 + (size_t)(k0)*N + (size_t)t*WgS); \
        }                                                                     \
        cp_commit();                                                          \
    } while (0)

    G_STAGE(0, 0);
    if (NIT > 1) G_STAGE(1, 16);
    int cur = 0;

    for (int it = 0; it < NIT; it++) {
        if (it + 1 < NIT) cp_wait<1>(); else cp_wait<0>();
        __syncthreads();

        const float* Ac = Ab + cur*128*APAD;
        const float* Bc = Bb + cur*16*BPAD;
#pragma unroll
        for (int kt = 0; kt < 2; kt++) {
            const int k0 = kt << 3;
            unsigned afr[4][4], bfr[8][2];
#pragma unroll
            for (int mtl = 0; mtl < 4; mtl++) {
                int m = wm + (mtl << 4);
                afr[mtl][0] = __float_as_uint(Ac[(m + gl    )*APAD + k0 + qd    ]);
                afr[mtl][1] = __float_as_uint(Ac[(m + gl + 8)*APAD + k0 + qd    ]);
                afr[mtl][2] = __float_as_uint(Ac[(m + gl    )*APAD + k0 + qd + 4]);
                afr[mtl][3] = __float_as_uint(Ac[(m + gl + 8)*APAD + k0 + qd + 4]);
            }
#pragma unroll
            for (int ntl = 0; ntl < 8; ntl++) {
                int n = wn + (ntl << 3) + gl;
                bfr[ntl][0] = __float_as_uint(Bc[(k0 + qd    )*BPAD + n]);
                bfr[ntl][1] = __float_as_uint(Bc[(k0 + qd + 4)*BPAD + n]);
            }
#pragma unroll
            for (int mtl = 0; mtl < 4; mtl++)
#pragma unroll
                for (int ntl = 0; ntl < 8; ntl++)
                    mma_tf32(acc[mtl][ntl], afr[mtl], bfr[ntl]);
        }
        if (it + 2 < NIT) {
            int nx2 = cur + 2; if (nx2 >= 3) nx2 -= 3;
            G_STAGE(nx2, (it + 2) << 4);
        }
        cur = (cur == 2) ? 0 : cur + 1;
    }
#undef G_STAGE

    const float sc = g.scale[z];
    if (g.epi == 0) {
#pragma unroll
        for (int mtl = 0; mtl < 4; mtl++) {
            int row0 = bm + wm + (mtl << 4) + gl;
#pragma unroll
            for (int ntl = 0; ntl < 8; ntl++) {
                int col = bn + wn + (ntl << 3) + (qd << 1);
                float v0 = acc[mtl][ntl][0], v1 = acc[mtl][ntl][1];
                float v2 = acc[mtl][ntl][2], v3 = acc[mtl][ntl][3];
                if (bias) {
                    float b0 = bias[col], b1 = bias[col + 1];
                    v0 += b0; v1 += b1; v2 += b0; v3 += b1;
                }
                v0 *= sc; v1 *= sc; v2 *= sc; v3 *= sc;
                *(float2*)(out + (size_t)row0 * N + col)       = make_float2(v0, v1);
                *(float2*)(out + (size_t)(row0 + 8) * N + col) = make_float2(v2, v3);
            }
        }
        return;
    }

    // epi == 1: bias+scale in place, optional fused RoPE, scatter store
#pragma unroll
    for (int mtl = 0; mtl < 4; mtl++)
#pragma unroll
        for (int ntl = 0; ntl < 8; ntl++) {
            int col = bn + wn + (ntl << 3) + (qd << 1);
            float b0 = bias ? bias[col] : 0.f, b1 = bias ? bias[col + 1] : 0.f;
            acc[mtl][ntl][0] = (acc[mtl][ntl][0] + b0) * sc;
            acc[mtl][ntl][1] = (acc[mtl][ntl][1] + b1) * sc;
            acc[mtl][ntl][2] = (acc[mtl][ntl][2] + b0) * sc;
            acc[mtl][ntl][3] = (acc[mtl][ntl][3] + b1) * sc;
        }

    if (g.rope[z]) {
        const float* tb = g.tb;
        float frq[8];
#pragma unroll
        for (int ntl = 0; ntl < 4; ntl++)
#pragma unroll
            for (int e = 0; e < 2; e++)
                frq[ntl*2 + e] = expf(-(float)((ntl << 3) + (qd << 1) + e) * 0.28782313662425574f);
#pragma unroll
        for (int mtl = 0; mtl < 4; mtl++) {
            int row0 = bm + wm + (mtl << 4) + gl;
            int row1 = row0 + 8;
            float tt0 = tb[(row0 >> 11)*SS + (row0 & (SS-1))];
            float tt1 = tb[(row1 >> 11)*SS + (row1 & (SS-1))];
#pragma unroll
            for (int ntl = 0; ntl < 4; ntl++) {
#pragma unroll
                for (int e = 0; e < 2; e++) {
                    float fr = frq[ntl*2 + e];
                    float sn, cs;
                    sincosf(tt0 * fr, &sn, &cs);
                    float x1 = acc[mtl][ntl][e], x2 = acc[mtl][ntl+4][e];
                    acc[mtl][ntl][e]   = x1*cs - x2*sn;
                    acc[mtl][ntl+4][e] = x2*cs + x1*sn;
                    sincosf(tt1 * fr, &sn, &cs);
                    x1 = acc[mtl][ntl][e+2]; x2 = acc[mtl][ntl+4][e+2];
                    acc[mtl][ntl][e+2]   = x1*cs - x2*sn;
                    acc[mtl][ntl+4][e+2] = x2*cs + x1*sn;
                }
            }
        }
    }

#pragma unroll
    for (int mtl = 0; mtl < 4; mtl++) {
        int row0 = bm + wm + (mtl << 4) + gl;
        int row1 = row0 + 8;
        int b0i = row0 >> 11, s0 = row0 & (SS - 1);
        int b1i = row1 >> 11, s1 = row1 & (SS - 1);
#pragma unroll
        for (int ntl = 0; ntl < 8; ntl++) {
            int col = bn + wn + (ntl << 3) + (qd << 1);
            int h = col >> 6, d = col & 63;
            *(float2*)(out + (((size_t)(b0i*HH + h) * SS + s0) << 6) + d) =
                make_float2(acc[mtl][ntl][0], acc[mtl][ntl][1]);
            *(float2*)(out + (((size_t)(b1i*HH + h) * SS + s1) << 6) + d) =
                make_float2(acc[mtl][ntl][2], acc[mtl][ntl][3]);
        }
    }
}

// ---------------- fused FFN-up: t1 = silu(h0@W1) * (h0@W3) ----------------
// CTA tile 128 rows x 64 cols (both weights share the A tile). 4 warps, warp
// tile 64x32 per weight. B smem [16][136]: cols 0..63 = W1 tile, 64..127 = W3.
__global__ __launch_bounds__(128, 2) void ffn1_kernel(
    const float* __restrict__ A, const float* __restrict__ W1,
    const float* __restrict__ W3, float* __restrict__ out)
{
    extern __shared__ float gsm[];
    float* Ab = gsm;
    float* Bb = gsm + 3*128*APAD;

    const int K = EE, N = FFD;
    const int bm = blockIdx.x << 7, bn = blockIdx.y << 6;

    const int tid = threadIdx.x;
    const int lane = tid & 31, warp = tid >> 5;
    const int wm = (warp >> 1) << 6;
    const int wn = (warp & 1) << 5;
    const int gl = lane >> 2, qd = lane & 3;

    float ac1[4][4][4], ac2[4][4][4];
#pragma unroll
    for (int i = 0; i < 4; i++)
#pragma unroll
        for (int j = 0; j < 4; j++)
#pragma unroll
            for (int r = 0; r < 4; r++) { ac1[i][j][r] = 0.f; ac2[i][j][r] = 0.f; }

    const float* Agp0 = A + (size_t)(bm + (tid >> 2)) * K + ((tid & 3) << 2);
    const size_t AgS = (size_t)32 * K;
    const unsigned sAb = s2u(Ab + (tid >> 2)*APAD + ((tid & 3) << 2));

    // B staging: thread handles fixed cc = tid&31 (cc<16 -> W1, else W3), rows (tid>>5)+4t
    const int cc = tid & 31;
    const int brow0 = tid >> 5;
    const float* Bgp = (cc < 16)
        ? (W1 + (size_t)brow0 * N + bn + (cc << 2))
        : (W3 + (size_t)brow0 * N + bn + ((cc - 16) << 2));
    const int bdst = (cc < 16) ? (cc << 2) : (64 + ((cc - 16) << 2));
    const size_t BgS = (size_t)4 * N;
    const unsigned sBb = s2u(Bb + brow0*BPAD + bdst);

    const unsigned ABUF = 128 * APAD * 4;
    const unsigned BBUF = 16 * BPAD * 4;
    const unsigned AT = 32 * APAD * 4;
    const unsigned BT = 4 * BPAD * 4;

    const int NIT = K >> 4;   // 48

#define F_STAGE(s, k0) do {                                                   \
        _Pragma("unroll")                                                     \
        for (int t = 0; t < 4; t++) {                                         \
            cpasync16(sAb + (s)*ABUF + t*AT, Agp0 + (k0) + (size_t)t*AgS);    \
            cpasync16(sBb + (s)*BBUF + t*BT, Bgp + (size_t)(k0)*N + (size_t)t*BgS); \
        }                                                                     \
        cp_commit();                                                          \
    } while (0)

    F_STAGE(0, 0);
    F_STAGE(1, 16);
    int cur = 0;

    for (int it = 0; it < NIT; it++) {
        if (it + 1 < NIT) cp_wait<1>(); else cp_wait<0>();
        __syncthreads();

        const float* Ac = Ab + cur*128*APAD;
        const float* Bc = Bb + cur*16*BPAD;
#pragma unroll
        for (int kt = 0; kt < 2; kt++) {
            const int k0 = kt << 3;
            unsigned afr[4][4], bf1[4][2], bf2[4][2];
#pragma unroll
            for (int mtl = 0; mtl < 4; mtl++) {
                int m = wm + (mtl << 4);
                afr[mtl][0] = __float_as_uint(Ac[(m + gl    )*APAD + k0 + qd    ]);
                afr[mtl][1] = __float_as_uint(Ac[(m + gl + 8)*APAD + k0 + qd    ]);
                afr[mtl][2] = __float_as_uint(Ac[(m + gl    )*APAD + k0 + qd + 4]);
                afr[mtl][3] = __float_as_uint(Ac[(m + gl + 8)*APAD + k0 + qd + 4]);
            }
#pragma unroll
            for (int ntl = 0; ntl < 4; ntl++) {
                int n = wn + (ntl << 3) + gl;
                bf1[ntl][0] = __float_as_uint(Bc[(k0 + qd    )*BPAD + n]);
                bf1[ntl][1] = __float_as_uint(Bc[(k0 + qd + 4)*BPAD + n]);
                bf2[ntl][0] = __float_as_uint(Bc[(k0 + qd    )*BPAD + 64 + n]);
                bf2[ntl][1] = __float_as_uint(Bc[(k0 + qd + 4)*BPAD + 64 + n]);
            }
#pragma unroll
            for (int mtl = 0; mtl < 4; mtl++)
#pragma unroll
                for (int ntl = 0; ntl < 4; ntl++) {
                    mma_tf32(ac1[mtl][ntl], afr[mtl], bf1[ntl]);
                    mma_tf32(ac2[mtl][ntl], afr[mtl], bf2[ntl]);
                }
        }
        if (it + 2 < NIT) {
            int nx2 = cur + 2; if (nx2 >= 3) nx2 -= 3;
            F_STAGE(nx2, (it + 2) << 4);
        }
        cur = (cur == 2) ? 0 : cur + 1;
    }
#undef F_STAGE

#pragma unroll
    for (int mtl = 0; mtl < 4; mtl++) {
        int row0 = bm + wm + (mtl << 4) + gl;
#pragma unroll
        for (int ntl = 0; ntl < 4; ntl++) {
            int col = bn + wn + (ntl << 3) + (qd << 1);
            float r[4];
#pragma unroll
            for (int e = 0; e < 4; e++) {
                float a = ac1[mtl][ntl][e];
                r[e] = a / (1.f + __expf(-a)) * ac2[mtl][ntl][e];
            }
            *(float2*)(out + (size_t)row0 * N + col)       = make_float2(r[0], r[1]);
            *(float2*)(out + (size_t)(row0 + 8) * N + col) = make_float2(r[2], r[3]);
        }
    }
}

// ---------------- banded + global-key attention: 32-query tiles ----------------
#define PBW 548
#define PGW 20
#define KST 76
#define CHB (32*KST)
#define RNGB (2*CHB)
#define BAND_SMEM ((2176 + 32*PGW + 32*PBW + 3*RNGB + 16*KST + 32) * 4 + 544 * 4)

__global__ __launch_bounds__(512) void band_attn_kernel(
    const float* __restrict__ q, const float* __restrict__ k, const float* __restrict__ v,
    const int* __restrict__ am, const int* __restrict__ gm,
    float* __restrict__ attn)
{
    extern __shared__ float sm[];
    float* qs  = sm;                        // [32][68]
    float* pg  = sm + 2176;                 // [32][20]
    float* pb  = pg + 32*PGW;               // [32][548]
    float* ks  = pb + 32*PBW;               // ring [3][2][32][76]
    float* gvs = ks + 3*RNGB;               // [16][76]
    float* scl = gvs + 16*KST;              // [32]
    int*   rmv = (int*)(scl + 32);          // [544]

    const int b = blockIdx.z, h = blockIdx.y, base = blockIdx.x << 5;
    const int tid = threadIdx.x;
    const int lane = tid & 31, warp = tid >> 5;
    const int gl = lane >> 2, qd = lane & 3;

    const float* qb = q + ((size_t)(b*HH + h) * SS) * DHH;
    const float* kb = k + ((size_t)(b*HH + h) * SS) * DHH;
    const float* vb = v + ((size_t)(b*HH + h) * SS) * DHH;

    const int jmin = base - WW;

    auto stage_round = [&](const float* src, int r) {
        int nch = (r < 8) ? 2 : 1;
        float* dst = ks + (r % 3) * RNGB;
        for (int i = tid; i < (nch << 9); i += 512) {
            int cidx = i >> 9;
            int kk = (i >> 4) & 31, d4 = i & 15;
            int j = jmin + (r << 6) + (cidx << 5) + kk;
            bool valid = (j >= 0 && j < SS);
            cpasync16z(s2u(dst + cidx*CHB + kk*KST + (d4 << 2)),
                       src + (((size_t)(valid ? j : 0)) << 6) + (d4 << 2),
                       valid ? 16u : 0u);
        }
        cp_commit();
    };

    {
        int row = tid >> 4, d4 = tid & 15;
        cpasync16(s2u(qs + row*68 + (d4 << 2)), qb + (((size_t)(base + row)) << 6) + (d4 << 2));
        if (tid < 256)
            cpasync16(s2u(gvs + row*KST + (d4 << 2)), kb + (((size_t)row) << 6) + (d4 << 2));
        cp_commit();
    }
    stage_round(kb, 0);
    stage_round(kb, 1);
    for (int i = tid; i < 544; i += 512) {
        int j = jmin + i;
        int rm = 1;
        if (j >= 0 && j < SS) { int m = am[b*SS + j] * (gm[b*SS + j] + 1); rm = (m != 1); }
        rmv[i] = rm;
    }
    cp_wait<1>();
    __syncthreads();

    const int qg = (warp >> 2) & 1;
    unsigned aq[8][4];
#pragma unroll
    for (int k8 = 0; k8 < 8; k8++) {
        int k0 = k8 << 3;
        int r0 = 16*qg + gl, r1 = r0 + 8;
        aq[k8][0] = __float_as_uint(qs[r0*68 + k0 + qd    ]);
        aq[k8][1] = __float_as_uint(qs[r1*68 + k0 + qd    ]);
        aq[k8][2] = __float_as_uint(qs[r0*68 + k0 + qd + 4]);
        aq[k8][3] = __float_as_uint(qs[r1*68 + k0 + qd + 4]);
    }

    if ((warp & 2) == 0 && warp < 8) {
        int nt = warp & 1;
        float acc[4] = {0.f, 0.f, 0.f, 0.f};
        unsigned bfr[2];
#pragma unroll
        for (int k8 = 0; k8 < 8; k8++) {
            int k0 = k8 << 3;
            bfr[0] = __float_as_uint(gvs[(nt*8 + gl)*KST + k0 + qd    ]);
            bfr[1] = __float_as_uint(gvs[(nt*8 + gl)*KST + k0 + qd + 4]);
            mma_tf32(acc, aq[k8], bfr);
        }
        int key = nt*8 + (qd << 1);
        int r0 = 16*qg + gl, r1 = r0 + 8;
        *(float2*)&pg[r0*PGW + key] = make_float2(acc[0], acc[1]);
        *(float2*)&pg[r1*PGW + key] = make_float2(acc[2], acc[3]);
    }

    for (int r = 0; r < 9; r++) {
        if (r + 1 <= 8) cp_wait<1>(); else cp_wait<0>();
        __syncthreads();

        int cidx = warp >> 3;
        int cglob = (r << 1) + cidx;
        if (cglob <= 16) {
            const float* kc = ks + (r % 3)*RNGB + cidx*CHB;
            int ntile = warp & 3;
            float acc[4] = {0.f, 0.f, 0.f, 0.f};
            unsigned bfr[2];
#pragma unroll
            for (int k8 = 0; k8 < 8; k8++) {
                int k0 = k8 << 3;
                bfr[0] = __float_as_uint(kc[(ntile*8 + gl)*KST + k0 + qd    ]);
                bfr[1] = __float_as_uint(kc[(ntile*8 + gl)*KST + k0 + qd + 4]);
                mma_tf32(acc, aq[k8], bfr);
            }
            int c = (cglob << 5) + (ntile << 3) + (qd << 1);
            int m0 = rmv[c], m1 = rmv[c + 1];
            float v0 = m0 ? NEGV : acc[0];
            float v1 = m1 ? NEGV : acc[1];
            float v2 = m0 ? NEGV : acc[2];
            float v3 = m1 ? NEGV : acc[3];
            int r0 = 16*qg + gl, r1 = r0 + 8;
            *(float2*)&pb[r0*PBW + c] = make_float2(v0, v1);
            *(float2*)&pb[r1*PBW + c] = make_float2(v2, v3);
        }
        if (r + 2 <= 8) stage_round(kb, r + 2);
    }
    __syncthreads();

    if (tid < 256) {
        int row = tid >> 4, d4 = tid & 15;
        cpasync16(s2u(gvs + row*KST + (d4 << 2)), vb + (((size_t)row) << 6) + (d4 << 2));
    }
    cp_commit();
    stage_round(vb, 0);
    stage_round(vb, 1);

    {
        const int p = tid >> 4, r = tid & 15;
        float mx = pg[p*PGW + r];
        for (int l = r; l <= 512; l += 16) mx = fmaxf(mx, pb[p*PBW + p + l]);
#pragma unroll
        for (int o = 8; o; o >>= 1) mx = fmaxf(mx, __shfl_xor_sync(0xffffffffu, mx, o, 16));
        float gv0 = __expf(pg[p*PGW + r] - mx);
        pg[p*PGW + r] = tfr(gv0);
        float sum = gv0;
        for (int l = r; l <= 512; l += 16) {
            float e = __expf(pb[p*PBW + p + l] - mx);
            pb[p*PBW + p + l] = tfr(e);
            sum += e;
        }
#pragma unroll
        for (int o = 8; o; o >>= 1) sum += __shfl_xor_sync(0xffffffffu, sum, o, 16);
        if (r == 0) {
            int iq = base + p;
            int mm = am[b*SS + iq] * (gm[b*SS + iq] + 1);
            scl[p] = (mm == 0) ? 0.f : (1.f / sum);
        }
    }
    for (int i = tid; i < 1120; i += 512) {
        int p = i / 35, o = i % 35;
        int jr = (o < p) ? o : (513 + o);
        pb[p*PBW + jr] = 0.f;
    }
    cp_wait<1>();
    __syncthreads();

    const int qga = warp >> 3;
    const int nd = ((warp & 7) << 3) + gl;
    const int p0 = 16*qga + gl, p1 = p0 + 8;
    float av[4] = {0.f, 0.f, 0.f, 0.f};
    {
        unsigned afr[4], bfr[2];
#pragma unroll
        for (int k8 = 0; k8 < 2; k8++) {
            int k0 = k8 << 3;
            afr[0] = __float_as_uint(pg[p0*PGW + k0 + qd    ]);
            afr[1] = __float_as_uint(pg[p1*PGW + k0 + qd    ]);
            afr[2] = __float_as_uint(pg[p0*PGW + k0 + qd + 4]);
            afr[3] = __float_as_uint(pg[p1*PGW + k0 + qd + 4]);
            bfr[0] = __float_as_uint(gvs[(k0 + qd    )*KST + nd]);
            bfr[1] = __float_as_uint(gvs[(k0 + qd + 4)*KST + nd]);
            mma_tf32(av, afr, bfr);
        }
    }

    for (int r = 0; r < 9; r++) {
        if (r + 1 <= 8) cp_wait<1>(); else cp_wait<0>();
        __syncthreads();
        int nch = (r < 8) ? 2 : 1;
        const float* vbuf = ks + (r % 3)*RNGB;
        for (int cidx = 0; cidx < nch; cidx++) {
            int cb = ((r << 1) + cidx) << 5;
            const float* vc = vbuf + cidx*CHB;
            unsigned afr[4], bfr[2];
#pragma unroll
            for (int k8 = 0; k8 < 4; k8++) {
                int kA = (k8 << 3) + qd;
                int col = cb + kA;
                afr[0] = __float_as_uint(pb[p0*PBW + col    ]);
                afr[1] = __float_as_uint(pb[p1*PBW + col    ]);
                afr[2] = __float_as_uint(pb[p0*PBW + col + 4]);
                afr[3] = __float_as_uint(pb[p1*PBW + col + 4]);
                bfr[0] = __float_as_uint(vc[kA*KST       + nd]);
                bfr[1] = __float_as_uint(vc[(kA + 4)*KST + nd]);
                mma_tf32(av, afr, bfr);
            }
        }
        if (r + 2 <= 8) stage_round(vb, r + 2);
    }

    {
        float s0 = scl[p0], s1 = scl[p1];
        int d = ((warp & 7) << 3) + (qd << 1);
        int iq0 = base + p0, iq1 = base + p1;
        *(float2*)(attn + ((size_t)b*SS + iq0)*EE + h*DHH + d) = make_float2(av[0]*s0, av[1]*s0);
        *(float2*)(attn + ((size_t)b*SS + iq1)*EE + h*DHH + d) = make_float2(av[2]*s1, av[3]*s1);
    }
}

// ---------------- global attention (overwrites attn rows < G) ----------------
__global__ __launch_bounds__(256) void global_attn_kernel(
    const float* __restrict__ gq, const float* __restrict__ gk, const float* __restrict__ gv,
    const int* __restrict__ am, const int* __restrict__ gm,
    float* __restrict__ attn)
{
    int g = blockIdx.x, h = blockIdx.y, b = blockIdx.z;
    int tid = threadIdx.x;
    __shared__ float sc[SS];
    __shared__ float qrow[64];
    __shared__ float red[8];
    __shared__ float redv[4][64];

    const float* gkb = gk + ((size_t)(b*HH + h) * SS) * DHH;
    const float* gvb = gv + ((size_t)(b*HH + h) * SS) * DHH;
    if (tid < 64) qrow[tid] = gq[(((size_t)(b*HH + h) * SS + g) << 6) + tid];
    __syncthreads();

    float lmax = -3.4e38f;
    for (int j = tid; j < SS; j += 256) {
        int m = am[b*SS + j] * (gm[b*SS + j] + 1);
        float s;
        if (m == 0) s = NEGV;
        else {
            float a0=0.f,a1=0.f,a2=0.f,a3=0.f;
            const float4* kp = (const float4*)(gkb + (size_t)j * DHH);
            const float4* qp = (const float4*)qrow;
#pragma unroll
            for (int d4 = 0; d4 < 16; d4++) {
                float4 a = qp[d4], bb = kp[d4];
                a0 += a.x*bb.x; a1 += a.y*bb.y; a2 += a.z*bb.z; a3 += a.w*bb.w;
            }
            s = (a0 + a1) + (a2 + a3);
        }
        sc[j] = s;
        lmax = fmaxf(lmax, s);
    }
#pragma unroll
    for (int o = 16; o; o >>= 1) lmax = fmaxf(lmax, __shfl_xor_sync(0xffffffffu, lmax, o));
    if ((tid & 31) == 0) red[tid >> 5] = lmax;
    __syncthreads();
    float bmax = red[0];
#pragma unroll
    for (int w = 1; w < 8; w++) bmax = fmaxf(bmax, red[w]);

    float lsum = 0.f;
    for (int j = tid; j < SS; j += 256) {
        float e = __expf(sc[j] - bmax);
        sc[j] = e;
        lsum += e;
    }
#pragma unroll
    for (int o = 16; o; o >>= 1) lsum += __shfl_xor_sync(0xffffffffu, lsum, o);
    __syncthreads();
    if ((tid & 31) == 0) red[tid >> 5] = lsum;
    __syncthreads();
    float ssum = 0.f;
#pragma unroll
    for (int w = 0; w < 8; w++) ssum += red[w];
    float inv = 1.f / ssum;

    int grp = tid >> 6, d = tid & 63;
    float acc0 = 0.f, acc1 = 0.f;
    for (int j = grp; j < SS; j += 8) {
        acc0 += sc[j] * gvb[(size_t)j * DHH + d];
        acc1 += sc[j + 4] * gvb[(size_t)(j + 4) * DHH + d];
    }
    redv[grp][d] = acc0 + acc1;
    __syncthreads();
    if (grp == 0) {
        float o = (redv[0][d] + redv[1][d] + redv[2][d] + redv[3][d]) * inv;
        attn[((size_t)b*SS + g)*EE + h*DHH + d] = o;
    }
}

// ---------------- fused add + LayerNorm ----------------
__global__ __launch_bounds__(256) void add_ln_kernel(
    const float* __restrict__ a, const float* __restrict__ c,
    const float* __restrict__ gamma, const float* __restrict__ beta,
    float* __restrict__ out)
{
    int row = blockIdx.x;
    int tid = threadIdx.x;
    __shared__ float buf[EE];
    __shared__ float red[8];

    float local = 0.f;
#pragma unroll
    for (int i = 0; i < 3; i++) {
        int idx = tid + i*256;
        float v = a[(size_t)row*EE + idx] + c[(size_t)row*EE + idx];
        buf[idx] = v;
        local += v;
    }
#pragma unroll
    for (int o = 16; o; o >>= 1) local += __shfl_xor_sync(0xffffffffu, local, o);
    if ((tid & 31) == 0) red[tid >> 5] = local;
    __syncthreads();
    float s = 0.f;
#pragma unroll
    for (int w = 0; w < 8; w++) s += red[w];
    float mean = s * (1.f/768.f);

    float lv = 0.f;
#pragma unroll
    for (int i = 0; i < 3; i++) {
        float dd = buf[tid + i*256] - mean;
        lv += dd*dd;
    }
#pragma unroll
    for (int o = 16; o; o >>= 1) lv += __shfl_xor_sync(0xffffffffu, lv, o);
    __syncthreads();
    if ((tid & 31) == 0) red[tid >> 5] = lv;
    __syncthreads();
    float vs = 0.f;
#pragma unroll
    for (int w = 0; w < 8; w++) vs += red[w];
    float invstd = rsqrtf(vs * (1.f/768.f) + 1e-5f);

#pragma unroll
    for (int i = 0; i < 3; i++) {
        int idx = tid + i*256;
        out[(size_t)row*EE + idx] = (buf[idx] - mean) * invstd * gamma[idx] + beta[idx];
    }
}

// ---------------- launch ----------------
extern "C" void kernel_launch(void* const* d_in, const int* in_sizes, int n_in,
                              void* d_out, int out_size) {
    (void)in_sizes; (void)n_in; (void)out_size;
    const float* x    = (const float*)d_in[0];
    const int*   am   = (const int*)d_in[1];
    const int*   gm   = (const int*)d_in[2];
    const float* Wq   = (const float*)d_in[3];  const float* bq  = (const float*)d_in[4];
    const float* Wk   = (const float*)d_in[5];  const float* bk  = (const float*)d_in[6];
    const float* Wv   = (const float*)d_in[7];  const float* bv  = (const float*)d_in[8];
    const float* Wqg  = (const float*)d_in[9];  const float* bqg = (const float*)d_in[10];
    const float* Wkg  = (const float*)d_in[11]; const float* bkg = (const float*)d_in[12];
    const float* Wvg  = (const float*)d_in[13]; const float* bvg = (const float*)d_in[14];
    const float* ln0g = (const float*)d_in[15]; const float* ln0b = (const float*)d_in[16];
    const float* ln1g = (const float*)d_in[17]; const float* ln1b = (const float*)d_in[18];
    const float* W1   = (const float*)d_in[19];
    const float* W3   = (const float*)d_in[20];
    const float* W2   = (const float*)d_in[21];
    float* out = (float*)d_out;

    float *qp, *kp, *vp, *gqp, *gkp, *gvp, *attnp, *h0p, *t1p, *tbp;
    cudaGetSymbolAddress((void**)&qp,  g_q);
    cudaGetSymbolAddress((void**)&kp,  g_k);
    cudaGetSymbolAddress((void**)&vp,  g_v);
    cudaGetSymbolAddress((void**)&gqp, g_gq);
    cudaGetSymbolAddress((void**)&gkp, g_gk);
    cudaGetSymbolAddress((void**)&gvp, g_gv);
    cudaGetSymbolAddress((void**)&attnp, g_attn);
    cudaGetSymbolAddress((void**)&h0p, g_h0);
    cudaGetSymbolAddress((void**)&t1p, g_t1);
    cudaGetSymbolAddress((void**)&tbp, g_tbuf);

    cudaFuncSetAttribute(band_attn_kernel,
                         cudaFuncAttributeMaxDynamicSharedMemorySize, BAND_SMEM);
    cudaFuncSetAttribute(tf32gemm_kernel,
                         cudaFuncAttributeMaxDynamicSharedMemorySize, GEMM_SMEM);
    cudaFuncSetAttribute(ffn1_kernel,
                         cudaFuncAttributeMaxDynamicSharedMemorySize, GEMM_SMEM);

    mask_cumsum_kernel<<<BB, 256>>>(am, gm, tbp);

    // 6 projection GEMMs; RoPE fused into the q/k epilogues
    GemmArgs pa = {};
    pa.A = x; pa.N = EE; pa.K = EE; pa.epi = 1; pa.tb = tbp;
    pa.Wm[0] = Wq;  pa.bias[0] = bq;  pa.out[0] = qp;  pa.scale[0] = 0.125f; pa.rope[0] = 1;
    pa.Wm[1] = Wk;  pa.bias[1] = bk;  pa.out[1] = kp;  pa.scale[1] = 1.f;    pa.rope[1] = 1;
    pa.Wm[2] = Wv;  pa.bias[2] = bv;  pa.out[2] = vp;  pa.scale[2] = 1.f;    pa.rope[2] = 0;
    pa.Wm[3] = Wqg; pa.bias[3] = bqg; pa.out[3] = gqp; pa.scale[3] = 0.125f; pa.rope[3] = 0;
    pa.Wm[4] = Wkg; pa.bias[4] = bkg; pa.out[4] = gkp; pa.scale[4] = 1.f;    pa.rope[4] = 0;
    pa.Wm[5] = Wvg; pa.bias[5] = bvg; pa.out[5] = gvp; pa.scale[5] = 1.f;    pa.rope[5] = 0;
    tf32gemm_kernel<<<dim3(32, 6, 6), 128, GEMM_SMEM>>>(pa);

    band_attn_kernel<<<dim3(SS/32, HH, BB), 512, BAND_SMEM>>>(qp, kp, vp, am, gm, attnp);
    global_attn_kernel<<<dim3(GG, HH, BB), 256>>>(gqp, gkp, gvp, am, gm, attnp);

    add_ln_kernel<<<BB*SS, 256>>>(x, attnp, ln0g, ln0b, h0p);

    // fused FFN-up + SiLU-gate
    ffn1_kernel<<<dim3(32, 48), 128, GEMM_SMEM>>>(h0p, W1, W3, t1p);

    GemmArgs f2 = {};
    f2.A = t1p; f2.N = EE; f2.K = FFD; f2.epi = 0; f2.tb = tbp;
    f2.Wm[0] = W2; f2.bias[0] = nullptr; f2.out[0] = attnp; f2.scale[0] = 1.f;
    tf32gemm_kernel<<<dim3(32, 6, 1), 128, GEMM_SMEM>>>(f2);

    add_ln_kernel<<<BB*SS, 256>>>(h0p, attnp, ln1g, ln1b, out);
}